// round 10
// baseline (speedup 1.0000x reference)
#include <cuda_runtime.h>
#include <math.h>
#include <stdint.h>

// ---------------- problem constants (fixed shapes) ----------------
#define BQ   16
#define CH   256
#define CONDC 512
#define TT   2048
#define TSL  512
#define NH   4
#define KC   64

#define SA 136       // padded smem stride (words): mod 32 = 8, *4 % 16 == 0

// ---------------- scratch (device globals; no allocation) ----------------
__device__ float g_q  [BQ * CH * TT];         // q (fp32; flash ropes on load)
__device__ float g_k  [BQ * CH * TSL];        // k (roped+masked fp32)
__device__ float g_v  [BQ * CH * TSL];        // v fp32
__device__ float g_att[BQ * CH * TT];         // attn out fp32
__device__ float g_wkc[CH * CONDC];           // wk @ w_cond
__device__ float g_wvc[CH * CONDC];           // wv @ w_cond
__device__ float g_wfo[2 * CH * CH];          // w_film @ wo
__device__ float g_bkc[CH];
__device__ float g_bvc[CH];
__device__ float g_bfo[2 * CH];
__device__ float g_zero[512];                 // zero-initialized device global
__device__ float g_cos[32 * TT];              // [d][t]
__device__ float g_sin[32 * TT];

// ---------------- tf32 helpers ----------------
__device__ __forceinline__ uint32_t f2tf(float f) {
    uint32_t u;
    asm("cvt.rna.tf32.f32 %0, %1;" : "=r"(u) : "f"(f));
    return u;
}

__device__ __forceinline__ void mma_tf32(float* c, const uint32_t* a, const uint32_t* b) {
    asm volatile(
        "mma.sync.aligned.m16n8k8.row.col.f32.tf32.tf32.f32 "
        "{%0,%1,%2,%3}, {%4,%5,%6,%7}, {%8,%9}, {%0,%1,%2,%3};\n"
        : "+f"(c[0]), "+f"(c[1]), "+f"(c[2]), "+f"(c[3])
        : "r"(a[0]), "r"(a[1]), "r"(a[2]), "r"(a[3]), "r"(b[0]), "r"(b[1]));
}

// ---------------- RoPE tables, layout [d][t] ----------------
__global__ void rope_table_kernel() {
    int idx = blockIdx.x * blockDim.x + threadIdx.x;
    if (idx >= 32 * TT) return;
    int d = idx / TT;
    int t = idx % TT;
    float invf = (float)pow(10000.0, -(double)d / 32.0);
    float ang  = (float)t * invf;            // same fp32 rounding as reference
    g_cos[idx] = (float)cos((double)ang);
    g_sin[idx] = (float)sin((double)ang);
}

// ---------------- combined biases (full fp32) ----------------
// bkc = wk@b_cond + bk ; bvc = wv@b_cond + bv ; bfo = w_film@bo + b_film
__global__ void bias_combine_kernel(const float* __restrict__ wk, const float* __restrict__ bk,
                                    const float* __restrict__ wv, const float* __restrict__ bv,
                                    const float* __restrict__ b_cond,
                                    const float* __restrict__ wf, const float* __restrict__ bf,
                                    const float* __restrict__ bo) {
    int tid = blockIdx.x * 256 + threadIdx.x;   // 0..1023
    if (tid < 256) {
        float s = 0.f;
        for (int k = 0; k < CONDC; ++k) s += wk[tid * CONDC + k] * b_cond[k];
        g_bkc[tid] = s + bk[tid];
    } else if (tid < 512) {
        int m = tid - 256;
        float s = 0.f;
        for (int k = 0; k < CONDC; ++k) s += wv[m * CONDC + k] * b_cond[k];
        g_bvc[m] = s + bv[m];
    } else {
        int m = tid - 512;
        float s = 0.f;
        for (int k = 0; k < CH; ++k) s += wf[m * CH + k] * bo[k];
        g_bfo[m] = s + bf[m];
    }
}

// NOTE on bias_combine dims: wk/wv are [CH][CH] (k from c uses wk[256,256])? No:
// k = wk @ c, wk is [CH][CH]=[256,256]; c = w_cond@cl + b_cond with b_cond len CH=256.
// So bkc = wk@b_cond needs wk rows of length CH (256) and b_cond len 256.
// (The kernel above uses CONDC=512 for wk — fixed below via template arg.)
// Corrected version:
__global__ void bias_combine2_kernel(const float* __restrict__ wk, const float* __restrict__ bk,
                                     const float* __restrict__ wv, const float* __restrict__ bv,
                                     const float* __restrict__ b_cond,
                                     const float* __restrict__ wf, const float* __restrict__ bf,
                                     const float* __restrict__ bo) {
    int tid = blockIdx.x * 256 + threadIdx.x;   // 0..1023
    if (tid < 256) {
        float s = 0.f;
        for (int k = 0; k < CH; ++k) s += wk[tid * CH + k] * b_cond[k];
        g_bkc[tid] = s + bk[tid];
    } else if (tid < 512) {
        int m = tid - 256;
        float s = 0.f;
        for (int k = 0; k < CH; ++k) s += wv[m * CH + k] * b_cond[k];
        g_bvc[m] = s + bv[m];
    } else {
        int m = tid - 512;
        float s = 0.f;
        for (int k = 0; k < CH; ++k) s += wf[m * CH + k] * bo[k];
        g_bfo[m] = s + bf[m];
    }
}

// ---------------- rope + mask K in place (fp32 out) ----------------
__global__ void rope_k_mask_kernel(float* __restrict__ k, const float* __restrict__ cmask) {
    int idx = blockIdx.x * blockDim.x + threadIdx.x;
    if (idx >= BQ * NH * 32 * TSL) return;
    int t  = idx & (TSL - 1);
    int rr = idx >> 9;
    int d  = rr & 31;
    int bh = rr >> 5;
    int b  = bh >> 2;
    float cs = g_cos[d * TT + t];
    float sn = g_sin[d * TT + t];
    float cm = cmask[(size_t)b * TSL + t];
    size_t base = ((size_t)bh * KC + d) * TSL + t;
    float k1 = k[base];
    float k2 = k[base + (size_t)32 * TSL];
    k[base]                    = (k1 * cs - k2 * sn) * cm;
    k[base + (size_t)32 * TSL] = (k2 * cs + k1 * sn) * cm;
}

// ============================================================================
// tf32 MMA GEMM, 128x128 CTA tile, 256 threads (8 warps, 2x4), warp tile 64x32,
// BK=32, double-buffered dynamic smem, f2tf on smem store (R7-proven).
// A stored [M][K] global. Y = A@B + bias[m].
// GSEL 0: plain (blockIdx.z = batch).
// GSEL 1: kv-fused (blockIdx.z & 15 = batch, >>4 selects A/bias/Y set).
// GSEL 2: weight-combine pair (batch = 0, blockIdx.z selects set).
// ============================================================================
#define GEMM_SMEM (4 * 32 * SA * 4)

template<int GSEL>
__global__ __launch_bounds__(256, 2)
void mma_gemm64(const float* __restrict__ A0, const float* __restrict__ A1,
                const float* __restrict__ B,
                const float* __restrict__ bias0, const float* __restrict__ bias1,
                float* __restrict__ Y0, float* __restrict__ Y1,
                int Ndim, int Kdim, size_t strideB, size_t strideY)
{
    extern __shared__ uint32_t smg[];
    uint32_t* Asm = smg;
    uint32_t* Bsm = smg + 2 * 32 * SA;

    const int tid = threadIdx.x;
    int bz, sel = 0;
    if (GSEL == 1)      { bz = blockIdx.z & 15; sel = blockIdx.z >> 4; }
    else if (GSEL == 2) { bz = 0;               sel = blockIdx.z; }
    else                { bz = blockIdx.z; }
    const float* A    = (GSEL >= 1 && sel) ? A1 : A0;
    const float* bias = (GSEL >= 1 && sel) ? bias1 : bias0;
    float*       Y    = (GSEL >= 1 && sel) ? Y1 : Y0;
    const float* Bb = B + (size_t)bz * strideB;
    float*       Yb = Y + (size_t)bz * strideY;
    const int m0 = blockIdx.y * 128, n0 = blockIdx.x * 128;

    const int wid = tid >> 5, lane = tid & 31;
    const int wm = wid >> 2, wn = wid & 3;
    const int r = lane >> 2, c = lane & 3;

    const int a_m = ((tid >> 1) + ((tid & 1) << 4)) & 127;
    const int a_k = (tid & 1) << 4;
    const int b_row = tid >> 3;
    const int b_c4  = (tid & 7) * 4;

    float acc[4][4][4] = {};
    const int nk = Kdim / 32;

    float4 avr[4], bvr[4];
#define LDG_T(k0)                                                                       \
    {                                                                                   \
        _Pragma("unroll")                                                               \
        for (int j = 0; j < 4; ++j) {                                                   \
            avr[j] = *(const float4*)&A[(size_t)(m0 + a_m) * Kdim + (k0) + a_k + 4 * j];\
            bvr[j] = *(const float4*)&Bb[(size_t)((k0) + b_row) * Ndim + n0 + b_c4 + 32 * j]; \
        }                                                                               \
    }
#define STS_T(buf)                                                                      \
    {                                                                                   \
        uint32_t* Ab = Asm + (buf) * 32 * SA;                                           \
        uint32_t* Bd = Bsm + (buf) * 32 * SA;                                           \
        _Pragma("unroll")                                                               \
        for (int j = 0; j < 4; ++j) {                                                   \
            Ab[(a_k + 4 * j + 0) * SA + a_m] = f2tf(avr[j].x);                          \
            Ab[(a_k + 4 * j + 1) * SA + a_m] = f2tf(avr[j].y);                          \
            Ab[(a_k + 4 * j + 2) * SA + a_m] = f2tf(avr[j].z);                          \
            Ab[(a_k + 4 * j + 3) * SA + a_m] = f2tf(avr[j].w);                          \
            uint4 bu;                                                                   \
            bu.x = f2tf(bvr[j].x); bu.y = f2tf(bvr[j].y);                               \
            bu.z = f2tf(bvr[j].z); bu.w = f2tf(bvr[j].w);                               \
            *(uint4*)&Bd[b_row * SA + b_c4 + 32 * j] = bu;                              \
        }                                                                               \
    }

    LDG_T(0);
    STS_T(0);
    __syncthreads();

    for (int kb = 0; kb < nk; ++kb) {
        const int cur = kb & 1;
        const bool more = (kb + 1 < nk);
        if (more) LDG_T((kb + 1) * 32);

        const uint32_t* Ac = Asm + cur * 32 * SA;
        const uint32_t* Bc = Bsm + cur * 32 * SA;
#pragma unroll
        for (int k8 = 0; k8 < 32; k8 += 8) {
            uint32_t af[4][4], bf[4][2];
#pragma unroll
            for (int mt = 0; mt < 4; ++mt) {
                int mb = wm * 64 + mt * 16 + r;
                af[mt][0] = Ac[(k8 + c) * SA + mb];
                af[mt][1] = Ac[(k8 + c) * SA + mb + 8];
                af[mt][2] = Ac[(k8 + c + 4) * SA + mb];
                af[mt][3] = Ac[(k8 + c + 4) * SA + mb + 8];
            }
#pragma unroll
            for (int nt = 0; nt < 4; ++nt) {
                int nb = wn * 32 + nt * 8 + r;
                bf[nt][0] = Bc[(k8 + c) * SA + nb];
                bf[nt][1] = Bc[(k8 + c + 4) * SA + nb];
            }
#pragma unroll
            for (int mt = 0; mt < 4; ++mt)
#pragma unroll
                for (int nt = 0; nt < 4; ++nt)
                    mma_tf32(acc[mt][nt], af[mt], bf[nt]);
        }
        if (more) STS_T(cur ^ 1);
        __syncthreads();
    }
#undef LDG_T
#undef STS_T

#pragma unroll
    for (int mt = 0; mt < 4; ++mt) {
#pragma unroll
        for (int h = 0; h < 2; ++h) {
            const int row = m0 + wm * 64 + mt * 16 + h * 8 + r;
            float bval = bias[row];
#pragma unroll
            for (int nt = 0; nt < 4; ++nt) {
                const int col = n0 + wn * 32 + nt * 8 + c * 2;
                float2 o;
                o.x = acc[mt][nt][h * 2 + 0] + bval;
                o.y = acc[mt][nt][h * 2 + 1] + bval;
                *(float2*)&Yb[(size_t)row * Ndim + col] = o;
            }
        }
    }
}

// ============================================================================
// Fused flash attention (R7-identical: rope Q on load, f2tf on K/V store)
// ============================================================================
#define FSA 136
#define FSK 72
#define FSV 68
#define FLASH_SMEM ((64*FSA + 64*FSK + 64*FSV + 64*FSA + 512) * 4)

__global__ __launch_bounds__(256, 2)
void flash_attn(const float* __restrict__ Qg, const float* __restrict__ Kg,
                const float* __restrict__ Vg, const float* __restrict__ cmask,
                float* __restrict__ O)
{
    extern __shared__ uint32_t sm[];
    uint32_t* Qs  = sm;
    uint32_t* Ks  = sm + 64 * FSA;
    uint32_t* Vs  = Ks + 64 * FSK;
    uint32_t* Ps  = Vs + 64 * FSV;
    float*    cmb = (float*)(Ps + 64 * FSA);

    const int bh = blockIdx.z;
    const int b  = bh >> 2;
    const int m0 = blockIdx.y * 128;
    const int tid = threadIdx.x, wid = tid >> 5, lane = tid & 31;
    const int r = lane >> 2, c = lane & 3;
    const int mb = wid * 16 + r;

    const float* Qb = Qg + (size_t)bh * KC * TT;
    const float* Kb = Kg + (size_t)bh * KC * TSL;
    const float* Vb = Vg + (size_t)bh * KC * TSL;

    // ---- load Q tile (64 x 128) with RoPE ----
    {
        int d  = tid >> 3;
        int mg = (tid & 7) * 16;
#pragma unroll
        for (int j = 0; j < 16; j += 4) {
            int m = mg + j;
            int t = m0 + m;
            float4 q1 = *(const float4*)&Qb[(size_t)d * TT + t];
            float4 q2 = *(const float4*)&Qb[(size_t)(d + 32) * TT + t];
            float4 cv = *(const float4*)&g_cos[(size_t)d * TT + t];
            float4 sv = *(const float4*)&g_sin[(size_t)d * TT + t];
            Qs[d * FSA + m + 0] = f2tf(q1.x * cv.x - q2.x * sv.x);
            Qs[d * FSA + m + 1] = f2tf(q1.y * cv.y - q2.y * sv.y);
            Qs[d * FSA + m + 2] = f2tf(q1.z * cv.z - q2.z * sv.z);
            Qs[d * FSA + m + 3] = f2tf(q1.w * cv.w - q2.w * sv.w);
            Qs[(d + 32) * FSA + m + 0] = f2tf(q2.x * cv.x + q1.x * sv.x);
            Qs[(d + 32) * FSA + m + 1] = f2tf(q2.y * cv.y + q1.y * sv.y);
            Qs[(d + 32) * FSA + m + 2] = f2tf(q2.z * cv.z + q1.z * sv.z);
            Qs[(d + 32) * FSA + m + 3] = f2tf(q2.w * cv.w + q1.w * sv.w);
        }
    }
    for (int i = tid; i < TSL; i += 256)
        cmb[i] = (cmask[(size_t)b * TSL + i] == 0.f) ? -1e4f : 0.f;

    const int prow = tid >> 2;
    const int pcol = (tid & 3) * 4;
    float4 kr[4], vr[4];
#pragma unroll
    for (int j = 0; j < 4; ++j) {
        kr[j] = *(const float4*)&Kb[(size_t)prow * TSL + pcol + 16 * j];
        vr[j] = *(const float4*)&Vb[(size_t)prow * TSL + pcol + 16 * j];
    }

    float m_run[2] = {-1e30f, -1e30f};
    float l_run[2] = {0.f, 0.f};
    float acc_o[8][4] = {};

    __syncthreads();

    for (int ci = 0; ci < 8; ++ci) {
        const int s0 = ci * 64;
#pragma unroll
        for (int j = 0; j < 4; ++j) {
            int col = pcol + 16 * j;
            Ks[prow * FSK + col + 0] = f2tf(kr[j].x);
            Ks[prow * FSK + col + 1] = f2tf(kr[j].y);
            Ks[prow * FSK + col + 2] = f2tf(kr[j].z);
            Ks[prow * FSK + col + 3] = f2tf(kr[j].w);
            Vs[prow * FSV + col + 0] = f2tf(vr[j].x);
            Vs[prow * FSV + col + 1] = f2tf(vr[j].y);
            Vs[prow * FSV + col + 2] = f2tf(vr[j].z);
            Vs[prow * FSV + col + 3] = f2tf(vr[j].w);
        }
        __syncthreads();
        if (ci < 7) {
#pragma unroll
            for (int j = 0; j < 4; ++j) {
                kr[j] = *(const float4*)&Kb[(size_t)prow * TSL + s0 + 64 + pcol + 16 * j];
                vr[j] = *(const float4*)&Vb[(size_t)prow * TSL + s0 + 64 + pcol + 16 * j];
            }
        }

        float acc_s[8][4] = {};
#pragma unroll
        for (int k8 = 0; k8 < 64; k8 += 8) {
            uint32_t af[4];
            af[0] = Qs[(k8 + c) * FSA + mb];
            af[1] = Qs[(k8 + c) * FSA + mb + 8];
            af[2] = Qs[(k8 + c + 4) * FSA + mb];
            af[3] = Qs[(k8 + c + 4) * FSA + mb + 8];
#pragma unroll
            for (int nt = 0; nt < 8; ++nt) {
                uint32_t bf[2];
                bf[0] = Ks[(k8 + c) * FSK + nt * 8 + r];
                bf[1] = Ks[(k8 + c + 4) * FSK + nt * 8 + r];
                mma_tf32(acc_s[nt], af, bf);
            }
        }

        float mx[2] = {-1e30f, -1e30f};
#pragma unroll
        for (int nt = 0; nt < 8; ++nt) {
            float2 bias = *(float2*)&cmb[s0 + nt * 8 + 2 * c];
#pragma unroll
            for (int jj = 0; jj < 4; ++jj) {
                float v = acc_s[nt][jj] * 0.125f + ((jj & 1) ? bias.y : bias.x);
                acc_s[nt][jj] = v;
                mx[jj >> 1] = fmaxf(mx[jj >> 1], v);
            }
        }
#pragma unroll
        for (int h = 0; h < 2; ++h) {
            mx[h] = fmaxf(mx[h], __shfl_xor_sync(0xffffffffu, mx[h], 1));
            mx[h] = fmaxf(mx[h], __shfl_xor_sync(0xffffffffu, mx[h], 2));
        }
        float mnew[2], scale[2], lad[2] = {0.f, 0.f};
#pragma unroll
        for (int h = 0; h < 2; ++h) {
            mnew[h]  = fmaxf(m_run[h], mx[h]);
            scale[h] = __expf(m_run[h] - mnew[h]);
            m_run[h] = mnew[h];
        }
#pragma unroll
        for (int nt = 0; nt < 8; ++nt) {
#pragma unroll
            for (int jj = 0; jj < 4; ++jj) {
                float e = __expf(acc_s[nt][jj] - mnew[jj >> 1]);
                acc_s[nt][jj] = e;
                lad[jj >> 1] += e;
            }
        }
#pragma unroll
        for (int h = 0; h < 2; ++h) {
            lad[h] += __shfl_xor_sync(0xffffffffu, lad[h], 1);
            lad[h] += __shfl_xor_sync(0xffffffffu, lad[h], 2);
            l_run[h] = l_run[h] * scale[h] + lad[h];
        }
#pragma unroll
        for (int nt = 0; nt < 8; ++nt) {
#pragma unroll
            for (int jj = 0; jj < 4; ++jj)
                acc_o[nt][jj] *= scale[jj >> 1];
        }
#pragma unroll
        for (int nt = 0; nt < 8; ++nt) {
#pragma unroll
            for (int jj = 0; jj < 4; ++jj) {
                int kcol = nt * 8 + 2 * c + (jj & 1);
                int mrow = wid * 16 + r + (jj >> 1) * 8;
                Ps[kcol * FSA + mrow] = f2tf(acc_s[nt][jj]);
            }
        }
        __syncwarp();

#pragma unroll
        for (int k8 = 0; k8 < 64; k8 += 8) {
            uint32_t af[4];
            af[0] = Ps[(k8 + c) * FSA + mb];
            af[1] = Ps[(k8 + c) * FSA + mb + 8];
            af[2] = Ps[(k8 + c + 4) * FSA + mb];
            af[3] = Ps[(k8 + c + 4) * FSA + mb + 8];
#pragma unroll
            for (int nt = 0; nt < 8; ++nt) {
                uint32_t bf[2];
                bf[0] = Vs[(nt * 8 + r) * FSV + k8 + c];
                bf[1] = Vs[(nt * 8 + r) * FSV + k8 + c + 4];
                mma_tf32(acc_o[nt], af, bf);
            }
        }
        __syncthreads();
    }

    float inv[2] = {1.f / l_run[0], 1.f / l_run[1]};
    float* Pf = (float*)Ps;
#pragma unroll
    for (int nt = 0; nt < 8; ++nt) {
#pragma unroll
        for (int jj = 0; jj < 4; ++jj) {
            int n = nt * 8 + 2 * c + (jj & 1);
            int m = wid * 16 + r + (jj >> 1) * 8;
            Pf[n * FSA + m] = acc_o[nt][jj] * inv[jj >> 1];
        }
    }
    __syncthreads();
    {
        int row = tid >> 2;
        int mq  = (tid & 3) * 4;
#pragma unroll
        for (int j = 0; j < 8; ++j) {
            int m = mq + 16 * j;
            *(float4*)&O[((size_t)bh * KC + row) * TT + m0 + m] =
                *(float4*)&Pf[row * FSA + m];
        }
    }
}

// ============================================================================
// Fused FiLM GEMM (R7-identical; now fed wfo/att/bfo)
// ============================================================================
#define FILM_SMEM ((3 * 2 * 16 * SA) * 4)

__global__ __launch_bounds__(512)
void film_gemm(const float* __restrict__ Wf, const float* __restrict__ Yin,
               const float* __restrict__ bfilm, const float* __restrict__ x,
               const float* __restrict__ xmask, float* __restrict__ out)
{
    extern __shared__ uint32_t smf[];
    uint32_t* AsG = smf;
    uint32_t* AsB = smf + 2 * 16 * SA;
    uint32_t* Bs  = smf + 4 * 16 * SA;

    const int tid = threadIdx.x;
    const int bz  = blockIdx.z;
    const float* Bb = Yin + (size_t)bz * CH * TT;
    const int m0 = blockIdx.y * 128, n0 = blockIdx.x * 128;

    const int wid = tid >> 5, lane = tid & 31;
    const int wm = wid >> 2, wn = wid & 3;
    const int r = lane >> 2, c = lane & 3;

    const int l_row = tid >> 5;
    const int l_col = lane * 4;
    const int l_am  = tid >> 2;
    const int l_ak  = (tid & 3) * 4;

    float acc_g[2][4][4] = {};
    float acc_b[2][4][4] = {};

    float4 bvr, agr, abr;
#define LDG_TILE_F(k0)                                                                  \
    {                                                                                   \
        bvr = *(const float4*)&Bb[(size_t)((k0) + l_row) * TT + n0 + l_col];            \
        agr = *(const float4*)&Wf[(size_t)(m0 + l_am) * CH + (k0) + l_ak];              \
        abr = *(const float4*)&Wf[(size_t)(256 + m0 + l_am) * CH + (k0) + l_ak];        \
    }
#define STS_TILE_F(buf)                                                                 \
    {                                                                                   \
        uint4 bu; bu.x = f2tf(bvr.x); bu.y = f2tf(bvr.y); bu.z = f2tf(bvr.z); bu.w = f2tf(bvr.w); \
        *(uint4*)&Bs[(buf) * 16 * SA + l_row * SA + l_col] = bu;                        \
        AsG[(buf) * 16 * SA + (l_ak + 0) * SA + l_am] = f2tf(agr.x);                    \
        AsG[(buf) * 16 * SA + (l_ak + 1) * SA + l_am] = f2tf(agr.y);                    \
        AsG[(buf) * 16 * SA + (l_ak + 2) * SA + l_am] = f2tf(agr.z);                    \
        AsG[(buf) * 16 * SA + (l_ak + 3) * SA + l_am] = f2tf(agr.w);                    \
        AsB[(buf) * 16 * SA + (l_ak + 0) * SA + l_am] = f2tf(abr.x);                    \
        AsB[(buf) * 16 * SA + (l_ak + 1) * SA + l_am] = f2tf(abr.y);                    \
        AsB[(buf) * 16 * SA + (l_ak + 2) * SA + l_am] = f2tf(abr.z);                    \
        AsB[(buf) * 16 * SA + (l_ak + 3) * SA + l_am] = f2tf(abr.w);                    \
    }

    LDG_TILE_F(0);
    STS_TILE_F(0);
    __syncthreads();

    const int nk = CH / 16;
    for (int kb = 0; kb < nk; ++kb) {
        const int cur = kb & 1;
        const bool more = (kb + 1 < nk);
        if (more) LDG_TILE_F((kb + 1) * 16);

#pragma unroll
        for (int k8 = 0; k8 < 16; k8 += 8) {
            uint32_t afg[2][4], afb[2][4], bf[4][2];
#pragma unroll
            for (int mt = 0; mt < 2; ++mt) {
                int mbx = wm * 32 + mt * 16 + r;
                afg[mt][0] = AsG[cur * 16 * SA + (k8 + c) * SA + mbx];
                afg[mt][1] = AsG[cur * 16 * SA + (k8 + c) * SA + mbx + 8];
                afg[mt][2] = AsG[cur * 16 * SA + (k8 + c + 4) * SA + mbx];
                afg[mt][3] = AsG[cur * 16 * SA + (k8 + c + 4) * SA + mbx + 8];
                afb[mt][0] = AsB[cur * 16 * SA + (k8 + c) * SA + mbx];
                afb[mt][1] = AsB[cur * 16 * SA + (k8 + c) * SA + mbx + 8];
                afb[mt][2] = AsB[cur * 16 * SA + (k8 + c + 4) * SA + mbx];
                afb[mt][3] = AsB[cur * 16 * SA + (k8 + c + 4) * SA + mbx + 8];
            }
#pragma unroll
            for (int nt = 0; nt < 4; ++nt) {
                int nb = wn * 32 + nt * 8 + r;
                bf[nt][0] = Bs[cur * 16 * SA + (k8 + c) * SA + nb];
                bf[nt][1] = Bs[cur * 16 * SA + (k8 + c + 4) * SA + nb];
            }
#pragma unroll
            for (int mt = 0; mt < 2; ++mt)
#pragma unroll
                for (int nt = 0; nt < 4; ++nt) {
                    mma_tf32(acc_g[mt][nt], afg[mt], bf[nt]);
                    mma_tf32(acc_b[mt][nt], afb[mt], bf[nt]);
                }
        }
        if (more) STS_TILE_F(cur ^ 1);
        __syncthreads();
    }
#undef LDG_TILE_F
#undef STS_TILE_F

#pragma unroll
    for (int mt = 0; mt < 2; ++mt) {
#pragma unroll
        for (int h = 0; h < 2; ++h) {
            const int row = m0 + wm * 32 + mt * 16 + r + h * 8;
            float bg = bfilm[row];
            float bb = bfilm[256 + row];
#pragma unroll
            for (int nt = 0; nt < 4; ++nt) {
                const int col = n0 + wn * 32 + nt * 8 + c * 2;
                float g0  = acc_g[mt][nt][h * 2 + 0] + bg;
                float g1  = acc_g[mt][nt][h * 2 + 1] + bg;
                float be0 = acc_b[mt][nt][h * 2 + 0] + bb;
                float be1 = acc_b[mt][nt][h * 2 + 1] + bb;
                float2 xv = *(const float2*)&x[((size_t)bz * CH + row) * TT + col];
                float xmm0 = xmask[(size_t)bz * TT + col];
                float xmm1 = xmask[(size_t)bz * TT + col + 1];
                float2 o;
                o.x = (xv.x * g0 + be0) * xmm0;
                o.y = (xv.y * g1 + be1) * xmm1;
                *(float2*)&out[((size_t)bz * CH + row) * TT + col] = o;
            }
        }
    }
}

// ---------------- launch ----------------
extern "C" void kernel_launch(void* const* d_in, const int* in_sizes, int n_in,
                              void* d_out, int out_size) {
    const float* x           = (const float*)d_in[0];
    const float* x_mask      = (const float*)d_in[1];
    const float* cond_latent = (const float*)d_in[2];
    const float* cond_mask   = (const float*)d_in[3];
    const float* w_cond      = (const float*)d_in[4];
    const float* b_cond      = (const float*)d_in[5];
    const float* wq          = (const float*)d_in[6];
    const float* bq          = (const float*)d_in[7];
    const float* wk          = (const float*)d_in[8];
    const float* bk          = (const float*)d_in[9];
    const float* wv          = (const float*)d_in[10];
    const float* bv          = (const float*)d_in[11];
    const float* wo          = (const float*)d_in[12];
    const float* bo          = (const float*)d_in[13];
    const float* w_film      = (const float*)d_in[14];
    const float* b_film      = (const float*)d_in[15];
    float* out = (float*)d_out;

    float *p_q, *p_k, *p_v, *p_att, *p_wkc, *p_wvc, *p_wfo, *p_bkc, *p_bvc, *p_bfo, *p_zero;
    cudaGetSymbolAddress((void**)&p_q,    g_q);
    cudaGetSymbolAddress((void**)&p_k,    g_k);
    cudaGetSymbolAddress((void**)&p_v,    g_v);
    cudaGetSymbolAddress((void**)&p_att,  g_att);
    cudaGetSymbolAddress((void**)&p_wkc,  g_wkc);
    cudaGetSymbolAddress((void**)&p_wvc,  g_wvc);
    cudaGetSymbolAddress((void**)&p_wfo,  g_wfo);
    cudaGetSymbolAddress((void**)&p_bkc,  g_bkc);
    cudaGetSymbolAddress((void**)&p_bvc,  g_bvc);
    cudaGetSymbolAddress((void**)&p_bfo,  g_bfo);
    cudaGetSymbolAddress((void**)&p_zero, g_zero);

    cudaFuncSetAttribute(mma_gemm64<0>, cudaFuncAttributeMaxDynamicSharedMemorySize, GEMM_SMEM);
    cudaFuncSetAttribute(mma_gemm64<1>, cudaFuncAttributeMaxDynamicSharedMemorySize, GEMM_SMEM);
    cudaFuncSetAttribute(mma_gemm64<2>, cudaFuncAttributeMaxDynamicSharedMemorySize, GEMM_SMEM);
    cudaFuncSetAttribute(flash_attn,    cudaFuncAttributeMaxDynamicSharedMemorySize, FLASH_SMEM);
    cudaFuncSetAttribute(film_gemm,     cudaFuncAttributeMaxDynamicSharedMemorySize, FILM_SMEM);

    // prologue: rope tables, combined biases, combined weights
    rope_table_kernel<<<(32 * TT + 255) / 256, 256>>>();
    bias_combine2_kernel<<<4, 256>>>(wk, bk, wv, bv, b_cond, w_film, b_film, bo);

    // wkc = wk @ w_cond ; wvc = wv @ w_cond     [256 x 512], K = 256
    mma_gemm64<2><<<dim3(CONDC / 128, CH / 128, 2), 256, GEMM_SMEM>>>(
        wk, wv, w_cond, p_zero, p_zero, p_wkc, p_wvc,
        CONDC, CH, 0, 0);

    // wfo = w_film @ wo                          [512 x 256], K = 256
    mma_gemm64<0><<<dim3(CH / 128, 2 * CH / 128, 1), 256, GEMM_SMEM>>>(
        w_film, nullptr, wo, p_zero, nullptr, p_wfo, nullptr,
        CH, CH, 0, 0);

    // q = wq @ x + bq                            [b][256][2048]
    mma_gemm64<0><<<dim3(TT / 128, CH / 128, BQ), 256, GEMM_SMEM>>>(
        wq, nullptr, x, bq, nullptr, p_q, nullptr,
        TT, CH, (size_t)CH * TT, (size_t)CH * TT);

    // k = wkc @ cond_latent + bkc ; v = wvc @ cond_latent + bvc   (K = 512)
    mma_gemm64<1><<<dim3(TSL / 128, CH / 128, 2 * BQ), 256, GEMM_SMEM>>>(
        p_wkc, p_wvc, cond_latent, p_bkc, p_bvc, p_k, p_v,
        TSL, CONDC, (size_t)CONDC * TSL, (size_t)CH * TSL);

    // rope + cond-mask K in place
    rope_k_mask_kernel<<<(BQ * NH * 32 * TSL + 255) / 256, 256>>>(p_k, cond_mask);

    // fused attention (Q-rope + scores + bias-mask + softmax + P@V)
    flash_attn<<<dim3(1, TT / 128, BQ * NH), 256, FLASH_SMEM>>>(
        p_q, p_k, p_v, cond_mask, p_att);

    // fused FiLM directly on att: gamma/beta = wfo @ att + bfo
    film_gemm<<<dim3(TT / 128, CH / 128, BQ), 512, FILM_SMEM>>>(
        p_wfo, p_att, p_bfo, x, x_mask, out);
}

// round 11
// speedup vs baseline: 1.4201x; 1.4201x over previous
#include <cuda_runtime.h>
#include <math.h>
#include <stdint.h>

// ---------------- problem constants (fixed shapes) ----------------
#define BQ   16
#define CH   256
#define CONDC 512
#define TT   2048
#define TSL  512
#define NH   4
#define KC   64

#define SA 136       // padded smem stride (words): mod 32 = 8, *4 % 16 == 0

// ---------------- scratch (device globals; no allocation) ----------------
__device__ float g_q  [BQ * CH * TT];         // q fp32 (flash ropes+packs)
__device__ float g_k  [BQ * CH * TSL];        // k roped+masked fp32
__device__ float g_v  [BQ * CH * TSL];        // v fp32
__device__ float g_att[BQ * CH * TT];         // attn out fp32
__device__ float g_wkc[CH * CONDC];           // wk @ w_cond
__device__ float g_wvc[CH * CONDC];           // wv @ w_cond
__device__ float g_wfo[2 * CH * CH];          // w_film @ wo
__device__ float g_bkc[CH];
__device__ float g_bvc[CH];
__device__ float g_bfo[2 * CH];
__device__ float g_zero[512];
__device__ float g_cos[32 * TT];              // [d][t]
__device__ float g_sin[32 * TT];

// ---------------- fp16 helpers ----------------
__device__ __forceinline__ uint32_t h2pk(float lo, float hi) {
    uint32_t u;
    asm("cvt.rn.f16x2.f32 %0, %1, %2;" : "=r"(u) : "f"(hi), "f"(lo));
    return u;
}

__device__ __forceinline__ void mma_f16(float* c, const uint32_t* a, const uint32_t* b) {
    asm volatile(
        "mma.sync.aligned.m16n8k16.row.col.f32.f16.f16.f32 "
        "{%0,%1,%2,%3}, {%4,%5,%6,%7}, {%8,%9}, {%0,%1,%2,%3};\n"
        : "+f"(c[0]), "+f"(c[1]), "+f"(c[2]), "+f"(c[3])
        : "r"(a[0]), "r"(a[1]), "r"(a[2]), "r"(a[3]), "r"(b[0]), "r"(b[1]));
}

// ---------------- RoPE tables, layout [d][t] ----------------
__global__ void rope_table_kernel() {
    int idx = blockIdx.x * blockDim.x + threadIdx.x;
    if (idx >= 32 * TT) return;
    int d = idx / TT;
    int t = idx % TT;
    float invf = (float)pow(10000.0, -(double)d / 32.0);
    float ang  = (float)t * invf;            // same fp32 rounding as reference
    g_cos[idx] = (float)cos((double)ang);
    g_sin[idx] = (float)sin((double)ang);
}

// ---------------- combined biases (full fp32) ----------------
__global__ void bias_combine2_kernel(const float* __restrict__ wk, const float* __restrict__ bk,
                                     const float* __restrict__ wv, const float* __restrict__ bv,
                                     const float* __restrict__ b_cond,
                                     const float* __restrict__ wf, const float* __restrict__ bf,
                                     const float* __restrict__ bo) {
    int tid = blockIdx.x * 256 + threadIdx.x;   // 0..1023
    if (tid < 256) {
        float s = 0.f;
        for (int k = 0; k < CH; ++k) s += wk[tid * CH + k] * b_cond[k];
        g_bkc[tid] = s + bk[tid];
    } else if (tid < 512) {
        int m = tid - 256;
        float s = 0.f;
        for (int k = 0; k < CH; ++k) s += wv[m * CH + k] * b_cond[k];
        g_bvc[m] = s + bv[m];
    } else {
        int m = tid - 512;
        float s = 0.f;
        for (int k = 0; k < CH; ++k) s += wf[m * CH + k] * bo[k];
        g_bfo[m] = s + bf[m];
    }
}

// ---------------- rope + mask K in place (fp32 out) ----------------
__global__ void rope_k_mask_kernel(float* __restrict__ k, const float* __restrict__ cmask) {
    int idx = blockIdx.x * blockDim.x + threadIdx.x;
    if (idx >= BQ * NH * 32 * TSL) return;
    int t  = idx & (TSL - 1);
    int rr = idx >> 9;
    int d  = rr & 31;
    int bh = rr >> 5;
    int b  = bh >> 2;
    float cs = g_cos[d * TT + t];
    float sn = g_sin[d * TT + t];
    float cm = cmask[(size_t)b * TSL + t];
    size_t base = ((size_t)bh * KC + d) * TSL + t;
    float k1 = k[base];
    float k2 = k[base + (size_t)32 * TSL];
    k[base]                    = (k1 * cs - k2 * sn) * cm;
    k[base + (size_t)32 * TSL] = (k2 * cs + k1 * sn) * cm;
}

// ============================================================================
// fp16 MMA GEMM, 128x128 CTA tile, 256 threads (8 warps, 2x4), warp tile 64x32,
// BK=32 floats (16 half2 words/slab), double-buffered dynamic smem.
// A stored [M][K] global fp32; B [K][N] fp32; pack to half2 along K on STS.
// Y = A@B + bias[m] (fp32 out).
// GSEL 0: plain. GSEL 1: kv-fused (z&15 batch, z>>4 sel). GSEL 2: merged
// weight combines (z=0 wkc, z=1 wvc, z=2 wfo; per-z dims; bias forced zero).
// ============================================================================
#define GEMM_SMEM (4 * 16 * SA * 4)

template<int GSEL>
__global__ __launch_bounds__(256, 2)
void mma_gemm64(const float* __restrict__ A0, const float* __restrict__ A1,
                const float* __restrict__ A2,
                const float* __restrict__ B0, const float* __restrict__ B1,
                const float* __restrict__ bias0, const float* __restrict__ bias1,
                float* __restrict__ Y0, float* __restrict__ Y1, float* __restrict__ Y2,
                int Ndim, int Kdim, size_t strideB, size_t strideY)
{
    extern __shared__ uint32_t smg[];
    uint32_t* Asm = smg;                 // [2][16*SA]
    uint32_t* Bsm = smg + 2 * 16 * SA;   // [2][16*SA]

    const int tid = threadIdx.x;
    int bz = 0, sel = 0;
    if (GSEL == 1)      { bz = blockIdx.z & 15; sel = blockIdx.z >> 4; }
    else if (GSEL == 2) { sel = blockIdx.z; }
    else                { bz = blockIdx.z; }

    const float* A;
    const float* bias;
    float*       Y;
    const float* Bsrc = B0;
    if (GSEL == 2) {
        A    = (sel == 0) ? A0 : (sel == 1) ? A1 : A2;
        Y    = (sel == 0) ? Y0 : (sel == 1) ? Y1 : Y2;
        bias = bias0;   // zero
        if (sel == 2) Bsrc = B1;
        int Md = (sel < 2) ? 256 : 512;
        Ndim   = (sel < 2) ? 512 : 256;
        if ((int)blockIdx.y * 128 >= Md || (int)blockIdx.x * 128 >= Ndim) return;
    } else {
        A    = (GSEL == 1 && sel) ? A1 : A0;
        bias = (GSEL == 1 && sel) ? bias1 : bias0;
        Y    = (GSEL == 1 && sel) ? Y1 : Y0;
    }
    const float* Bb = Bsrc + (size_t)bz * strideB;
    float*       Yb = Y    + (size_t)bz * strideY;
    const int m0 = blockIdx.y * 128, n0 = blockIdx.x * 128;

    const int wid = tid >> 5, lane = tid & 31;
    const int wm = wid >> 2, wn = wid & 3;
    const int r = lane >> 2, c = lane & 3;

    // A loader: xor-16 row remap, 16 floats (8 words) per thread
    const int a_m  = ((tid >> 1) + ((tid & 1) << 4)) & 127;
    const int a_kw = (tid & 1) * 8;                 // word offset 0 or 8
    // B loader: k-pair row kp, 4 word-cols, two 64-col groups
    const int b_kp = tid >> 4;                      // 0..15
    const int b_n4 = (tid & 15) * 4;

    float acc[4][4][4] = {};
    const int nk = Kdim / 32;

    float4 avr[4], blo[2], bhi[2];
#define LDG_T(k0)                                                                        \
    {                                                                                    \
        _Pragma("unroll")                                                                \
        for (int j = 0; j < 4; ++j)                                                      \
            avr[j] = *(const float4*)&A[(size_t)(m0 + a_m) * Kdim + (k0) + a_kw * 2 + 4 * j]; \
        _Pragma("unroll")                                                                \
        for (int j = 0; j < 2; ++j) {                                                    \
            blo[j] = *(const float4*)&Bb[(size_t)((k0) + 2 * b_kp)     * Ndim + n0 + b_n4 + 64 * j]; \
            bhi[j] = *(const float4*)&Bb[(size_t)((k0) + 2 * b_kp + 1) * Ndim + n0 + b_n4 + 64 * j]; \
        }                                                                                \
    }
#define STS_T(buf)                                                                       \
    {                                                                                    \
        uint32_t* Ab = Asm + (buf) * 16 * SA;                                            \
        uint32_t* Bd = Bsm + (buf) * 16 * SA;                                            \
        _Pragma("unroll")                                                                \
        for (int j = 0; j < 4; ++j) {                                                    \
            Ab[(a_kw + 2 * j + 0) * SA + a_m] = h2pk(avr[j].x, avr[j].y);                \
            Ab[(a_kw + 2 * j + 1) * SA + a_m] = h2pk(avr[j].z, avr[j].w);                \
        }                                                                                \
        _Pragma("unroll")                                                                \
        for (int j = 0; j < 2; ++j) {                                                    \
            uint4 w;                                                                    \
            w.x = h2pk(blo[j].x, bhi[j].x);                                              \
            w.y = h2pk(blo[j].y, bhi[j].y);                                              \
            w.z = h2pk(blo[j].z, bhi[j].z);                                              \
            w.w = h2pk(blo[j].w, bhi[j].w);                                              \
            *(uint4*)&Bd[b_kp * SA + b_n4 + 64 * j] = w;                                 \
        }                                                                                \
    }

    LDG_T(0);
    STS_T(0);
    __syncthreads();

    for (int kb = 0; kb < nk; ++kb) {
        const int cur = kb & 1;
        const bool more = (kb + 1 < nk);
        if (more) LDG_T((kb + 1) * 32);

        const uint32_t* Ac = Asm + cur * 16 * SA;
        const uint32_t* Bc = Bsm + cur * 16 * SA;
#pragma unroll
        for (int kw = 0; kw < 16; kw += 8) {
            uint32_t af[4][4], bf[4][2];
#pragma unroll
            for (int mt = 0; mt < 4; ++mt) {
                int mb = wm * 64 + mt * 16 + r;
                af[mt][0] = Ac[(kw + c) * SA + mb];
                af[mt][1] = Ac[(kw + c) * SA + mb + 8];
                af[mt][2] = Ac[(kw + c + 4) * SA + mb];
                af[mt][3] = Ac[(kw + c + 4) * SA + mb + 8];
            }
#pragma unroll
            for (int nt = 0; nt < 4; ++nt) {
                int nb = wn * 32 + nt * 8 + r;
                bf[nt][0] = Bc[(kw + c) * SA + nb];
                bf[nt][1] = Bc[(kw + c + 4) * SA + nb];
            }
#pragma unroll
            for (int mt = 0; mt < 4; ++mt)
#pragma unroll
                for (int nt = 0; nt < 4; ++nt)
                    mma_f16(acc[mt][nt], af[mt], bf[nt]);
        }
        if (more) STS_T(cur ^ 1);
        __syncthreads();
    }
#undef LDG_T
#undef STS_T

#pragma unroll
    for (int mt = 0; mt < 4; ++mt) {
#pragma unroll
        for (int h = 0; h < 2; ++h) {
            const int row = m0 + wm * 64 + mt * 16 + h * 8 + r;
            float bval = bias[row];
#pragma unroll
            for (int nt = 0; nt < 4; ++nt) {
                const int col = n0 + wn * 32 + nt * 8 + c * 2;
                float2 o;
                o.x = acc[mt][nt][h * 2 + 0] + bval;
                o.y = acc[mt][nt][h * 2 + 1] + bval;
                *(float2*)&Yb[(size_t)row * Ndim + col] = o;
            }
        }
    }
}

// ============================================================================
// Fused flash attention, fp16 MMA. Q roped+packed on load; K pre-roped fp32
// -> packed; V packed along position. Online softmax unchanged (fp32).
// smem words: Qs[32][136] Ks[32][72] Vs[64][36] Ps[32][136] cmb[512]
// ============================================================================
#define FSA 136
#define FSK 72
#define FSV2 36
#define FSP 136
#define OFF_KS 4352
#define OFF_VS 6656
#define OFF_PS 8960
#define OFF_CMB 13312
#define FLASH_SMEM (13824 * 4)

__global__ __launch_bounds__(256, 2)
void flash_attn(const float* __restrict__ Qg, const float* __restrict__ Kg,
                const float* __restrict__ Vg, const float* __restrict__ cmask,
                float* __restrict__ O)
{
    extern __shared__ uint32_t sm[];
    uint32_t* Qs  = sm;
    uint32_t* Ks  = sm + OFF_KS;
    uint32_t* Vs  = sm + OFF_VS;
    uint32_t* Ps  = sm + OFF_PS;
    float*    cmb = (float*)(sm + OFF_CMB);

    const int bh = blockIdx.z;
    const int b  = bh >> 2;
    const int m0 = blockIdx.y * 128;
    const int tid = threadIdx.x, wid = tid >> 5, lane = tid & 31;
    const int r = lane >> 2, c = lane & 3;
    const int mb = wid * 16 + r;

    const float* Qb = Qg + (size_t)bh * KC * TT;
    const float* Kb = Kg + (size_t)bh * KC * TSL;
    const float* Vb = Vg + (size_t)bh * KC * TSL;

    // ---- load Q tile with RoPE, pack d-pairs into half2 words ----
    {
        const int e  = tid >> 4;            // d-pair 0..15
        const int mg = (tid & 15) * 8;
        float av[2][8], bv2[2][8];
#pragma unroll
        for (int dof = 0; dof < 2; ++dof) {
            const int d = 2 * e + dof;
#pragma unroll
            for (int j = 0; j < 8; j += 4) {
                float4 q1 = *(const float4*)&Qb[(size_t)d * TT + m0 + mg + j];
                float4 q2 = *(const float4*)&Qb[(size_t)(d + 32) * TT + m0 + mg + j];
                float4 cv = *(const float4*)&g_cos[(size_t)d * TT + m0 + mg + j];
                float4 sv = *(const float4*)&g_sin[(size_t)d * TT + m0 + mg + j];
                av[dof][j + 0] = q1.x * cv.x - q2.x * sv.x;
                av[dof][j + 1] = q1.y * cv.y - q2.y * sv.y;
                av[dof][j + 2] = q1.z * cv.z - q2.z * sv.z;
                av[dof][j + 3] = q1.w * cv.w - q2.w * sv.w;
                bv2[dof][j + 0] = q2.x * cv.x + q1.x * sv.x;
                bv2[dof][j + 1] = q2.y * cv.y + q1.y * sv.y;
                bv2[dof][j + 2] = q2.z * cv.z + q1.z * sv.z;
                bv2[dof][j + 3] = q2.w * cv.w + q1.w * sv.w;
            }
        }
#pragma unroll
        for (int j = 0; j < 8; ++j) {
            Qs[e * FSA + mg + j]        = h2pk(av[0][j],  av[1][j]);
            Qs[(e + 16) * FSA + mg + j] = h2pk(bv2[0][j], bv2[1][j]);
        }
    }
    for (int i = tid; i < TSL; i += 256)
        cmb[i] = (cmask[(size_t)b * TSL + i] == 0.f) ? -1e4f : 0.f;

    // ---- prefetch chunk 0 ----
    const int e2 = tid >> 3;            // K d-pair 0..31
    const int n8 = (tid & 7) * 8;
    const int ch = tid >> 2;            // V channel 0..63
    const int kc = (tid & 3) * 16;
    float4 kr[4], vr[4];
#pragma unroll
    for (int j = 0; j < 2; ++j) {
        kr[j]     = *(const float4*)&Kb[(size_t)(2 * e2)     * TSL + n8 + 4 * j];
        kr[j + 2] = *(const float4*)&Kb[(size_t)(2 * e2 + 1) * TSL + n8 + 4 * j];
    }
#pragma unroll
    for (int j = 0; j < 4; ++j)
        vr[j] = *(const float4*)&Vb[(size_t)ch * TSL + kc + 4 * j];

    float m_run[2] = {-1e30f, -1e30f};
    float l_run[2] = {0.f, 0.f};
    float acc_o[8][4] = {};

    __syncthreads();

    for (int ci = 0; ci < 8; ++ci) {
        const int s0 = ci * 64;
        // ---- store prefetched K/V (pack half2) ----
        {
            uint4 w0, w1;
            w0.x = h2pk(kr[0].x, kr[2].x); w0.y = h2pk(kr[0].y, kr[2].y);
            w0.z = h2pk(kr[0].z, kr[2].z); w0.w = h2pk(kr[0].w, kr[2].w);
            w1.x = h2pk(kr[1].x, kr[3].x); w1.y = h2pk(kr[1].y, kr[3].y);
            w1.z = h2pk(kr[1].z, kr[3].z); w1.w = h2pk(kr[1].w, kr[3].w);
            *(uint4*)&Ks[e2 * FSK + n8]     = w0;
            *(uint4*)&Ks[e2 * FSK + n8 + 4] = w1;
            uint4 v0, v1;
            v0.x = h2pk(vr[0].x, vr[0].y); v0.y = h2pk(vr[0].z, vr[0].w);
            v0.z = h2pk(vr[1].x, vr[1].y); v0.w = h2pk(vr[1].z, vr[1].w);
            v1.x = h2pk(vr[2].x, vr[2].y); v1.y = h2pk(vr[2].z, vr[2].w);
            v1.z = h2pk(vr[3].x, vr[3].y); v1.w = h2pk(vr[3].z, vr[3].w);
            *(uint4*)&Vs[ch * FSV2 + (kc >> 1)]     = v0;
            *(uint4*)&Vs[ch * FSV2 + (kc >> 1) + 4] = v1;
        }
        __syncthreads();
        if (ci < 7) {
#pragma unroll
            for (int j = 0; j < 2; ++j) {
                kr[j]     = *(const float4*)&Kb[(size_t)(2 * e2)     * TSL + s0 + 64 + n8 + 4 * j];
                kr[j + 2] = *(const float4*)&Kb[(size_t)(2 * e2 + 1) * TSL + s0 + 64 + n8 + 4 * j];
            }
#pragma unroll
            for (int j = 0; j < 4; ++j)
                vr[j] = *(const float4*)&Vb[(size_t)ch * TSL + s0 + 64 + kc + 4 * j];
        }

        // ---- S = Q^T K : warp tile 16 x 64, K=64 (4 fp16 MMA steps) ----
        float acc_s[8][4] = {};
#pragma unroll
        for (int kw = 0; kw < 32; kw += 8) {
            uint32_t af[4];
            af[0] = Qs[(kw + c) * FSA + mb];
            af[1] = Qs[(kw + c) * FSA + mb + 8];
            af[2] = Qs[(kw + c + 4) * FSA + mb];
            af[3] = Qs[(kw + c + 4) * FSA + mb + 8];
#pragma unroll
            for (int nt = 0; nt < 8; ++nt) {
                uint32_t bf[2];
                bf[0] = Ks[(kw + c) * FSK + nt * 8 + r];
                bf[1] = Ks[(kw + c + 4) * FSK + nt * 8 + r];
                mma_f16(acc_s[nt], af, bf);
            }
        }

        // ---- scale + bias + online softmax (fp32, unchanged) ----
        float mx[2] = {-1e30f, -1e30f};
#pragma unroll
        for (int nt = 0; nt < 8; ++nt) {
            float2 bias = *(float2*)&cmb[s0 + nt * 8 + 2 * c];
#pragma unroll
            for (int jj = 0; jj < 4; ++jj) {
                float v = acc_s[nt][jj] * 0.125f + ((jj & 1) ? bias.y : bias.x);
                acc_s[nt][jj] = v;
                mx[jj >> 1] = fmaxf(mx[jj >> 1], v);
            }
        }
#pragma unroll
        for (int h = 0; h < 2; ++h) {
            mx[h] = fmaxf(mx[h], __shfl_xor_sync(0xffffffffu, mx[h], 1));
            mx[h] = fmaxf(mx[h], __shfl_xor_sync(0xffffffffu, mx[h], 2));
        }
        float mnew[2], scale[2], lad[2] = {0.f, 0.f};
#pragma unroll
        for (int h = 0; h < 2; ++h) {
            mnew[h]  = fmaxf(m_run[h], mx[h]);
            scale[h] = __expf(m_run[h] - mnew[h]);
            m_run[h] = mnew[h];
        }
#pragma unroll
        for (int nt = 0; nt < 8; ++nt) {
#pragma unroll
            for (int jj = 0; jj < 4; ++jj) {
                float e = __expf(acc_s[nt][jj] - mnew[jj >> 1]);
                acc_s[nt][jj] = e;
                lad[jj >> 1] += e;
            }
        }
#pragma unroll
        for (int h = 0; h < 2; ++h) {
            lad[h] += __shfl_xor_sync(0xffffffffu, lad[h], 1);
            lad[h] += __shfl_xor_sync(0xffffffffu, lad[h], 2);
            l_run[h] = l_run[h] * scale[h] + lad[h];
        }
#pragma unroll
        for (int nt = 0; nt < 8; ++nt) {
#pragma unroll
            for (int jj = 0; jj < 4; ++jj)
                acc_o[nt][jj] *= scale[jj >> 1];
        }
        // P -> smem: pack position-pairs (2c, 2c+1) into one word
#pragma unroll
        for (int nt = 0; nt < 8; ++nt) {
            int kwp = nt * 4 + c;
            Ps[kwp * FSP + wid * 16 + r]     = h2pk(acc_s[nt][0], acc_s[nt][1]);
            Ps[kwp * FSP + wid * 16 + r + 8] = h2pk(acc_s[nt][2], acc_s[nt][3]);
        }
        __syncwarp();

        // ---- O += P @ V^T : K=64 (4 fp16 MMA steps) ----
#pragma unroll
        for (int kw = 0; kw < 32; kw += 8) {
            uint32_t af[4];
            af[0] = Ps[(kw + c) * FSP + mb];
            af[1] = Ps[(kw + c) * FSP + mb + 8];
            af[2] = Ps[(kw + c + 4) * FSP + mb];
            af[3] = Ps[(kw + c + 4) * FSP + mb + 8];
#pragma unroll
            for (int nt = 0; nt < 8; ++nt) {
                uint32_t bf[2];
                bf[0] = Vs[(nt * 8 + r) * FSV2 + kw + c];
                bf[1] = Vs[(nt * 8 + r) * FSV2 + kw + c + 4];
                mma_f16(acc_o[nt], af, bf);
            }
        }
        __syncthreads();
    }

    // ---- epilogue: /l, transpose via smem (reuses Q/K/V region), store ----
    float inv[2] = {1.f / l_run[0], 1.f / l_run[1]};
    float* Pf = (float*)sm;    // [64][136] floats
#pragma unroll
    for (int nt = 0; nt < 8; ++nt) {
#pragma unroll
        for (int jj = 0; jj < 4; ++jj) {
            int n = nt * 8 + 2 * c + (jj & 1);
            int m = wid * 16 + r + (jj >> 1) * 8;
            Pf[n * FSA + m] = acc_o[nt][jj] * inv[jj >> 1];
        }
    }
    __syncthreads();
    {
        int row = tid >> 2;
        int mq  = (tid & 3) * 4;
#pragma unroll
        for (int j = 0; j < 8; ++j) {
            int m = mq + 16 * j;
            *(float4*)&O[((size_t)bh * KC + row) * TT + m0 + m] =
                *(float4*)&Pf[row * FSA + m];
        }
    }
}

// ============================================================================
// Fused FiLM GEMM, fp16 MMA, dual accumulator (gamma+beta share B).
// K = 256 -> 8 BK=32 slabs (16 half2 word-rows each). 512 threads.
// ============================================================================
#define FILM_SMEM (6 * 16 * SA * 4)

__global__ __launch_bounds__(512)
void film_gemm(const float* __restrict__ Wf, const float* __restrict__ Yin,
               const float* __restrict__ bfilm, const float* __restrict__ x,
               const float* __restrict__ xmask, float* __restrict__ out)
{
    extern __shared__ uint32_t smf[];
    uint32_t* AsG = smf;                  // [2][16*SA]
    uint32_t* AsB = smf + 2 * 16 * SA;
    uint32_t* Bs  = smf + 4 * 16 * SA;

    const int tid = threadIdx.x;
    const int bz  = blockIdx.z;
    const float* Bb = Yin + (size_t)bz * CH * TT;
    const int m0 = blockIdx.y * 128, n0 = blockIdx.x * 128;

    const int wid = tid >> 5, lane = tid & 31;
    const int wm = wid >> 2, wn = wid & 3;
    const int r = lane >> 2, c = lane & 3;

    // A loader: 4 word-cols per thread, bank-staggered row remap
    const int a_kw = (tid & 3) * 4;                    // word col base 0,4,8,12
    const int a_m  = ((tid >> 2) + (tid & 3) * 8) & 127;
    // B loader: k-pair row, 4 word cols
    const int b_kp = tid >> 5;                          // 0..15
    const int b_n4 = (tid & 31) * 4;

    float acc_g[2][4][4] = {};
    float acc_b[2][4][4] = {};

    float4 ag0, ag1, ab0, ab1, blo, bhi;
#define LDG_TILE_F(k0)                                                                   \
    {                                                                                    \
        ag0 = *(const float4*)&Wf[(size_t)(m0 + a_m) * CH + (k0) + a_kw * 2];            \
        ag1 = *(const float4*)&Wf[(size_t)(m0 + a_m) * CH + (k0) + a_kw * 2 + 4];        \
        ab0 = *(const float4*)&Wf[(size_t)(256 + m0 + a_m) * CH + (k0) + a_kw * 2];      \
        ab1 = *(const float4*)&Wf[(size_t)(256 + m0 + a_m) * CH + (k0) + a_kw * 2 + 4];  \
        blo = *(const float4*)&Bb[(size_t)((k0) + 2 * b_kp)     * TT + n0 + b_n4];       \
        bhi = *(const float4*)&Bb[(size_t)((k0) + 2 * b_kp + 1) * TT + n0 + b_n4];       \
    }
#define STS_TILE_F(buf)                                                                  \
    {                                                                                    \
        uint32_t* G = AsG + (buf) * 16 * SA;                                             \
        uint32_t* Bq = AsB + (buf) * 16 * SA;                                            \
        G[(a_kw + 0) * SA + a_m] = h2pk(ag0.x, ag0.y);                                   \
        G[(a_kw + 1) * SA + a_m] = h2pk(ag0.z, ag0.w);                                   \
        G[(a_kw + 2) * SA + a_m] = h2pk(ag1.x, ag1.y);                                   \
        G[(a_kw + 3) * SA + a_m] = h2pk(ag1.z, ag1.w);                                   \
        Bq[(a_kw + 0) * SA + a_m] = h2pk(ab0.x, ab0.y);                                  \
        Bq[(a_kw + 1) * SA + a_m] = h2pk(ab0.z, ab0.w);                                  \
        Bq[(a_kw + 2) * SA + a_m] = h2pk(ab1.x, ab1.y);                                  \
        Bq[(a_kw + 3) * SA + a_m] = h2pk(ab1.z, ab1.w);                                  \
        uint4 w;                                                                         \
        w.x = h2pk(blo.x, bhi.x); w.y = h2pk(blo.y, bhi.y);                              \
        w.z = h2pk(blo.z, bhi.z); w.w = h2pk(blo.w, bhi.w);                              \
        *(uint4*)&Bs[(buf) * 16 * SA + b_kp * SA + b_n4] = w;                            \
    }

    LDG_TILE_F(0);
    STS_TILE_F(0);
    __syncthreads();

    const int nk = CH / 32;   // 8 slabs
    for (int kb = 0; kb < nk; ++kb) {
        const int cur = kb & 1;
        const bool more = (kb + 1 < nk);
        if (more) LDG_TILE_F((kb + 1) * 32);

#pragma unroll
        for (int kw = 0; kw < 16; kw += 8) {
            uint32_t afg[2][4], afb[2][4], bf[4][2];
#pragma unroll
            for (int mt = 0; mt < 2; ++mt) {
                int mbx = wm * 32 + mt * 16 + r;
                afg[mt][0] = AsG[cur * 16 * SA + (kw + c) * SA + mbx];
                afg[mt][1] = AsG[cur * 16 * SA + (kw + c) * SA + mbx + 8];
                afg[mt][2] = AsG[cur * 16 * SA + (kw + c + 4) * SA + mbx];
                afg[mt][3] = AsG[cur * 16 * SA + (kw + c + 4) * SA + mbx + 8];
                afb[mt][0] = AsB[cur * 16 * SA + (kw + c) * SA + mbx];
                afb[mt][1] = AsB[cur * 16 * SA + (kw + c) * SA + mbx + 8];
                afb[mt][2] = AsB[cur * 16 * SA + (kw + c + 4) * SA + mbx];
                afb[mt][3] = AsB[cur * 16 * SA + (kw + c + 4) * SA + mbx + 8];
            }
#pragma unroll
            for (int nt = 0; nt < 4; ++nt) {
                int nb = wn * 32 + nt * 8 + r;
                bf[nt][0] = Bs[cur * 16 * SA + (kw + c) * SA + nb];
                bf[nt][1] = Bs[cur * 16 * SA + (kw + c + 4) * SA + nb];
            }
#pragma unroll
            for (int mt = 0; mt < 2; ++mt)
#pragma unroll
                for (int nt = 0; nt < 4; ++nt) {
                    mma_f16(acc_g[mt][nt], afg[mt], bf[nt]);
                    mma_f16(acc_b[mt][nt], afb[mt], bf[nt]);
                }
        }
        if (more) STS_TILE_F(cur ^ 1);
        __syncthreads();
    }
#undef LDG_TILE_F
#undef STS_TILE_F

#pragma unroll
    for (int mt = 0; mt < 2; ++mt) {
#pragma unroll
        for (int h = 0; h < 2; ++h) {
            const int row = m0 + wm * 32 + mt * 16 + r + h * 8;
            float bg = bfilm[row];
            float bb = bfilm[256 + row];
#pragma unroll
            for (int nt = 0; nt < 4; ++nt) {
                const int col = n0 + wn * 32 + nt * 8 + c * 2;
                float g0  = acc_g[mt][nt][h * 2 + 0] + bg;
                float g1  = acc_g[mt][nt][h * 2 + 1] + bg;
                float be0 = acc_b[mt][nt][h * 2 + 0] + bb;
                float be1 = acc_b[mt][nt][h * 2 + 1] + bb;
                float2 xv = *(const float2*)&x[((size_t)bz * CH + row) * TT + col];
                float xmm0 = xmask[(size_t)bz * TT + col];
                float xmm1 = xmask[(size_t)bz * TT + col + 1];
                float2 o;
                o.x = (xv.x * g0 + be0) * xmm0;
                o.y = (xv.y * g1 + be1) * xmm1;
                *(float2*)&out[((size_t)bz * CH + row) * TT + col] = o;
            }
        }
    }
}

// ---------------- launch ----------------
extern "C" void kernel_launch(void* const* d_in, const int* in_sizes, int n_in,
                              void* d_out, int out_size) {
    const float* x           = (const float*)d_in[0];
    const float* x_mask      = (const float*)d_in[1];
    const float* cond_latent = (const float*)d_in[2];
    const float* cond_mask   = (const float*)d_in[3];
    const float* w_cond      = (const float*)d_in[4];
    const float* b_cond      = (const float*)d_in[5];
    const float* wq          = (const float*)d_in[6];
    const float* bq          = (const float*)d_in[7];
    const float* wk          = (const float*)d_in[8];
    const float* bk          = (const float*)d_in[9];
    const float* wv          = (const float*)d_in[10];
    const float* bv          = (const float*)d_in[11];
    const float* wo          = (const float*)d_in[12];
    const float* bo          = (const float*)d_in[13];
    const float* w_film      = (const float*)d_in[14];
    const float* b_film      = (const float*)d_in[15];
    float* out = (float*)d_out;

    float *p_q, *p_k, *p_v, *p_att, *p_wkc, *p_wvc, *p_wfo, *p_bkc, *p_bvc, *p_bfo, *p_zero;
    cudaGetSymbolAddress((void**)&p_q,    g_q);
    cudaGetSymbolAddress((void**)&p_k,    g_k);
    cudaGetSymbolAddress((void**)&p_v,    g_v);
    cudaGetSymbolAddress((void**)&p_att,  g_att);
    cudaGetSymbolAddress((void**)&p_wkc,  g_wkc);
    cudaGetSymbolAddress((void**)&p_wvc,  g_wvc);
    cudaGetSymbolAddress((void**)&p_wfo,  g_wfo);
    cudaGetSymbolAddress((void**)&p_bkc,  g_bkc);
    cudaGetSymbolAddress((void**)&p_bvc,  g_bvc);
    cudaGetSymbolAddress((void**)&p_bfo,  g_bfo);
    cudaGetSymbolAddress((void**)&p_zero, g_zero);

    cudaFuncSetAttribute(mma_gemm64<0>, cudaFuncAttributeMaxDynamicSharedMemorySize, GEMM_SMEM);
    cudaFuncSetAttribute(mma_gemm64<1>, cudaFuncAttributeMaxDynamicSharedMemorySize, GEMM_SMEM);
    cudaFuncSetAttribute(mma_gemm64<2>, cudaFuncAttributeMaxDynamicSharedMemorySize, GEMM_SMEM);
    cudaFuncSetAttribute(flash_attn,    cudaFuncAttributeMaxDynamicSharedMemorySize, FLASH_SMEM);
    cudaFuncSetAttribute(film_gemm,     cudaFuncAttributeMaxDynamicSharedMemorySize, FILM_SMEM);

    // prologue
    rope_table_kernel<<<(32 * TT + 255) / 256, 256>>>();
    bias_combine2_kernel<<<4, 256>>>(wk, bk, wv, bv, b_cond, w_film, b_film, bo);

    // merged weight combines: z0 wkc=wk@w_cond, z1 wvc=wv@w_cond, z2 wfo=w_film@wo
    mma_gemm64<2><<<dim3(4, 4, 3), 256, GEMM_SMEM>>>(
        wk, wv, w_film, w_cond, wo, p_zero, p_zero,
        p_wkc, p_wvc, p_wfo, 0, CH, 0, 0);

    // q = wq @ x + bq
    mma_gemm64<0><<<dim3(TT / 128, CH / 128, BQ), 256, GEMM_SMEM>>>(
        wq, nullptr, nullptr, x, nullptr, bq, nullptr, p_q, nullptr, nullptr,
        TT, CH, (size_t)CH * TT, (size_t)CH * TT);

    // k = wkc @ cond_latent + bkc ; v = wvc @ cond_latent + bvc   (K = 512)
    mma_gemm64<1><<<dim3(TSL / 128, CH / 128, 2 * BQ), 256, GEMM_SMEM>>>(
        p_wkc, p_wvc, nullptr, cond_latent, nullptr, p_bkc, p_bvc, p_k, p_v, nullptr,
        TSL, CONDC, (size_t)CONDC * TSL, (size_t)CH * TSL);

    // rope + cond-mask K in place
    rope_k_mask_kernel<<<(BQ * NH * 32 * TSL + 255) / 256, 256>>>(p_k, cond_mask);

    // fused attention
    flash_attn<<<dim3(1, TT / 128, BQ * NH), 256, FLASH_SMEM>>>(
        p_q, p_k, p_v, cond_mask, p_att);

    // fused FiLM: gamma/beta = wfo @ att + bfo
    film_gemm<<<dim3(TT / 128, CH / 128, BQ), 512, FILM_SMEM>>>(
        p_wfo, p_att, p_bfo, x, x_mask, out);
}

// round 12
// speedup vs baseline: 1.4618x; 1.0294x over previous
#include <cuda_runtime.h>
#include <math.h>
#include <stdint.h>

// ---------------- problem constants (fixed shapes) ----------------
#define BQ   16
#define CH   256
#define CONDC 512
#define TT   2048
#define TSL  512
#define NH   4
#define KC   64

#define SA 136       // padded smem stride (words): mod 32 = 8, *4 % 16 == 0

// ---------------- scratch (device globals; no allocation) ----------------
__device__ float g_q  [BQ * CH * TT];         // q fp32 (flash ropes+packs)
__device__ float g_k  [BQ * CH * TSL];        // k roped+masked fp32 (done in kv epilogue)
__device__ float g_v  [BQ * CH * TSL];        // v fp32
__device__ float g_att[BQ * CH * TT];         // attn out fp32
__device__ float g_wkc[CH * CONDC];           // wk @ w_cond
__device__ float g_wvc[CH * CONDC];           // wv @ w_cond
__device__ float g_wfo[2 * CH * CH];          // w_film @ wo
__device__ float g_bkc[CH];
__device__ float g_bvc[CH];
__device__ float g_bfo[2 * CH];
__device__ float g_zero[512];
__device__ float g_cos[32 * TT];              // [d][t]
__device__ float g_sin[32 * TT];

// ---------------- fp16 helpers ----------------
__device__ __forceinline__ uint32_t h2pk(float lo, float hi) {
    uint32_t u;
    asm("cvt.rn.f16x2.f32 %0, %1, %2;" : "=r"(u) : "f"(hi), "f"(lo));
    return u;
}

__device__ __forceinline__ void mma_f16(float* c, const uint32_t* a, const uint32_t* b) {
    asm volatile(
        "mma.sync.aligned.m16n8k16.row.col.f32.f16.f16.f32 "
        "{%0,%1,%2,%3}, {%4,%5,%6,%7}, {%8,%9}, {%0,%1,%2,%3};\n"
        : "+f"(c[0]), "+f"(c[1]), "+f"(c[2]), "+f"(c[3])
        : "r"(a[0]), "r"(a[1]), "r"(a[2]), "r"(a[3]), "r"(b[0]), "r"(b[1]));
}

// ---------------- RoPE tables, layout [d][t] ----------------
__global__ void rope_table_kernel() {
    int idx = blockIdx.x * blockDim.x + threadIdx.x;
    if (idx >= 32 * TT) return;
    int d = idx / TT;
    int t = idx % TT;
    float invf = (float)pow(10000.0, -(double)d / 32.0);
    float ang  = (float)t * invf;            // same fp32 rounding as reference
    g_cos[idx] = (float)cos((double)ang);
    g_sin[idx] = (float)sin((double)ang);
}

// ---------------- combined biases (full fp32) ----------------
__global__ void bias_combine2_kernel(const float* __restrict__ wk, const float* __restrict__ bk,
                                     const float* __restrict__ wv, const float* __restrict__ bv,
                                     const float* __restrict__ b_cond,
                                     const float* __restrict__ wf, const float* __restrict__ bf,
                                     const float* __restrict__ bo) {
    int tid = blockIdx.x * 256 + threadIdx.x;   // 0..1023
    if (tid < 256) {
        float s = 0.f;
        for (int k = 0; k < CH; ++k) s += wk[tid * CH + k] * b_cond[k];
        g_bkc[tid] = s + bk[tid];
    } else if (tid < 512) {
        int m = tid - 256;
        float s = 0.f;
        for (int k = 0; k < CH; ++k) s += wv[m * CH + k] * b_cond[k];
        g_bvc[m] = s + bv[m];
    } else {
        int m = tid - 512;
        float s = 0.f;
        for (int k = 0; k < CH; ++k) s += wf[m * CH + k] * bo[k];
        g_bfo[m] = s + bf[m];
    }
}

// ============================================================================
// fp16 MMA GEMM, 128x128 CTA tile, 256 threads (8 warps, 2x4), warp tile 64x32,
// BK=32 floats (16 half2 words/slab), double-buffered dynamic smem.
// GSEL 0: plain. GSEL 1: kv-fused (z&15 batch, z>>4 sel; sel==0 (k) applies
// rope + cond-mask in the epilogue). GSEL 2: merged weight combines.
// ============================================================================
#define GEMM_SMEM (4 * 16 * SA * 4)

template<int GSEL>
__global__ __launch_bounds__(256, 2)
void mma_gemm64(const float* __restrict__ A0, const float* __restrict__ A1,
                const float* __restrict__ A2,
                const float* __restrict__ B0, const float* __restrict__ B1,
                const float* __restrict__ bias0, const float* __restrict__ bias1,
                float* __restrict__ Y0, float* __restrict__ Y1, float* __restrict__ Y2,
                const float* __restrict__ cmask,
                int Ndim, int Kdim, size_t strideB, size_t strideY)
{
    extern __shared__ uint32_t smg[];
    uint32_t* Asm = smg;                 // [2][16*SA]
    uint32_t* Bsm = smg + 2 * 16 * SA;   // [2][16*SA]

    const int tid = threadIdx.x;
    int bz = 0, sel = 0;
    if (GSEL == 1)      { bz = blockIdx.z & 15; sel = blockIdx.z >> 4; }
    else if (GSEL == 2) { sel = blockIdx.z; }
    else                { bz = blockIdx.z; }

    const float* A;
    const float* bias;
    float*       Y;
    const float* Bsrc = B0;
    if (GSEL == 2) {
        A    = (sel == 0) ? A0 : (sel == 1) ? A1 : A2;
        Y    = (sel == 0) ? Y0 : (sel == 1) ? Y1 : Y2;
        bias = bias0;   // zero
        if (sel == 2) Bsrc = B1;
        int Md = (sel < 2) ? 256 : 512;
        Ndim   = (sel < 2) ? 512 : 256;
        if ((int)blockIdx.y * 128 >= Md || (int)blockIdx.x * 128 >= Ndim) return;
    } else {
        A    = (GSEL == 1 && sel) ? A1 : A0;
        bias = (GSEL == 1 && sel) ? bias1 : bias0;
        Y    = (GSEL == 1 && sel) ? Y1 : Y0;
    }
    const float* Bb = Bsrc + (size_t)bz * strideB;
    float*       Yb = Y    + (size_t)bz * strideY;
    const int m0 = blockIdx.y * 128, n0 = blockIdx.x * 128;

    const int wid = tid >> 5, lane = tid & 31;
    const int wm = wid >> 2, wn = wid & 3;
    const int r = lane >> 2, c = lane & 3;

    const int a_m  = ((tid >> 1) + ((tid & 1) << 4)) & 127;
    const int a_kw = (tid & 1) * 8;
    const int b_kp = tid >> 4;
    const int b_n4 = (tid & 15) * 4;

    float acc[4][4][4] = {};
    const int nk = Kdim / 32;

    float4 avr[4], blo[2], bhi[2];
#define LDG_T(k0)                                                                        \
    {                                                                                    \
        _Pragma("unroll")                                                                \
        for (int j = 0; j < 4; ++j)                                                      \
            avr[j] = *(const float4*)&A[(size_t)(m0 + a_m) * Kdim + (k0) + a_kw * 2 + 4 * j]; \
        _Pragma("unroll")                                                                \
        for (int j = 0; j < 2; ++j) {                                                    \
            blo[j] = *(const float4*)&Bb[(size_t)((k0) + 2 * b_kp)     * Ndim + n0 + b_n4 + 64 * j]; \
            bhi[j] = *(const float4*)&Bb[(size_t)((k0) + 2 * b_kp + 1) * Ndim + n0 + b_n4 + 64 * j]; \
        }                                                                                \
    }
#define STS_T(buf)                                                                       \
    {                                                                                    \
        uint32_t* Ab = Asm + (buf) * 16 * SA;                                            \
        uint32_t* Bd = Bsm + (buf) * 16 * SA;                                            \
        _Pragma("unroll")                                                                \
        for (int j = 0; j < 4; ++j) {                                                    \
            Ab[(a_kw + 2 * j + 0) * SA + a_m] = h2pk(avr[j].x, avr[j].y);                \
            Ab[(a_kw + 2 * j + 1) * SA + a_m] = h2pk(avr[j].z, avr[j].w);                \
        }                                                                                \
        _Pragma("unroll")                                                                \
        for (int j = 0; j < 2; ++j) {                                                    \
            uint4 w;                                                                    \
            w.x = h2pk(blo[j].x, bhi[j].x);                                              \
            w.y = h2pk(blo[j].y, bhi[j].y);                                              \
            w.z = h2pk(blo[j].z, bhi[j].z);                                              \
            w.w = h2pk(blo[j].w, bhi[j].w);                                              \
            *(uint4*)&Bd[b_kp * SA + b_n4 + 64 * j] = w;                                 \
        }                                                                                \
    }

    LDG_T(0);
    STS_T(0);
    __syncthreads();

    for (int kb = 0; kb < nk; ++kb) {
        const int cur = kb & 1;
        const bool more = (kb + 1 < nk);
        if (more) LDG_T((kb + 1) * 32);

        const uint32_t* Ac = Asm + cur * 16 * SA;
        const uint32_t* Bc = Bsm + cur * 16 * SA;
#pragma unroll
        for (int kw = 0; kw < 16; kw += 8) {
            uint32_t af[4][4], bf[4][2];
#pragma unroll
            for (int mt = 0; mt < 4; ++mt) {
                int mb = wm * 64 + mt * 16 + r;
                af[mt][0] = Ac[(kw + c) * SA + mb];
                af[mt][1] = Ac[(kw + c) * SA + mb + 8];
                af[mt][2] = Ac[(kw + c + 4) * SA + mb];
                af[mt][3] = Ac[(kw + c + 4) * SA + mb + 8];
            }
#pragma unroll
            for (int nt = 0; nt < 4; ++nt) {
                int nb = wn * 32 + nt * 8 + r;
                bf[nt][0] = Bc[(kw + c) * SA + nb];
                bf[nt][1] = Bc[(kw + c + 4) * SA + nb];
            }
#pragma unroll
            for (int mt = 0; mt < 4; ++mt)
#pragma unroll
                for (int nt = 0; nt < 4; ++nt)
                    mma_f16(acc[mt][nt], af[mt], bf[nt]);
        }
        if (more) STS_T(cur ^ 1);
        __syncthreads();
    }
#undef LDG_T
#undef STS_T

    if (GSEL == 1 && sel == 0) {
        // ---- k epilogue: bias + RoPE + cond-mask, paired rows (d, d+32) ----
#pragma unroll
        for (int mtl = 0; mtl < 2; ++mtl) {
#pragma unroll
            for (int h = 0; h < 2; ++h) {
                const int row_lo = m0 + wm * 64 + mtl * 16 + h * 8 + r;  // d in [0,32)
                const int row_hi = row_lo + 32;
                const int d = row_lo & 63;
                float b_lo = bias[row_lo], b_hi = bias[row_hi];
#pragma unroll
                for (int nt = 0; nt < 4; ++nt) {
                    const int col = n0 + wn * 32 + nt * 8 + c * 2;
                    float2 cs = *(const float2*)&g_cos[(size_t)d * TT + col];
                    float2 sn = *(const float2*)&g_sin[(size_t)d * TT + col];
                    float2 cm = *(const float2*)&cmask[(size_t)bz * TSL + col];
                    float k1x = acc[mtl][nt][h * 2 + 0] + b_lo;
                    float k1y = acc[mtl][nt][h * 2 + 1] + b_lo;
                    float k2x = acc[mtl + 2][nt][h * 2 + 0] + b_hi;
                    float k2y = acc[mtl + 2][nt][h * 2 + 1] + b_hi;
                    float2 olo, ohi;
                    olo.x = (k1x * cs.x - k2x * sn.x) * cm.x;
                    olo.y = (k1y * cs.y - k2y * sn.y) * cm.y;
                    ohi.x = (k2x * cs.x + k1x * sn.x) * cm.x;
                    ohi.y = (k2y * cs.y + k1y * sn.y) * cm.y;
                    *(float2*)&Yb[(size_t)row_lo * Ndim + col] = olo;
                    *(float2*)&Yb[(size_t)row_hi * Ndim + col] = ohi;
                }
            }
        }
    } else {
#pragma unroll
        for (int mt = 0; mt < 4; ++mt) {
#pragma unroll
            for (int h = 0; h < 2; ++h) {
                const int row = m0 + wm * 64 + mt * 16 + h * 8 + r;
                float bval = bias[row];
#pragma unroll
                for (int nt = 0; nt < 4; ++nt) {
                    const int col = n0 + wn * 32 + nt * 8 + c * 2;
                    float2 o;
                    o.x = acc[mt][nt][h * 2 + 0] + bval;
                    o.y = acc[mt][nt][h * 2 + 1] + bval;
                    *(float2*)&Yb[(size_t)row * Ndim + col] = o;
                }
            }
        }
    }
}

// ============================================================================
// Fused flash attention, fp16 MMA, fixed-shift softmax (no online max:
// scores bounded ~|1|, masked = -1e4 -> exp underflows to 0; softmax is
// shift-invariant so result is identical to the max-subtracted form).
// smem words: Qs[32][136] Ks[32][72] Vs[64][36] Ps[32][136] cmb[512]
// ============================================================================
#define FSA 136
#define FSK 72
#define FSV2 36
#define FSP 136
#define OFF_KS 4352
#define OFF_VS 6656
#define OFF_PS 8960
#define OFF_CMB 13312
#define FLASH_SMEM (13824 * 4)

__global__ __launch_bounds__(256, 2)
void flash_attn(const float* __restrict__ Qg, const float* __restrict__ Kg,
                const float* __restrict__ Vg, const float* __restrict__ cmask,
                float* __restrict__ O)
{
    extern __shared__ uint32_t sm[];
    uint32_t* Qs  = sm;
    uint32_t* Ks  = sm + OFF_KS;
    uint32_t* Vs  = sm + OFF_VS;
    uint32_t* Ps  = sm + OFF_PS;
    float*    cmb = (float*)(sm + OFF_CMB);

    const int bh = blockIdx.z;
    const int b  = bh >> 2;
    const int m0 = blockIdx.y * 128;
    const int tid = threadIdx.x, wid = tid >> 5, lane = tid & 31;
    const int r = lane >> 2, c = lane & 3;
    const int mb = wid * 16 + r;

    const float* Qb = Qg + (size_t)bh * KC * TT;
    const float* Kb = Kg + (size_t)bh * KC * TSL;
    const float* Vb = Vg + (size_t)bh * KC * TSL;

    // ---- load Q tile with RoPE, pack d-pairs into half2 words ----
    {
        const int e  = tid >> 4;            // d-pair 0..15
        const int mg = (tid & 15) * 8;
        float av[2][8], bv2[2][8];
#pragma unroll
        for (int dof = 0; dof < 2; ++dof) {
            const int d = 2 * e + dof;
#pragma unroll
            for (int j = 0; j < 8; j += 4) {
                float4 q1 = *(const float4*)&Qb[(size_t)d * TT + m0 + mg + j];
                float4 q2 = *(const float4*)&Qb[(size_t)(d + 32) * TT + m0 + mg + j];
                float4 cv = *(const float4*)&g_cos[(size_t)d * TT + m0 + mg + j];
                float4 sv = *(const float4*)&g_sin[(size_t)d * TT + m0 + mg + j];
                av[dof][j + 0] = q1.x * cv.x - q2.x * sv.x;
                av[dof][j + 1] = q1.y * cv.y - q2.y * sv.y;
                av[dof][j + 2] = q1.z * cv.z - q2.z * sv.z;
                av[dof][j + 3] = q1.w * cv.w - q2.w * sv.w;
                bv2[dof][j + 0] = q2.x * cv.x + q1.x * sv.x;
                bv2[dof][j + 1] = q2.y * cv.y + q1.y * sv.y;
                bv2[dof][j + 2] = q2.z * cv.z + q1.z * sv.z;
                bv2[dof][j + 3] = q2.w * cv.w + q1.w * sv.w;
            }
        }
#pragma unroll
        for (int j = 0; j < 8; ++j) {
            Qs[e * FSA + mg + j]        = h2pk(av[0][j],  av[1][j]);
            Qs[(e + 16) * FSA + mg + j] = h2pk(bv2[0][j], bv2[1][j]);
        }
    }
    for (int i = tid; i < TSL; i += 256)
        cmb[i] = (cmask[(size_t)b * TSL + i] == 0.f) ? -1e4f : 0.f;

    // ---- prefetch chunk 0 ----
    const int e2 = tid >> 3;            // K d-pair 0..31
    const int n8 = (tid & 7) * 8;
    const int ch = tid >> 2;            // V channel 0..63
    const int kc = (tid & 3) * 16;
    float4 kr[4], vr[4];
#pragma unroll
    for (int j = 0; j < 2; ++j) {
        kr[j]     = *(const float4*)&Kb[(size_t)(2 * e2)     * TSL + n8 + 4 * j];
        kr[j + 2] = *(const float4*)&Kb[(size_t)(2 * e2 + 1) * TSL + n8 + 4 * j];
    }
#pragma unroll
    for (int j = 0; j < 4; ++j)
        vr[j] = *(const float4*)&Vb[(size_t)ch * TSL + kc + 4 * j];

    float l_run[2] = {0.f, 0.f};
    float acc_o[8][4] = {};

    __syncthreads();

    for (int ci = 0; ci < 8; ++ci) {
        const int s0 = ci * 64;
        // ---- store prefetched K/V (pack half2) ----
        {
            uint4 w0, w1;
            w0.x = h2pk(kr[0].x, kr[2].x); w0.y = h2pk(kr[0].y, kr[2].y);
            w0.z = h2pk(kr[0].z, kr[2].z); w0.w = h2pk(kr[0].w, kr[2].w);
            w1.x = h2pk(kr[1].x, kr[3].x); w1.y = h2pk(kr[1].y, kr[3].y);
            w1.z = h2pk(kr[1].z, kr[3].z); w1.w = h2pk(kr[1].w, kr[3].w);
            *(uint4*)&Ks[e2 * FSK + n8]     = w0;
            *(uint4*)&Ks[e2 * FSK + n8 + 4] = w1;
            uint4 v0, v1;
            v0.x = h2pk(vr[0].x, vr[0].y); v0.y = h2pk(vr[0].z, vr[0].w);
            v0.z = h2pk(vr[1].x, vr[1].y); v0.w = h2pk(vr[1].z, vr[1].w);
            v1.x = h2pk(vr[2].x, vr[2].y); v1.y = h2pk(vr[2].z, vr[2].w);
            v1.z = h2pk(vr[3].x, vr[3].y); v1.w = h2pk(vr[3].z, vr[3].w);
            *(uint4*)&Vs[ch * FSV2 + (kc >> 1)]     = v0;
            *(uint4*)&Vs[ch * FSV2 + (kc >> 1) + 4] = v1;
        }
        __syncthreads();
        if (ci < 7) {
#pragma unroll
            for (int j = 0; j < 2; ++j) {
                kr[j]     = *(const float4*)&Kb[(size_t)(2 * e2)     * TSL + s0 + 64 + n8 + 4 * j];
                kr[j + 2] = *(const float4*)&Kb[(size_t)(2 * e2 + 1) * TSL + s0 + 64 + n8 + 4 * j];
            }
#pragma unroll
            for (int j = 0; j < 4; ++j)
                vr[j] = *(const float4*)&Vb[(size_t)ch * TSL + s0 + 64 + kc + 4 * j];
        }

        // ---- S = Q^T K : warp tile 16 x 64, K=64 (4 fp16 MMA steps) ----
        float acc_s[8][4] = {};
#pragma unroll
        for (int kw = 0; kw < 32; kw += 8) {
            uint32_t af[4];
            af[0] = Qs[(kw + c) * FSA + mb];
            af[1] = Qs[(kw + c) * FSA + mb + 8];
            af[2] = Qs[(kw + c + 4) * FSA + mb];
            af[3] = Qs[(kw + c + 4) * FSA + mb + 8];
#pragma unroll
            for (int nt = 0; nt < 8; ++nt) {
                uint32_t bf[2];
                bf[0] = Ks[(kw + c) * FSK + nt * 8 + r];
                bf[1] = Ks[(kw + c + 4) * FSK + nt * 8 + r];
                mma_f16(acc_s[nt], af, bf);
            }
        }

        // ---- scale + bias + exp (fixed shift), accumulate row sums ----
        float lad[2] = {0.f, 0.f};
#pragma unroll
        for (int nt = 0; nt < 8; ++nt) {
            float2 bias = *(float2*)&cmb[s0 + nt * 8 + 2 * c];
#pragma unroll
            for (int jj = 0; jj < 4; ++jj) {
                float e = __expf(acc_s[nt][jj] * 0.125f + ((jj & 1) ? bias.y : bias.x));
                acc_s[nt][jj] = e;
                lad[jj >> 1] += e;
            }
        }
#pragma unroll
        for (int h = 0; h < 2; ++h) {
            lad[h] += __shfl_xor_sync(0xffffffffu, lad[h], 1);
            lad[h] += __shfl_xor_sync(0xffffffffu, lad[h], 2);
            l_run[h] += lad[h];
        }
        // P -> smem: pack position-pairs (2c, 2c+1) into one word
#pragma unroll
        for (int nt = 0; nt < 8; ++nt) {
            int kwp = nt * 4 + c;
            Ps[kwp * FSP + wid * 16 + r]     = h2pk(acc_s[nt][0], acc_s[nt][1]);
            Ps[kwp * FSP + wid * 16 + r + 8] = h2pk(acc_s[nt][2], acc_s[nt][3]);
        }
        __syncwarp();

        // ---- O += P @ V^T : K=64 (4 fp16 MMA steps) ----
#pragma unroll
        for (int kw = 0; kw < 32; kw += 8) {
            uint32_t af[4];
            af[0] = Ps[(kw + c) * FSP + mb];
            af[1] = Ps[(kw + c) * FSP + mb + 8];
            af[2] = Ps[(kw + c + 4) * FSP + mb];
            af[3] = Ps[(kw + c + 4) * FSP + mb + 8];
#pragma unroll
            for (int nt = 0; nt < 8; ++nt) {
                uint32_t bf[2];
                bf[0] = Vs[(nt * 8 + r) * FSV2 + kw + c];
                bf[1] = Vs[(nt * 8 + r) * FSV2 + kw + c + 4];
                mma_f16(acc_o[nt], af, bf);
            }
        }
        __syncthreads();
    }

    // ---- epilogue: /l, transpose via smem, coalesced store ----
    float inv[2] = {1.f / l_run[0], 1.f / l_run[1]};
    float* Pf = (float*)sm;    // [64][136] floats
#pragma unroll
    for (int nt = 0; nt < 8; ++nt) {
#pragma unroll
        for (int jj = 0; jj < 4; ++jj) {
            int n = nt * 8 + 2 * c + (jj & 1);
            int m = wid * 16 + r + (jj >> 1) * 8;
            Pf[n * FSA + m] = acc_o[nt][jj] * inv[jj >> 1];
        }
    }
    __syncthreads();
    {
        int row = tid >> 2;
        int mq  = (tid & 3) * 4;
#pragma unroll
        for (int j = 0; j < 8; ++j) {
            int m = mq + 16 * j;
            *(float4*)&O[((size_t)bh * KC + row) * TT + m0 + m] =
                *(float4*)&Pf[row * FSA + m];
        }
    }
}

// ============================================================================
// Fused FiLM GEMM, fp16 MMA, dual accumulator (unchanged from R11)
// ============================================================================
#define FILM_SMEM (6 * 16 * SA * 4)

__global__ __launch_bounds__(512)
void film_gemm(const float* __restrict__ Wf, const float* __restrict__ Yin,
               const float* __restrict__ bfilm, const float* __restrict__ x,
               const float* __restrict__ xmask, float* __restrict__ out)
{
    extern __shared__ uint32_t smf[];
    uint32_t* AsG = smf;
    uint32_t* AsB = smf + 2 * 16 * SA;
    uint32_t* Bs  = smf + 4 * 16 * SA;

    const int tid = threadIdx.x;
    const int bz  = blockIdx.z;
    const float* Bb = Yin + (size_t)bz * CH * TT;
    const int m0 = blockIdx.y * 128, n0 = blockIdx.x * 128;

    const int wid = tid >> 5, lane = tid & 31;
    const int wm = wid >> 2, wn = wid & 3;
    const int r = lane >> 2, c = lane & 3;

    const int a_kw = (tid & 3) * 4;
    const int a_m  = ((tid >> 2) + (tid & 3) * 8) & 127;
    const int b_kp = tid >> 5;
    const int b_n4 = (tid & 31) * 4;

    float acc_g[2][4][4] = {};
    float acc_b[2][4][4] = {};

    float4 ag0, ag1, ab0, ab1, blo, bhi;
#define LDG_TILE_F(k0)                                                                   \
    {                                                                                    \
        ag0 = *(const float4*)&Wf[(size_t)(m0 + a_m) * CH + (k0) + a_kw * 2];            \
        ag1 = *(const float4*)&Wf[(size_t)(m0 + a_m) * CH + (k0) + a_kw * 2 + 4];        \
        ab0 = *(const float4*)&Wf[(size_t)(256 + m0 + a_m) * CH + (k0) + a_kw * 2];      \
        ab1 = *(const float4*)&Wf[(size_t)(256 + m0 + a_m) * CH + (k0) + a_kw * 2 + 4];  \
        blo = *(const float4*)&Bb[(size_t)((k0) + 2 * b_kp)     * TT + n0 + b_n4];       \
        bhi = *(const float4*)&Bb[(size_t)((k0) + 2 * b_kp + 1) * TT + n0 + b_n4];       \
    }
#define STS_TILE_F(buf)                                                                  \
    {                                                                                    \
        uint32_t* G = AsG + (buf) * 16 * SA;                                             \
        uint32_t* Bq = AsB + (buf) * 16 * SA;                                            \
        G[(a_kw + 0) * SA + a_m] = h2pk(ag0.x, ag0.y);                                   \
        G[(a_kw + 1) * SA + a_m] = h2pk(ag0.z, ag0.w);                                   \
        G[(a_kw + 2) * SA + a_m] = h2pk(ag1.x, ag1.y);                                   \
        G[(a_kw + 3) * SA + a_m] = h2pk(ag1.z, ag1.w);                                   \
        Bq[(a_kw + 0) * SA + a_m] = h2pk(ab0.x, ab0.y);                                  \
        Bq[(a_kw + 1) * SA + a_m] = h2pk(ab0.z, ab0.w);                                  \
        Bq[(a_kw + 2) * SA + a_m] = h2pk(ab1.x, ab1.y);                                  \
        Bq[(a_kw + 3) * SA + a_m] = h2pk(ab1.z, ab1.w);                                  \
        uint4 w;                                                                         \
        w.x = h2pk(blo.x, bhi.x); w.y = h2pk(blo.y, bhi.y);                              \
        w.z = h2pk(blo.z, bhi.z); w.w = h2pk(blo.w, bhi.w);                              \
        *(uint4*)&Bs[(buf) * 16 * SA + b_kp * SA + b_n4] = w;                            \
    }

    LDG_TILE_F(0);
    STS_TILE_F(0);
    __syncthreads();

    const int nk = CH / 32;
    for (int kb = 0; kb < nk; ++kb) {
        const int cur = kb & 1;
        const bool more = (kb + 1 < nk);
        if (more) LDG_TILE_F((kb + 1) * 32);

#pragma unroll
        for (int kw = 0; kw < 16; kw += 8) {
            uint32_t afg[2][4], afb[2][4], bf[4][2];
#pragma unroll
            for (int mt = 0; mt < 2; ++mt) {
                int mbx = wm * 32 + mt * 16 + r;
                afg[mt][0] = AsG[cur * 16 * SA + (kw + c) * SA + mbx];
                afg[mt][1] = AsG[cur * 16 * SA + (kw + c) * SA + mbx + 8];
                afg[mt][2] = AsG[cur * 16 * SA + (kw + c + 4) * SA + mbx];
                afg[mt][3] = AsG[cur * 16 * SA + (kw + c + 4) * SA + mbx + 8];
                afb[mt][0] = AsB[cur * 16 * SA + (kw + c) * SA + mbx];
                afb[mt][1] = AsB[cur * 16 * SA + (kw + c) * SA + mbx + 8];
                afb[mt][2] = AsB[cur * 16 * SA + (kw + c + 4) * SA + mbx];
                afb[mt][3] = AsB[cur * 16 * SA + (kw + c + 4) * SA + mbx + 8];
            }
#pragma unroll
            for (int nt = 0; nt < 4; ++nt) {
                int nb = wn * 32 + nt * 8 + r;
                bf[nt][0] = Bs[cur * 16 * SA + (kw + c) * SA + nb];
                bf[nt][1] = Bs[cur * 16 * SA + (kw + c + 4) * SA + nb];
            }
#pragma unroll
            for (int mt = 0; mt < 2; ++mt)
#pragma unroll
                for (int nt = 0; nt < 4; ++nt) {
                    mma_f16(acc_g[mt][nt], afg[mt], bf[nt]);
                    mma_f16(acc_b[mt][nt], afb[mt], bf[nt]);
                }
        }
        if (more) STS_TILE_F(cur ^ 1);
        __syncthreads();
    }
#undef LDG_TILE_F
#undef STS_TILE_F

#pragma unroll
    for (int mt = 0; mt < 2; ++mt) {
#pragma unroll
        for (int h = 0; h < 2; ++h) {
            const int row = m0 + wm * 32 + mt * 16 + r + h * 8;
            float bg = bfilm[row];
            float bb = bfilm[256 + row];
#pragma unroll
            for (int nt = 0; nt < 4; ++nt) {
                const int col = n0 + wn * 32 + nt * 8 + c * 2;
                float g0  = acc_g[mt][nt][h * 2 + 0] + bg;
                float g1  = acc_g[mt][nt][h * 2 + 1] + bg;
                float be0 = acc_b[mt][nt][h * 2 + 0] + bb;
                float be1 = acc_b[mt][nt][h * 2 + 1] + bb;
                float2 xv = *(const float2*)&x[((size_t)bz * CH + row) * TT + col];
                float xmm0 = xmask[(size_t)bz * TT + col];
                float xmm1 = xmask[(size_t)bz * TT + col + 1];
                float2 o;
                o.x = (xv.x * g0 + be0) * xmm0;
                o.y = (xv.y * g1 + be1) * xmm1;
                *(float2*)&out[((size_t)bz * CH + row) * TT + col] = o;
            }
        }
    }
}

// ---------------- launch ----------------
extern "C" void kernel_launch(void* const* d_in, const int* in_sizes, int n_in,
                              void* d_out, int out_size) {
    const float* x           = (const float*)d_in[0];
    const float* x_mask      = (const float*)d_in[1];
    const float* cond_latent = (const float*)d_in[2];
    const float* cond_mask   = (const float*)d_in[3];
    const float* w_cond      = (const float*)d_in[4];
    const float* b_cond      = (const float*)d_in[5];
    const float* wq          = (const float*)d_in[6];
    const float* bq          = (const float*)d_in[7];
    const float* wk          = (const float*)d_in[8];
    const float* bk          = (const float*)d_in[9];
    const float* wv          = (const float*)d_in[10];
    const float* bv          = (const float*)d_in[11];
    const float* wo          = (const float*)d_in[12];
    const float* bo          = (const float*)d_in[13];
    const float* w_film      = (const float*)d_in[14];
    const float* b_film      = (const float*)d_in[15];
    float* out = (float*)d_out;

    float *p_q, *p_k, *p_v, *p_att, *p_wkc, *p_wvc, *p_wfo, *p_bkc, *p_bvc, *p_bfo, *p_zero;
    cudaGetSymbolAddress((void**)&p_q,    g_q);
    cudaGetSymbolAddress((void**)&p_k,    g_k);
    cudaGetSymbolAddress((void**)&p_v,    g_v);
    cudaGetSymbolAddress((void**)&p_att,  g_att);
    cudaGetSymbolAddress((void**)&p_wkc,  g_wkc);
    cudaGetSymbolAddress((void**)&p_wvc,  g_wvc);
    cudaGetSymbolAddress((void**)&p_wfo,  g_wfo);
    cudaGetSymbolAddress((void**)&p_bkc,  g_bkc);
    cudaGetSymbolAddress((void**)&p_bvc,  g_bvc);
    cudaGetSymbolAddress((void**)&p_bfo,  g_bfo);
    cudaGetSymbolAddress((void**)&p_zero, g_zero);

    cudaFuncSetAttribute(mma_gemm64<0>, cudaFuncAttributeMaxDynamicSharedMemorySize, GEMM_SMEM);
    cudaFuncSetAttribute(mma_gemm64<1>, cudaFuncAttributeMaxDynamicSharedMemorySize, GEMM_SMEM);
    cudaFuncSetAttribute(mma_gemm64<2>, cudaFuncAttributeMaxDynamicSharedMemorySize, GEMM_SMEM);
    cudaFuncSetAttribute(flash_attn,    cudaFuncAttributeMaxDynamicSharedMemorySize, FLASH_SMEM);
    cudaFuncSetAttribute(film_gemm,     cudaFuncAttributeMaxDynamicSharedMemorySize, FILM_SMEM);

    // prologue
    rope_table_kernel<<<(32 * TT + 255) / 256, 256>>>();
    bias_combine2_kernel<<<4, 256>>>(wk, bk, wv, bv, b_cond, w_film, b_film, bo);

    // merged weight combines: z0 wkc=wk@w_cond, z1 wvc=wv@w_cond, z2 wfo=w_film@wo
    mma_gemm64<2><<<dim3(4, 4, 3), 256, GEMM_SMEM>>>(
        wk, wv, w_film, w_cond, wo, p_zero, p_zero,
        p_wkc, p_wvc, p_wfo, nullptr, 0, CH, 0, 0);

    // q = wq @ x + bq
    mma_gemm64<0><<<dim3(TT / 128, CH / 128, BQ), 256, GEMM_SMEM>>>(
        wq, nullptr, nullptr, x, nullptr, bq, nullptr, p_q, nullptr, nullptr,
        nullptr, TT, CH, (size_t)CH * TT, (size_t)CH * TT);

    // k = rope+mask(wkc @ cl + bkc) ; v = wvc @ cl + bvc   (K = 512)
    mma_gemm64<1><<<dim3(TSL / 128, CH / 128, 2 * BQ), 256, GEMM_SMEM>>>(
        p_wkc, p_wvc, nullptr, cond_latent, nullptr, p_bkc, p_bvc, p_k, p_v, nullptr,
        cond_mask, TSL, CONDC, (size_t)CONDC * TSL, (size_t)CH * TSL);

    // fused attention (fixed-shift softmax)
    flash_attn<<<dim3(1, TT / 128, BQ * NH), 256, FLASH_SMEM>>>(
        p_q, p_k, p_v, cond_mask, p_att);

    // fused FiLM: gamma/beta = wfo @ att + bfo
    film_gemm<<<dim3(TT / 128, CH / 128, BQ), 512, FILM_SMEM>>>(
        p_wfo, p_att, p_bfo, x, x_mask, out);
}

// round 13
// speedup vs baseline: 1.4705x; 1.0059x over previous
#include <cuda_runtime.h>
#include <math.h>
#include <stdint.h>

// ---------------- problem constants (fixed shapes) ----------------
#define BQ   16
#define CH   256
#define CONDC 512
#define TT   2048
#define TSL  512
#define NH   4
#define KC   64

#define SA 136       // padded smem stride (words): mod 32 = 8, *4 % 16 == 0

// ---------------- scratch (device globals; no allocation) ----------------
__device__ float g_q  [BQ * CH * TT];         // q roped fp32 (done in gemm epilogue)
__device__ float g_k  [BQ * CH * TSL];        // k roped+masked fp32 (gemm epilogue)
__device__ float g_v  [BQ * CH * TSL];        // v fp32
__device__ float g_att[BQ * CH * TT];         // attn out fp32
__device__ float g_wkc[CH * CONDC];           // wk @ w_cond
__device__ float g_wvc[CH * CONDC];           // wv @ w_cond
__device__ float g_wfo[2 * CH * CH];          // w_film @ wo
__device__ float g_bkc[CH];
__device__ float g_bvc[CH];
__device__ float g_bfo[2 * CH];
__device__ float g_zero[512];
__device__ float g_cos[32 * TT];              // [d][t]
__device__ float g_sin[32 * TT];

// ---------------- fp16 helpers ----------------
__device__ __forceinline__ uint32_t h2pk(float lo, float hi) {
    uint32_t u;
    asm("cvt.rn.f16x2.f32 %0, %1, %2;" : "=r"(u) : "f"(hi), "f"(lo));
    return u;
}

__device__ __forceinline__ void mma_f16(float* c, const uint32_t* a, const uint32_t* b) {
    asm volatile(
        "mma.sync.aligned.m16n8k16.row.col.f32.f16.f16.f32 "
        "{%0,%1,%2,%3}, {%4,%5,%6,%7}, {%8,%9}, {%0,%1,%2,%3};\n"
        : "+f"(c[0]), "+f"(c[1]), "+f"(c[2]), "+f"(c[3])
        : "r"(a[0]), "r"(a[1]), "r"(a[2]), "r"(a[3]), "r"(b[0]), "r"(b[1]));
}

// ---------------- RoPE tables, layout [d][t] ----------------
__global__ void rope_table_kernel() {
    int idx = blockIdx.x * blockDim.x + threadIdx.x;
    if (idx >= 32 * TT) return;
    int d = idx / TT;
    int t = idx % TT;
    float invf = (float)pow(10000.0, -(double)d / 32.0);
    float ang  = (float)t * invf;            // same fp32 rounding as reference
    g_cos[idx] = (float)cos((double)ang);
    g_sin[idx] = (float)sin((double)ang);
}

// ---------------- combined biases (full fp32) ----------------
__global__ void bias_combine2_kernel(const float* __restrict__ wk, const float* __restrict__ bk,
                                     const float* __restrict__ wv, const float* __restrict__ bv,
                                     const float* __restrict__ b_cond,
                                     const float* __restrict__ wf, const float* __restrict__ bf,
                                     const float* __restrict__ bo) {
    int tid = blockIdx.x * 256 + threadIdx.x;   // 0..1023
    if (tid < 256) {
        float s = 0.f;
        for (int k = 0; k < CH; ++k) s += wk[tid * CH + k] * b_cond[k];
        g_bkc[tid] = s + bk[tid];
    } else if (tid < 512) {
        int m = tid - 256;
        float s = 0.f;
        for (int k = 0; k < CH; ++k) s += wv[m * CH + k] * b_cond[k];
        g_bvc[m] = s + bv[m];
    } else {
        int m = tid - 512;
        float s = 0.f;
        for (int k = 0; k < CH; ++k) s += wf[m * CH + k] * bo[k];
        g_bfo[m] = s + bf[m];
    }
}

// ============================================================================
// fp16 MMA GEMM, 128x128 CTA tile, 256 threads (8 warps, 2x4), warp tile 64x32,
// BK=32 floats, double-buffered dynamic smem.
// GSEL 2: merged weight combines (z: 0 wkc, 1 wvc, 2 wfo; zero bias).
// GSEL 3: merged q + kv launch.
//   z < 16  : q (batch z)  B=x,  K=256, N=2048, epilogue rope (no mask)
//   z >= 16 : kv ((z-16)&15 batch, >>4 sel) B=cl, K=512, N=512;
//             sel 0 -> k, epilogue rope+mask; sel 1 -> v, plain. x>=4 exits.
// emode: 0 plain, 1 rope+mask, 2 rope.
// ============================================================================
#define GEMM_SMEM (4 * 16 * SA * 4)

template<int GSEL>
__global__ __launch_bounds__(256, 2)
void mma_gemm64(const float* __restrict__ A0, const float* __restrict__ A1,
                const float* __restrict__ A2,
                const float* __restrict__ B0, const float* __restrict__ B1,
                const float* __restrict__ bias0, const float* __restrict__ bias1,
                const float* __restrict__ bias2,
                float* __restrict__ Y0, float* __restrict__ Y1, float* __restrict__ Y2,
                const float* __restrict__ cmask)
{
    extern __shared__ uint32_t smg[];
    uint32_t* Asm = smg;                 // [2][16*SA]
    uint32_t* Bsm = smg + 2 * 16 * SA;   // [2][16*SA]

    const int tid = threadIdx.x;
    int bz = 0, emode = 0, Ndim, Kdim;
    size_t strideB = 0, strideY = 0;
    const float* A;
    const float* bias;
    const float* Bsrc;
    float*       Y;

    if (GSEL == 2) {
        const int sel = blockIdx.z;
        A    = (sel == 0) ? A0 : (sel == 1) ? A1 : A2;
        Y    = (sel == 0) ? Y0 : (sel == 1) ? Y1 : Y2;
        bias = bias0;                     // zero
        Bsrc = (sel == 2) ? B1 : B0;
        int Md = (sel < 2) ? 256 : 512;
        Ndim   = (sel < 2) ? 512 : 256;
        Kdim   = CH;
        if ((int)blockIdx.y * 128 >= Md || (int)blockIdx.x * 128 >= Ndim) return;
    } else { // GSEL == 3
        const int z = blockIdx.z;
        if (z < 16) {
            bz = z;
            A = A0; bias = bias0; Y = Y0; Bsrc = B0;
            emode = 2; Ndim = TT; Kdim = CH;
            strideB = (size_t)CH * TT; strideY = (size_t)CH * TT;
        } else {
            if (blockIdx.x >= TSL / 128) return;
            const int zz = z - 16;
            bz = zz & 15;
            const int sel = zz >> 4;
            A    = sel ? A2 : A1;
            bias = sel ? bias2 : bias1;
            Y    = sel ? Y2 : Y1;
            Bsrc = B1;
            emode = sel ? 0 : 1;
            Ndim = TSL; Kdim = CONDC;
            strideB = (size_t)CONDC * TSL; strideY = (size_t)CH * TSL;
        }
    }
    const float* Bb = Bsrc + (size_t)bz * strideB;
    float*       Yb = Y    + (size_t)bz * strideY;
    const int m0 = blockIdx.y * 128, n0 = blockIdx.x * 128;

    const int wid = tid >> 5, lane = tid & 31;
    const int wm = wid >> 2, wn = wid & 3;
    const int r = lane >> 2, c = lane & 3;

    const int a_m  = ((tid >> 1) + ((tid & 1) << 4)) & 127;
    const int a_kw = (tid & 1) * 8;
    const int b_kp = tid >> 4;
    const int b_n4 = (tid & 15) * 4;

    float acc[4][4][4] = {};
    const int nk = Kdim / 32;

    float4 avr[4], blo[2], bhi[2];
#define LDG_T(k0)                                                                        \
    {                                                                                    \
        _Pragma("unroll")                                                                \
        for (int j = 0; j < 4; ++j)                                                      \
            avr[j] = *(const float4*)&A[(size_t)(m0 + a_m) * Kdim + (k0) + a_kw * 2 + 4 * j]; \
        _Pragma("unroll")                                                                \
        for (int j = 0; j < 2; ++j) {                                                    \
            blo[j] = *(const float4*)&Bb[(size_t)((k0) + 2 * b_kp)     * Ndim + n0 + b_n4 + 64 * j]; \
            bhi[j] = *(const float4*)&Bb[(size_t)((k0) + 2 * b_kp + 1) * Ndim + n0 + b_n4 + 64 * j]; \
        }                                                                                \
    }
#define STS_T(buf)                                                                       \
    {                                                                                    \
        uint32_t* Ab = Asm + (buf) * 16 * SA;                                            \
        uint32_t* Bd = Bsm + (buf) * 16 * SA;                                            \
        _Pragma("unroll")                                                                \
        for (int j = 0; j < 4; ++j) {                                                    \
            Ab[(a_kw + 2 * j + 0) * SA + a_m] = h2pk(avr[j].x, avr[j].y);                \
            Ab[(a_kw + 2 * j + 1) * SA + a_m] = h2pk(avr[j].z, avr[j].w);                \
        }                                                                                \
        _Pragma("unroll")                                                                \
        for (int j = 0; j < 2; ++j) {                                                    \
            uint4 w;                                                                    \
            w.x = h2pk(blo[j].x, bhi[j].x);                                              \
            w.y = h2pk(blo[j].y, bhi[j].y);                                              \
            w.z = h2pk(blo[j].z, bhi[j].z);                                              \
            w.w = h2pk(blo[j].w, bhi[j].w);                                              \
            *(uint4*)&Bd[b_kp * SA + b_n4 + 64 * j] = w;                                 \
        }                                                                                \
    }

    LDG_T(0);
    STS_T(0);
    __syncthreads();

    for (int kb = 0; kb < nk; ++kb) {
        const int cur = kb & 1;
        const bool more = (kb + 1 < nk);
        if (more) LDG_T((kb + 1) * 32);

        const uint32_t* Ac = Asm + cur * 16 * SA;
        const uint32_t* Bc = Bsm + cur * 16 * SA;
#pragma unroll
        for (int kw = 0; kw < 16; kw += 8) {
            uint32_t af[4][4], bf[4][2];
#pragma unroll
            for (int mt = 0; mt < 4; ++mt) {
                int mb = wm * 64 + mt * 16 + r;
                af[mt][0] = Ac[(kw + c) * SA + mb];
                af[mt][1] = Ac[(kw + c) * SA + mb + 8];
                af[mt][2] = Ac[(kw + c + 4) * SA + mb];
                af[mt][3] = Ac[(kw + c + 4) * SA + mb + 8];
            }
#pragma unroll
            for (int nt = 0; nt < 4; ++nt) {
                int nb = wn * 32 + nt * 8 + r;
                bf[nt][0] = Bc[(kw + c) * SA + nb];
                bf[nt][1] = Bc[(kw + c + 4) * SA + nb];
            }
#pragma unroll
            for (int mt = 0; mt < 4; ++mt)
#pragma unroll
                for (int nt = 0; nt < 4; ++nt)
                    mma_f16(acc[mt][nt], af[mt], bf[nt]);
        }
        if (more) STS_T(cur ^ 1);
        __syncthreads();
    }
#undef LDG_T
#undef STS_T

    if (GSEL == 3 && emode != 0) {
        // ---- rope epilogue (+cond-mask when emode==1), paired rows (d, d+32) ----
#pragma unroll
        for (int mtl = 0; mtl < 2; ++mtl) {
#pragma unroll
            for (int h = 0; h < 2; ++h) {
                const int row_lo = m0 + wm * 64 + mtl * 16 + h * 8 + r;  // d in [0,32)
                const int row_hi = row_lo + 32;
                const int d = row_lo & 63;
                float b_lo = bias[row_lo], b_hi = bias[row_hi];
#pragma unroll
                for (int nt = 0; nt < 4; ++nt) {
                    const int col = n0 + wn * 32 + nt * 8 + c * 2;
                    float2 cs = *(const float2*)&g_cos[(size_t)d * TT + col];
                    float2 sn = *(const float2*)&g_sin[(size_t)d * TT + col];
                    float2 cm;
                    if (emode == 1) cm = *(const float2*)&cmask[(size_t)bz * TSL + col];
                    else            { cm.x = 1.f; cm.y = 1.f; }
                    float k1x = acc[mtl][nt][h * 2 + 0] + b_lo;
                    float k1y = acc[mtl][nt][h * 2 + 1] + b_lo;
                    float k2x = acc[mtl + 2][nt][h * 2 + 0] + b_hi;
                    float k2y = acc[mtl + 2][nt][h * 2 + 1] + b_hi;
                    float2 olo, ohi;
                    olo.x = (k1x * cs.x - k2x * sn.x) * cm.x;
                    olo.y = (k1y * cs.y - k2y * sn.y) * cm.y;
                    ohi.x = (k2x * cs.x + k1x * sn.x) * cm.x;
                    ohi.y = (k2y * cs.y + k1y * sn.y) * cm.y;
                    *(float2*)&Yb[(size_t)row_lo * Ndim + col] = olo;
                    *(float2*)&Yb[(size_t)row_hi * Ndim + col] = ohi;
                }
            }
        }
    } else {
#pragma unroll
        for (int mt = 0; mt < 4; ++mt) {
#pragma unroll
            for (int h = 0; h < 2; ++h) {
                const int row = m0 + wm * 64 + mt * 16 + h * 8 + r;
                float bval = bias[row];
#pragma unroll
                for (int nt = 0; nt < 4; ++nt) {
                    const int col = n0 + wn * 32 + nt * 8 + c * 2;
                    float2 o;
                    o.x = acc[mt][nt][h * 2 + 0] + bval;
                    o.y = acc[mt][nt][h * 2 + 1] + bval;
                    *(float2*)&Yb[(size_t)row * Ndim + col] = o;
                }
            }
        }
    }
}

// ============================================================================
// Fused flash attention, fp16 MMA, fixed-shift softmax in exp2 domain.
// Q and K arrive pre-roped fp32 -> pure pack loads. Masked bias = -14427
// (= -1e4 * log2 e) -> exp2 underflows to exactly 0.
// smem words: Qs[32][136] Ks[32][72] Vs[64][36] Ps[32][136] cmb[512]
// ============================================================================
#define FSA 136
#define FSK 72
#define FSV2 36
#define FSP 136
#define OFF_KS 4352
#define OFF_VS 6656
#define OFF_PS 8960
#define OFF_CMB 13312
#define FLASH_SMEM (13824 * 4)
#define SCALE_LOG2E 0.18033688f   // 0.125 * log2(e)

__global__ __launch_bounds__(256, 2)
void flash_attn(const float* __restrict__ Qg, const float* __restrict__ Kg,
                const float* __restrict__ Vg, const float* __restrict__ cmask,
                float* __restrict__ O)
{
    extern __shared__ uint32_t sm[];
    uint32_t* Qs  = sm;
    uint32_t* Ks  = sm + OFF_KS;
    uint32_t* Vs  = sm + OFF_VS;
    uint32_t* Ps  = sm + OFF_PS;
    float*    cmb = (float*)(sm + OFF_CMB);

    const int bh = blockIdx.z;
    const int b  = bh >> 2;
    const int m0 = blockIdx.y * 128;
    const int tid = threadIdx.x, wid = tid >> 5, lane = tid & 31;
    const int r = lane >> 2, c = lane & 3;
    const int mb = wid * 16 + r;

    const float* Qb = Qg + (size_t)bh * KC * TT;
    const float* Kb = Kg + (size_t)bh * KC * TSL;
    const float* Vb = Vg + (size_t)bh * KC * TSL;

    // ---- load Q tile: pure pack of adjacent pre-roped channel pairs ----
    {
        const int e  = tid >> 4;            // d-pair 0..15
        const int mg = (tid & 15) * 8;
#pragma unroll
        for (int hh = 0; hh < 2; ++hh) {
            const int ra = 2 * e + hh * 32;
#pragma unroll
            for (int j = 0; j < 8; j += 4) {
                float4 qa = *(const float4*)&Qb[(size_t)ra * TT + m0 + mg + j];
                float4 qb = *(const float4*)&Qb[(size_t)(ra + 1) * TT + m0 + mg + j];
                Qs[(e + hh * 16) * FSA + mg + j + 0] = h2pk(qa.x, qb.x);
                Qs[(e + hh * 16) * FSA + mg + j + 1] = h2pk(qa.y, qb.y);
                Qs[(e + hh * 16) * FSA + mg + j + 2] = h2pk(qa.z, qb.z);
                Qs[(e + hh * 16) * FSA + mg + j + 3] = h2pk(qa.w, qb.w);
            }
        }
    }
    for (int i = tid; i < TSL; i += 256)
        cmb[i] = (cmask[(size_t)b * TSL + i] == 0.f) ? -14427.0f : 0.f;

    // ---- prefetch chunk 0 ----
    const int e2 = tid >> 3;            // K d-pair 0..31
    const int n8 = (tid & 7) * 8;
    const int ch = tid >> 2;            // V channel 0..63
    const int kc = (tid & 3) * 16;
    float4 kr[4], vr[4];
#pragma unroll
    for (int j = 0; j < 2; ++j) {
        kr[j]     = *(const float4*)&Kb[(size_t)(2 * e2)     * TSL + n8 + 4 * j];
        kr[j + 2] = *(const float4*)&Kb[(size_t)(2 * e2 + 1) * TSL + n8 + 4 * j];
    }
#pragma unroll
    for (int j = 0; j < 4; ++j)
        vr[j] = *(const float4*)&Vb[(size_t)ch * TSL + kc + 4 * j];

    float l_run[2] = {0.f, 0.f};
    float acc_o[8][4] = {};

    __syncthreads();

    for (int ci = 0; ci < 8; ++ci) {
        const int s0 = ci * 64;
        // ---- store prefetched K/V (pack half2) ----
        {
            uint4 w0, w1;
            w0.x = h2pk(kr[0].x, kr[2].x); w0.y = h2pk(kr[0].y, kr[2].y);
            w0.z = h2pk(kr[0].z, kr[2].z); w0.w = h2pk(kr[0].w, kr[2].w);
            w1.x = h2pk(kr[1].x, kr[3].x); w1.y = h2pk(kr[1].y, kr[3].y);
            w1.z = h2pk(kr[1].z, kr[3].z); w1.w = h2pk(kr[1].w, kr[3].w);
            *(uint4*)&Ks[e2 * FSK + n8]     = w0;
            *(uint4*)&Ks[e2 * FSK + n8 + 4] = w1;
            uint4 v0, v1;
            v0.x = h2pk(vr[0].x, vr[0].y); v0.y = h2pk(vr[0].z, vr[0].w);
            v0.z = h2pk(vr[1].x, vr[1].y); v0.w = h2pk(vr[1].z, vr[1].w);
            v1.x = h2pk(vr[2].x, vr[2].y); v1.y = h2pk(vr[2].z, vr[2].w);
            v1.z = h2pk(vr[3].x, vr[3].y); v1.w = h2pk(vr[3].z, vr[3].w);
            *(uint4*)&Vs[ch * FSV2 + (kc >> 1)]     = v0;
            *(uint4*)&Vs[ch * FSV2 + (kc >> 1) + 4] = v1;
        }
        __syncthreads();
        if (ci < 7) {
#pragma unroll
            for (int j = 0; j < 2; ++j) {
                kr[j]     = *(const float4*)&Kb[(size_t)(2 * e2)     * TSL + s0 + 64 + n8 + 4 * j];
                kr[j + 2] = *(const float4*)&Kb[(size_t)(2 * e2 + 1) * TSL + s0 + 64 + n8 + 4 * j];
            }
#pragma unroll
            for (int j = 0; j < 4; ++j)
                vr[j] = *(const float4*)&Vb[(size_t)ch * TSL + s0 + 64 + kc + 4 * j];
        }

        // ---- S = Q^T K : warp tile 16 x 64, K=64 (4 fp16 MMA steps) ----
        float acc_s[8][4] = {};
#pragma unroll
        for (int kw = 0; kw < 32; kw += 8) {
            uint32_t af[4];
            af[0] = Qs[(kw + c) * FSA + mb];
            af[1] = Qs[(kw + c) * FSA + mb + 8];
            af[2] = Qs[(kw + c + 4) * FSA + mb];
            af[3] = Qs[(kw + c + 4) * FSA + mb + 8];
#pragma unroll
            for (int nt = 0; nt < 8; ++nt) {
                uint32_t bf[2];
                bf[0] = Ks[(kw + c) * FSK + nt * 8 + r];
                bf[1] = Ks[(kw + c + 4) * FSK + nt * 8 + r];
                mma_f16(acc_s[nt], af, bf);
            }
        }

        // ---- exp2(scale*s + bias), accumulate row sums ----
        float lad[2] = {0.f, 0.f};
#pragma unroll
        for (int nt = 0; nt < 8; ++nt) {
            float2 bias = *(float2*)&cmb[s0 + nt * 8 + 2 * c];
#pragma unroll
            for (int jj = 0; jj < 4; ++jj) {
                float e = exp2f(acc_s[nt][jj] * SCALE_LOG2E + ((jj & 1) ? bias.y : bias.x));
                acc_s[nt][jj] = e;
                lad[jj >> 1] += e;
            }
        }
#pragma unroll
        for (int h = 0; h < 2; ++h) {
            lad[h] += __shfl_xor_sync(0xffffffffu, lad[h], 1);
            lad[h] += __shfl_xor_sync(0xffffffffu, lad[h], 2);
            l_run[h] += lad[h];
        }
        // P -> smem: pack position-pairs (2c, 2c+1) into one word
#pragma unroll
        for (int nt = 0; nt < 8; ++nt) {
            int kwp = nt * 4 + c;
            Ps[kwp * FSP + wid * 16 + r]     = h2pk(acc_s[nt][0], acc_s[nt][1]);
            Ps[kwp * FSP + wid * 16 + r + 8] = h2pk(acc_s[nt][2], acc_s[nt][3]);
        }
        __syncwarp();

        // ---- O += P @ V^T : K=64 (4 fp16 MMA steps) ----
#pragma unroll
        for (int kw = 0; kw < 32; kw += 8) {
            uint32_t af[4];
            af[0] = Ps[(kw + c) * FSP + mb];
            af[1] = Ps[(kw + c) * FSP + mb + 8];
            af[2] = Ps[(kw + c + 4) * FSP + mb];
            af[3] = Ps[(kw + c + 4) * FSP + mb + 8];
#pragma unroll
            for (int nt = 0; nt < 8; ++nt) {
                uint32_t bf[2];
                bf[0] = Vs[(nt * 8 + r) * FSV2 + kw + c];
                bf[1] = Vs[(nt * 8 + r) * FSV2 + kw + c + 4];
                mma_f16(acc_o[nt], af, bf);
            }
        }
        __syncthreads();
    }

    // ---- epilogue: /l, transpose via smem, coalesced store ----
    float inv[2] = {1.f / l_run[0], 1.f / l_run[1]};
    float* Pf = (float*)sm;    // [64][136] floats
#pragma unroll
    for (int nt = 0; nt < 8; ++nt) {
#pragma unroll
        for (int jj = 0; jj < 4; ++jj) {
            int n = nt * 8 + 2 * c + (jj & 1);
            int m = wid * 16 + r + (jj >> 1) * 8;
            Pf[n * FSA + m] = acc_o[nt][jj] * inv[jj >> 1];
        }
    }
    __syncthreads();
    {
        int row = tid >> 2;
        int mq  = (tid & 3) * 4;
#pragma unroll
        for (int j = 0; j < 8; ++j) {
            int m = mq + 16 * j;
            *(float4*)&O[((size_t)bh * KC + row) * TT + m0 + m] =
                *(float4*)&Pf[row * FSA + m];
        }
    }
}

// ============================================================================
// Fused FiLM GEMM, fp16 MMA, dual accumulator (unchanged from R12)
// ============================================================================
#define FILM_SMEM (6 * 16 * SA * 4)

__global__ __launch_bounds__(512)
void film_gemm(const float* __restrict__ Wf, const float* __restrict__ Yin,
               const float* __restrict__ bfilm, const float* __restrict__ x,
               const float* __restrict__ xmask, float* __restrict__ out)
{
    extern __shared__ uint32_t smf[];
    uint32_t* AsG = smf;
    uint32_t* AsB = smf + 2 * 16 * SA;
    uint32_t* Bs  = smf + 4 * 16 * SA;

    const int tid = threadIdx.x;
    const int bz  = blockIdx.z;
    const float* Bb = Yin + (size_t)bz * CH * TT;
    const int m0 = blockIdx.y * 128, n0 = blockIdx.x * 128;

    const int wid = tid >> 5, lane = tid & 31;
    const int wm = wid >> 2, wn = wid & 3;
    const int r = lane >> 2, c = lane & 3;

    const int a_kw = (tid & 3) * 4;
    const int a_m  = ((tid >> 2) + (tid & 3) * 8) & 127;
    const int b_kp = tid >> 5;
    const int b_n4 = (tid & 31) * 4;

    float acc_g[2][4][4] = {};
    float acc_b[2][4][4] = {};

    float4 ag0, ag1, ab0, ab1, blo, bhi;
#define LDG_TILE_F(k0)                                                                   \
    {                                                                                    \
        ag0 = *(const float4*)&Wf[(size_t)(m0 + a_m) * CH + (k0) + a_kw * 2];            \
        ag1 = *(const float4*)&Wf[(size_t)(m0 + a_m) * CH + (k0) + a_kw * 2 + 4];        \
        ab0 = *(const float4*)&Wf[(size_t)(256 + m0 + a_m) * CH + (k0) + a_kw * 2];      \
        ab1 = *(const float4*)&Wf[(size_t)(256 + m0 + a_m) * CH + (k0) + a_kw * 2 + 4];  \
        blo = *(const float4*)&Bb[(size_t)((k0) + 2 * b_kp)     * TT + n0 + b_n4];       \
        bhi = *(const float4*)&Bb[(size_t)((k0) + 2 * b_kp + 1) * TT + n0 + b_n4];       \
    }
#define STS_TILE_F(buf)                                                                  \
    {                                                                                    \
        uint32_t* G = AsG + (buf) * 16 * SA;                                             \
        uint32_t* Bq = AsB + (buf) * 16 * SA;                                            \
        G[(a_kw + 0) * SA + a_m] = h2pk(ag0.x, ag0.y);                                   \
        G[(a_kw + 1) * SA + a_m] = h2pk(ag0.z, ag0.w);                                   \
        G[(a_kw + 2) * SA + a_m] = h2pk(ag1.x, ag1.y);                                   \
        G[(a_kw + 3) * SA + a_m] = h2pk(ag1.z, ag1.w);                                   \
        Bq[(a_kw + 0) * SA + a_m] = h2pk(ab0.x, ab0.y);                                  \
        Bq[(a_kw + 1) * SA + a_m] = h2pk(ab0.z, ab0.w);                                  \
        Bq[(a_kw + 2) * SA + a_m] = h2pk(ab1.x, ab1.y);                                  \
        Bq[(a_kw + 3) * SA + a_m] = h2pk(ab1.z, ab1.w);                                  \
        uint4 w;                                                                         \
        w.x = h2pk(blo.x, bhi.x); w.y = h2pk(blo.y, bhi.y);                              \
        w.z = h2pk(blo.z, bhi.z); w.w = h2pk(blo.w, bhi.w);                              \
        *(uint4*)&Bs[(buf) * 16 * SA + b_kp * SA + b_n4] = w;                            \
    }

    LDG_TILE_F(0);
    STS_TILE_F(0);
    __syncthreads();

    const int nk = CH / 32;
    for (int kb = 0; kb < nk; ++kb) {
        const int cur = kb & 1;
        const bool more = (kb + 1 < nk);
        if (more) LDG_TILE_F((kb + 1) * 32);

#pragma unroll
        for (int kw = 0; kw < 16; kw += 8) {
            uint32_t afg[2][4], afb[2][4], bf[4][2];
#pragma unroll
            for (int mt = 0; mt < 2; ++mt) {
                int mbx = wm * 32 + mt * 16 + r;
                afg[mt][0] = AsG[cur * 16 * SA + (kw + c) * SA + mbx];
                afg[mt][1] = AsG[cur * 16 * SA + (kw + c) * SA + mbx + 8];
                afg[mt][2] = AsG[cur * 16 * SA + (kw + c + 4) * SA + mbx];
                afg[mt][3] = AsG[cur * 16 * SA + (kw + c + 4) * SA + mbx + 8];
                afb[mt][0] = AsB[cur * 16 * SA + (kw + c) * SA + mbx];
                afb[mt][1] = AsB[cur * 16 * SA + (kw + c) * SA + mbx + 8];
                afb[mt][2] = AsB[cur * 16 * SA + (kw + c + 4) * SA + mbx];
                afb[mt][3] = AsB[cur * 16 * SA + (kw + c + 4) * SA + mbx + 8];
            }
#pragma unroll
            for (int nt = 0; nt < 4; ++nt) {
                int nb = wn * 32 + nt * 8 + r;
                bf[nt][0] = Bs[cur * 16 * SA + (kw + c) * SA + nb];
                bf[nt][1] = Bs[cur * 16 * SA + (kw + c + 4) * SA + nb];
            }
#pragma unroll
            for (int mt = 0; mt < 2; ++mt)
#pragma unroll
                for (int nt = 0; nt < 4; ++nt) {
                    mma_f16(acc_g[mt][nt], afg[mt], bf[nt]);
                    mma_f16(acc_b[mt][nt], afb[mt], bf[nt]);
                }
        }
        if (more) STS_TILE_F(cur ^ 1);
        __syncthreads();
    }
#undef LDG_TILE_F
#undef STS_TILE_F

#pragma unroll
    for (int mt = 0; mt < 2; ++mt) {
#pragma unroll
        for (int h = 0; h < 2; ++h) {
            const int row = m0 + wm * 32 + mt * 16 + r + h * 8;
            float bg = bfilm[row];
            float bb = bfilm[256 + row];
#pragma unroll
            for (int nt = 0; nt < 4; ++nt) {
                const int col = n0 + wn * 32 + nt * 8 + c * 2;
                float g0  = acc_g[mt][nt][h * 2 + 0] + bg;
                float g1  = acc_g[mt][nt][h * 2 + 1] + bg;
                float be0 = acc_b[mt][nt][h * 2 + 0] + bb;
                float be1 = acc_b[mt][nt][h * 2 + 1] + bb;
                float2 xv = *(const float2*)&x[((size_t)bz * CH + row) * TT + col];
                float xmm0 = xmask[(size_t)bz * TT + col];
                float xmm1 = xmask[(size_t)bz * TT + col + 1];
                float2 o;
                o.x = (xv.x * g0 + be0) * xmm0;
                o.y = (xv.y * g1 + be1) * xmm1;
                *(float2*)&out[((size_t)bz * CH + row) * TT + col] = o;
            }
        }
    }
}

// ---------------- launch ----------------
extern "C" void kernel_launch(void* const* d_in, const int* in_sizes, int n_in,
                              void* d_out, int out_size) {
    const float* x           = (const float*)d_in[0];
    const float* x_mask      = (const float*)d_in[1];
    const float* cond_latent = (const float*)d_in[2];
    const float* cond_mask   = (const float*)d_in[3];
    const float* w_cond      = (const float*)d_in[4];
    const float* b_cond      = (const float*)d_in[5];
    const float* wq          = (const float*)d_in[6];
    const float* bq          = (const float*)d_in[7];
    const float* wk          = (const float*)d_in[8];
    const float* bk          = (const float*)d_in[9];
    const float* wv          = (const float*)d_in[10];
    const float* bv          = (const float*)d_in[11];
    const float* wo          = (const float*)d_in[12];
    const float* bo          = (const float*)d_in[13];
    const float* w_film      = (const float*)d_in[14];
    const float* b_film      = (const float*)d_in[15];
    float* out = (float*)d_out;

    float *p_q, *p_k, *p_v, *p_att, *p_wkc, *p_wvc, *p_wfo, *p_bkc, *p_bvc, *p_bfo, *p_zero;
    cudaGetSymbolAddress((void**)&p_q,    g_q);
    cudaGetSymbolAddress((void**)&p_k,    g_k);
    cudaGetSymbolAddress((void**)&p_v,    g_v);
    cudaGetSymbolAddress((void**)&p_att,  g_att);
    cudaGetSymbolAddress((void**)&p_wkc,  g_wkc);
    cudaGetSymbolAddress((void**)&p_wvc,  g_wvc);
    cudaGetSymbolAddress((void**)&p_wfo,  g_wfo);
    cudaGetSymbolAddress((void**)&p_bkc,  g_bkc);
    cudaGetSymbolAddress((void**)&p_bvc,  g_bvc);
    cudaGetSymbolAddress((void**)&p_bfo,  g_bfo);
    cudaGetSymbolAddress((void**)&p_zero, g_zero);

    cudaFuncSetAttribute(mma_gemm64<2>, cudaFuncAttributeMaxDynamicSharedMemorySize, GEMM_SMEM);
    cudaFuncSetAttribute(mma_gemm64<3>, cudaFuncAttributeMaxDynamicSharedMemorySize, GEMM_SMEM);
    cudaFuncSetAttribute(flash_attn,    cudaFuncAttributeMaxDynamicSharedMemorySize, FLASH_SMEM);
    cudaFuncSetAttribute(film_gemm,     cudaFuncAttributeMaxDynamicSharedMemorySize, FILM_SMEM);

    // prologue
    rope_table_kernel<<<(32 * TT + 255) / 256, 256>>>();
    bias_combine2_kernel<<<4, 256>>>(wk, bk, wv, bv, b_cond, w_film, b_film, bo);

    // merged weight combines: z0 wkc=wk@w_cond, z1 wvc=wv@w_cond, z2 wfo=w_film@wo
    mma_gemm64<2><<<dim3(4, 4, 3), 256, GEMM_SMEM>>>(
        wk, wv, w_film, w_cond, wo,
        p_zero, p_zero, p_zero,
        p_wkc, p_wvc, p_wfo, nullptr);

    // merged q + kv:
    //   z<16: q = rope(wq @ x + bq)
    //   z>=16: k = rope+mask(wkc @ cl + bkc); v = wvc @ cl + bvc
    mma_gemm64<3><<<dim3(TT / 128, CH / 128, 48), 256, GEMM_SMEM>>>(
        wq, p_wkc, p_wvc, x, cond_latent,
        bq, p_bkc, p_bvc,
        p_q, p_k, p_v, cond_mask);

    // fused attention (fixed-shift exp2 softmax, pre-roped Q/K)
    flash_attn<<<dim3(1, TT / 128, BQ * NH), 256, FLASH_SMEM>>>(
        p_q, p_k, p_v, cond_mask, p_att);

    // fused FiLM: gamma/beta = wfo @ att + bfo
    film_gemm<<<dim3(TT / 128, CH / 128, BQ), 512, FILM_SMEM>>>(
        p_wfo, p_att, p_bfo, x, x_mask, out);
}

// round 14
// speedup vs baseline: 1.4727x; 1.0016x over previous
#include <cuda_runtime.h>
#include <math.h>
#include <stdint.h>

// ---------------- problem constants (fixed shapes) ----------------
#define BQ   16
#define CH   256
#define CONDC 512
#define TT   2048
#define TSL  512
#define NH   4
#define KC   64

#define SA 136       // padded smem stride (words): mod 32 = 8, *4 % 16 == 0

// ---------------- scratch (device globals; no allocation) ----------------
__device__ float g_q  [BQ * CH * TT];         // q roped fp32 (gemm epilogue)
__device__ float g_k  [BQ * CH * TSL];        // k roped+masked fp32 (gemm epilogue)
__device__ float g_v  [BQ * CH * TSL];        // v fp32
__device__ float g_att[BQ * CH * TT];         // attn out fp32
__device__ float g_wkc[CH * CONDC];           // wk @ w_cond
__device__ float g_wvc[CH * CONDC];           // wv @ w_cond
__device__ float g_wfo[2 * CH * CH];          // w_film @ wo
__device__ float g_bkc[CH];
__device__ float g_bvc[CH];
__device__ float g_bfo[2 * CH];
__device__ float g_zero[512];
__device__ float g_cos[32 * TT];              // [d][t]
__device__ float g_sin[32 * TT];

// ---------------- fp16 helpers ----------------
__device__ __forceinline__ uint32_t h2pk(float lo, float hi) {
    uint32_t u;
    asm("cvt.rn.f16x2.f32 %0, %1, %2;" : "=r"(u) : "f"(hi), "f"(lo));
    return u;
}

__device__ __forceinline__ void mma_f16(float* c, const uint32_t* a, const uint32_t* b) {
    asm volatile(
        "mma.sync.aligned.m16n8k16.row.col.f32.f16.f16.f32 "
        "{%0,%1,%2,%3}, {%4,%5,%6,%7}, {%8,%9}, {%0,%1,%2,%3};\n"
        : "+f"(c[0]), "+f"(c[1]), "+f"(c[2]), "+f"(c[3])
        : "r"(a[0]), "r"(a[1]), "r"(a[2]), "r"(a[3]), "r"(b[0]), "r"(b[1]));
}

// ---------------- RoPE tables, layout [d][t] ----------------
__global__ void rope_table_kernel() {
    int idx = blockIdx.x * blockDim.x + threadIdx.x;
    if (idx >= 32 * TT) return;
    int d = idx / TT;
    int t = idx % TT;
    float invf = (float)pow(10000.0, -(double)d / 32.0);
    float ang  = (float)t * invf;            // same fp32 rounding as reference
    g_cos[idx] = (float)cos((double)ang);
    g_sin[idx] = (float)sin((double)ang);
}

// ---------------- combined biases (full fp32) ----------------
__global__ void bias_combine2_kernel(const float* __restrict__ wk, const float* __restrict__ bk,
                                     const float* __restrict__ wv, const float* __restrict__ bv,
                                     const float* __restrict__ b_cond,
                                     const float* __restrict__ wf, const float* __restrict__ bf,
                                     const float* __restrict__ bo) {
    int tid = blockIdx.x * 256 + threadIdx.x;   // 0..1023
    if (tid < 256) {
        float s = 0.f;
        for (int k = 0; k < CH; ++k) s += wk[tid * CH + k] * b_cond[k];
        g_bkc[tid] = s + bk[tid];
    } else if (tid < 512) {
        int m = tid - 256;
        float s = 0.f;
        for (int k = 0; k < CH; ++k) s += wv[m * CH + k] * b_cond[k];
        g_bvc[m] = s + bv[m];
    } else {
        int m = tid - 512;
        float s = 0.f;
        for (int k = 0; k < CH; ++k) s += wf[m * CH + k] * bo[k];
        g_bfo[m] = s + bf[m];
    }
}

// ============================================================================
// fp16 MMA GEMM, 128x128 CTA tile, 256 threads (8 warps, 2x4), warp tile 64x32,
// BK=32 floats, double-buffered dynamic smem.
// GSEL 0: q  (z = batch; B=x, K=256, N=2048; epilogue rope, no mask)
// GSEL 1: kv (z&15 = batch, z>>4 sel; B=cl, K=512, N=512;
//             sel 0 -> k: rope+mask epilogue, sel 1 -> v: plain)
// GSEL 2: merged weight combines (z: 0 wkc, 1 wvc, 2 wfo; zero bias)
// ============================================================================
#define GEMM_SMEM (4 * 16 * SA * 4)

template<int GSEL>
__global__ __launch_bounds__(256, 2)
void mma_gemm64(const float* __restrict__ A0, const float* __restrict__ A1,
                const float* __restrict__ A2,
                const float* __restrict__ B0, const float* __restrict__ B1,
                const float* __restrict__ bias0, const float* __restrict__ bias1,
                float* __restrict__ Y0, float* __restrict__ Y1, float* __restrict__ Y2,
                const float* __restrict__ cmask)
{
    extern __shared__ uint32_t smg[];
    uint32_t* Asm = smg;                 // [2][16*SA]
    uint32_t* Bsm = smg + 2 * 16 * SA;   // [2][16*SA]

    const int tid = threadIdx.x;
    int bz = 0, emode = 0, Ndim, Kdim;
    size_t strideB = 0, strideY = 0;
    const float* A;
    const float* bias;
    const float* Bsrc;
    float*       Y;

    if (GSEL == 0) {
        bz = blockIdx.z;
        A = A0; bias = bias0; Y = Y0; Bsrc = B0;
        emode = 2; Ndim = TT; Kdim = CH;
        strideB = (size_t)CH * TT; strideY = (size_t)CH * TT;
    } else if (GSEL == 1) {
        bz = blockIdx.z & 15;
        const int sel = blockIdx.z >> 4;
        A    = sel ? A1 : A0;
        bias = sel ? bias1 : bias0;
        Y    = sel ? Y1 : Y0;
        Bsrc = B0;
        emode = sel ? 0 : 1;
        Ndim = TSL; Kdim = CONDC;
        strideB = (size_t)CONDC * TSL; strideY = (size_t)CH * TSL;
    } else { // GSEL == 2
        const int sel = blockIdx.z;
        A    = (sel == 0) ? A0 : (sel == 1) ? A1 : A2;
        Y    = (sel == 0) ? Y0 : (sel == 1) ? Y1 : Y2;
        bias = bias0;                     // zero
        Bsrc = (sel == 2) ? B1 : B0;
        int Md = (sel < 2) ? 256 : 512;
        Ndim   = (sel < 2) ? 512 : 256;
        Kdim   = CH;
        if ((int)blockIdx.y * 128 >= Md || (int)blockIdx.x * 128 >= Ndim) return;
    }
    const float* Bb = Bsrc + (size_t)bz * strideB;
    float*       Yb = Y    + (size_t)bz * strideY;
    const int m0 = blockIdx.y * 128, n0 = blockIdx.x * 128;

    const int wid = tid >> 5, lane = tid & 31;
    const int wm = wid >> 2, wn = wid & 3;
    const int r = lane >> 2, c = lane & 3;

    const int a_m  = ((tid >> 1) + ((tid & 1) << 4)) & 127;
    const int a_kw = (tid & 1) * 8;
    const int b_kp = tid >> 4;
    const int b_n4 = (tid & 15) * 4;

    float acc[4][4][4] = {};
    const int nk = Kdim / 32;

    float4 avr[4], blo[2], bhi[2];
#define LDG_T(k0)                                                                        \
    {                                                                                    \
        _Pragma("unroll")                                                                \
        for (int j = 0; j < 4; ++j)                                                      \
            avr[j] = *(const float4*)&A[(size_t)(m0 + a_m) * Kdim + (k0) + a_kw * 2 + 4 * j]; \
        _Pragma("unroll")                                                                \
        for (int j = 0; j < 2; ++j) {                                                    \
            blo[j] = *(const float4*)&Bb[(size_t)((k0) + 2 * b_kp)     * Ndim + n0 + b_n4 + 64 * j]; \
            bhi[j] = *(const float4*)&Bb[(size_t)((k0) + 2 * b_kp + 1) * Ndim + n0 + b_n4 + 64 * j]; \
        }                                                                                \
    }
#define STS_T(buf)                                                                       \
    {                                                                                    \
        uint32_t* Ab = Asm + (buf) * 16 * SA;                                            \
        uint32_t* Bd = Bsm + (buf) * 16 * SA;                                            \
        _Pragma("unroll")                                                                \
        for (int j = 0; j < 4; ++j) {                                                    \
            Ab[(a_kw + 2 * j + 0) * SA + a_m] = h2pk(avr[j].x, avr[j].y);                \
            Ab[(a_kw + 2 * j + 1) * SA + a_m] = h2pk(avr[j].z, avr[j].w);                \
        }                                                                                \
        _Pragma("unroll")                                                                \
        for (int j = 0; j < 2; ++j) {                                                    \
            uint4 w;                                                                    \
            w.x = h2pk(blo[j].x, bhi[j].x);                                              \
            w.y = h2pk(blo[j].y, bhi[j].y);                                              \
            w.z = h2pk(blo[j].z, bhi[j].z);                                              \
            w.w = h2pk(blo[j].w, bhi[j].w);                                              \
            *(uint4*)&Bd[b_kp * SA + b_n4 + 64 * j] = w;                                 \
        }                                                                                \
    }

    LDG_T(0);
    STS_T(0);
    __syncthreads();

    for (int kb = 0; kb < nk; ++kb) {
        const int cur = kb & 1;
        const bool more = (kb + 1 < nk);
        if (more) LDG_T((kb + 1) * 32);

        const uint32_t* Ac = Asm + cur * 16 * SA;
        const uint32_t* Bc = Bsm + cur * 16 * SA;
#pragma unroll
        for (int kw = 0; kw < 16; kw += 8) {
            uint32_t af[4][4], bf[4][2];
#pragma unroll
            for (int mt = 0; mt < 4; ++mt) {
                int mb = wm * 64 + mt * 16 + r;
                af[mt][0] = Ac[(kw + c) * SA + mb];
                af[mt][1] = Ac[(kw + c) * SA + mb + 8];
                af[mt][2] = Ac[(kw + c + 4) * SA + mb];
                af[mt][3] = Ac[(kw + c + 4) * SA + mb + 8];
            }
#pragma unroll
            for (int nt = 0; nt < 4; ++nt) {
                int nb = wn * 32 + nt * 8 + r;
                bf[nt][0] = Bc[(kw + c) * SA + nb];
                bf[nt][1] = Bc[(kw + c + 4) * SA + nb];
            }
#pragma unroll
            for (int mt = 0; mt < 4; ++mt)
#pragma unroll
                for (int nt = 0; nt < 4; ++nt)
                    mma_f16(acc[mt][nt], af[mt], bf[nt]);
        }
        if (more) STS_T(cur ^ 1);
        __syncthreads();
    }
#undef LDG_T
#undef STS_T

    if (GSEL != 2 && emode != 0) {
        // ---- rope epilogue (+cond-mask when emode==1), paired rows (d, d+32) ----
#pragma unroll
        for (int mtl = 0; mtl < 2; ++mtl) {
#pragma unroll
            for (int h = 0; h < 2; ++h) {
                const int row_lo = m0 + wm * 64 + mtl * 16 + h * 8 + r;  // d in [0,32)
                const int row_hi = row_lo + 32;
                const int d = row_lo & 63;
                float b_lo = bias[row_lo], b_hi = bias[row_hi];
#pragma unroll
                for (int nt = 0; nt < 4; ++nt) {
                    const int col = n0 + wn * 32 + nt * 8 + c * 2;
                    float2 cs = *(const float2*)&g_cos[(size_t)d * TT + col];
                    float2 sn = *(const float2*)&g_sin[(size_t)d * TT + col];
                    float2 cm;
                    if (emode == 1) cm = *(const float2*)&cmask[(size_t)bz * TSL + col];
                    else            { cm.x = 1.f; cm.y = 1.f; }
                    float k1x = acc[mtl][nt][h * 2 + 0] + b_lo;
                    float k1y = acc[mtl][nt][h * 2 + 1] + b_lo;
                    float k2x = acc[mtl + 2][nt][h * 2 + 0] + b_hi;
                    float k2y = acc[mtl + 2][nt][h * 2 + 1] + b_hi;
                    float2 olo, ohi;
                    olo.x = (k1x * cs.x - k2x * sn.x) * cm.x;
                    olo.y = (k1y * cs.y - k2y * sn.y) * cm.y;
                    ohi.x = (k2x * cs.x + k1x * sn.x) * cm.x;
                    ohi.y = (k2y * cs.y + k1y * sn.y) * cm.y;
                    *(float2*)&Yb[(size_t)row_lo * Ndim + col] = olo;
                    *(float2*)&Yb[(size_t)row_hi * Ndim + col] = ohi;
                }
            }
        }
    } else {
#pragma unroll
        for (int mt = 0; mt < 4; ++mt) {
#pragma unroll
            for (int h = 0; h < 2; ++h) {
                const int row = m0 + wm * 64 + mt * 16 + h * 8 + r;
                float bval = bias[row];
#pragma unroll
                for (int nt = 0; nt < 4; ++nt) {
                    const int col = n0 + wn * 32 + nt * 8 + c * 2;
                    float2 o;
                    o.x = acc[mt][nt][h * 2 + 0] + bval;
                    o.y = acc[mt][nt][h * 2 + 1] + bval;
                    *(float2*)&Yb[(size_t)row * Ndim + col] = o;
                }
            }
        }
    }
}

// ============================================================================
// Fused flash attention, fp16 MMA, fixed-shift softmax in exp2 domain
// (unchanged from R13 — pre-roped Q/K, pure pack loads).
// ============================================================================
#define FSA 136
#define FSK 72
#define FSV2 36
#define FSP 136
#define OFF_KS 4352
#define OFF_VS 6656
#define OFF_PS 8960
#define OFF_CMB 13312
#define FLASH_SMEM (13824 * 4)
#define SCALE_LOG2E 0.18033688f   // 0.125 * log2(e)

__global__ __launch_bounds__(256, 2)
void flash_attn(const float* __restrict__ Qg, const float* __restrict__ Kg,
                const float* __restrict__ Vg, const float* __restrict__ cmask,
                float* __restrict__ O)
{
    extern __shared__ uint32_t sm[];
    uint32_t* Qs  = sm;
    uint32_t* Ks  = sm + OFF_KS;
    uint32_t* Vs  = sm + OFF_VS;
    uint32_t* Ps  = sm + OFF_PS;
    float*    cmb = (float*)(sm + OFF_CMB);

    const int bh = blockIdx.z;
    const int b  = bh >> 2;
    const int m0 = blockIdx.y * 128;
    const int tid = threadIdx.x, wid = tid >> 5, lane = tid & 31;
    const int r = lane >> 2, c = lane & 3;
    const int mb = wid * 16 + r;

    const float* Qb = Qg + (size_t)bh * KC * TT;
    const float* Kb = Kg + (size_t)bh * KC * TSL;
    const float* Vb = Vg + (size_t)bh * KC * TSL;

    // ---- load Q tile: pure pack of adjacent pre-roped channel pairs ----
    {
        const int e  = tid >> 4;            // d-pair 0..15
        const int mg = (tid & 15) * 8;
#pragma unroll
        for (int hh = 0; hh < 2; ++hh) {
            const int ra = 2 * e + hh * 32;
#pragma unroll
            for (int j = 0; j < 8; j += 4) {
                float4 qa = *(const float4*)&Qb[(size_t)ra * TT + m0 + mg + j];
                float4 qb = *(const float4*)&Qb[(size_t)(ra + 1) * TT + m0 + mg + j];
                Qs[(e + hh * 16) * FSA + mg + j + 0] = h2pk(qa.x, qb.x);
                Qs[(e + hh * 16) * FSA + mg + j + 1] = h2pk(qa.y, qb.y);
                Qs[(e + hh * 16) * FSA + mg + j + 2] = h2pk(qa.z, qb.z);
                Qs[(e + hh * 16) * FSA + mg + j + 3] = h2pk(qa.w, qb.w);
            }
        }
    }
    for (int i = tid; i < TSL; i += 256)
        cmb[i] = (cmask[(size_t)b * TSL + i] == 0.f) ? -14427.0f : 0.f;

    // ---- prefetch chunk 0 ----
    const int e2 = tid >> 3;            // K d-pair 0..31
    const int n8 = (tid & 7) * 8;
    const int ch = tid >> 2;            // V channel 0..63
    const int kc = (tid & 3) * 16;
    float4 kr[4], vr[4];
#pragma unroll
    for (int j = 0; j < 2; ++j) {
        kr[j]     = *(const float4*)&Kb[(size_t)(2 * e2)     * TSL + n8 + 4 * j];
        kr[j + 2] = *(const float4*)&Kb[(size_t)(2 * e2 + 1) * TSL + n8 + 4 * j];
    }
#pragma unroll
    for (int j = 0; j < 4; ++j)
        vr[j] = *(const float4*)&Vb[(size_t)ch * TSL + kc + 4 * j];

    float l_run[2] = {0.f, 0.f};
    float acc_o[8][4] = {};

    __syncthreads();

    for (int ci = 0; ci < 8; ++ci) {
        const int s0 = ci * 64;
        // ---- store prefetched K/V (pack half2) ----
        {
            uint4 w0, w1;
            w0.x = h2pk(kr[0].x, kr[2].x); w0.y = h2pk(kr[0].y, kr[2].y);
            w0.z = h2pk(kr[0].z, kr[2].z); w0.w = h2pk(kr[0].w, kr[2].w);
            w1.x = h2pk(kr[1].x, kr[3].x); w1.y = h2pk(kr[1].y, kr[3].y);
            w1.z = h2pk(kr[1].z, kr[3].z); w1.w = h2pk(kr[1].w, kr[3].w);
            *(uint4*)&Ks[e2 * FSK + n8]     = w0;
            *(uint4*)&Ks[e2 * FSK + n8 + 4] = w1;
            uint4 v0, v1;
            v0.x = h2pk(vr[0].x, vr[0].y); v0.y = h2pk(vr[0].z, vr[0].w);
            v0.z = h2pk(vr[1].x, vr[1].y); v0.w = h2pk(vr[1].z, vr[1].w);
            v1.x = h2pk(vr[2].x, vr[2].y); v1.y = h2pk(vr[2].z, vr[2].w);
            v1.z = h2pk(vr[3].x, vr[3].y); v1.w = h2pk(vr[3].z, vr[3].w);
            *(uint4*)&Vs[ch * FSV2 + (kc >> 1)]     = v0;
            *(uint4*)&Vs[ch * FSV2 + (kc >> 1) + 4] = v1;
        }
        __syncthreads();
        if (ci < 7) {
#pragma unroll
            for (int j = 0; j < 2; ++j) {
                kr[j]     = *(const float4*)&Kb[(size_t)(2 * e2)     * TSL + s0 + 64 + n8 + 4 * j];
                kr[j + 2] = *(const float4*)&Kb[(size_t)(2 * e2 + 1) * TSL + s0 + 64 + n8 + 4 * j];
            }
#pragma unroll
            for (int j = 0; j < 4; ++j)
                vr[j] = *(const float4*)&Vb[(size_t)ch * TSL + s0 + 64 + kc + 4 * j];
        }

        // ---- S = Q^T K : warp tile 16 x 64, K=64 (4 fp16 MMA steps) ----
        float acc_s[8][4] = {};
#pragma unroll
        for (int kw = 0; kw < 32; kw += 8) {
            uint32_t af[4];
            af[0] = Qs[(kw + c) * FSA + mb];
            af[1] = Qs[(kw + c) * FSA + mb + 8];
            af[2] = Qs[(kw + c + 4) * FSA + mb];
            af[3] = Qs[(kw + c + 4) * FSA + mb + 8];
#pragma unroll
            for (int nt = 0; nt < 8; ++nt) {
                uint32_t bf[2];
                bf[0] = Ks[(kw + c) * FSK + nt * 8 + r];
                bf[1] = Ks[(kw + c + 4) * FSK + nt * 8 + r];
                mma_f16(acc_s[nt], af, bf);
            }
        }

        // ---- exp2(scale*s + bias), accumulate row sums ----
        float lad[2] = {0.f, 0.f};
#pragma unroll
        for (int nt = 0; nt < 8; ++nt) {
            float2 bias = *(float2*)&cmb[s0 + nt * 8 + 2 * c];
#pragma unroll
            for (int jj = 0; jj < 4; ++jj) {
                float e = exp2f(acc_s[nt][jj] * SCALE_LOG2E + ((jj & 1) ? bias.y : bias.x));
                acc_s[nt][jj] = e;
                lad[jj >> 1] += e;
            }
        }
#pragma unroll
        for (int h = 0; h < 2; ++h) {
            lad[h] += __shfl_xor_sync(0xffffffffu, lad[h], 1);
            lad[h] += __shfl_xor_sync(0xffffffffu, lad[h], 2);
            l_run[h] += lad[h];
        }
        // P -> smem: pack position-pairs (2c, 2c+1) into one word
#pragma unroll
        for (int nt = 0; nt < 8; ++nt) {
            int kwp = nt * 4 + c;
            Ps[kwp * FSP + wid * 16 + r]     = h2pk(acc_s[nt][0], acc_s[nt][1]);
            Ps[kwp * FSP + wid * 16 + r + 8] = h2pk(acc_s[nt][2], acc_s[nt][3]);
        }
        __syncwarp();

        // ---- O += P @ V^T : K=64 (4 fp16 MMA steps) ----
#pragma unroll
        for (int kw = 0; kw < 32; kw += 8) {
            uint32_t af[4];
            af[0] = Ps[(kw + c) * FSP + mb];
            af[1] = Ps[(kw + c) * FSP + mb + 8];
            af[2] = Ps[(kw + c + 4) * FSP + mb];
            af[3] = Ps[(kw + c + 4) * FSP + mb + 8];
#pragma unroll
            for (int nt = 0; nt < 8; ++nt) {
                uint32_t bf[2];
                bf[0] = Vs[(nt * 8 + r) * FSV2 + kw + c];
                bf[1] = Vs[(nt * 8 + r) * FSV2 + kw + c + 4];
                mma_f16(acc_o[nt], af, bf);
            }
        }
        __syncthreads();
    }

    // ---- epilogue: /l, transpose via smem, coalesced store ----
    float inv[2] = {1.f / l_run[0], 1.f / l_run[1]};
    float* Pf = (float*)sm;    // [64][136] floats
#pragma unroll
    for (int nt = 0; nt < 8; ++nt) {
#pragma unroll
        for (int jj = 0; jj < 4; ++jj) {
            int n = nt * 8 + 2 * c + (jj & 1);
            int m = wid * 16 + r + (jj >> 1) * 8;
            Pf[n * FSA + m] = acc_o[nt][jj] * inv[jj >> 1];
        }
    }
    __syncthreads();
    {
        int row = tid >> 2;
        int mq  = (tid & 3) * 4;
#pragma unroll
        for (int j = 0; j < 8; ++j) {
            int m = mq + 16 * j;
            *(float4*)&O[((size_t)bh * KC + row) * TT + m0 + m] =
                *(float4*)&Pf[row * FSA + m];
        }
    }
}

// ============================================================================
// Fused FiLM GEMM, fp16 MMA, dual accumulator (unchanged from R13)
// ============================================================================
#define FILM_SMEM (6 * 16 * SA * 4)

__global__ __launch_bounds__(512)
void film_gemm(const float* __restrict__ Wf, const float* __restrict__ Yin,
               const float* __restrict__ bfilm, const float* __restrict__ x,
               const float* __restrict__ xmask, float* __restrict__ out)
{
    extern __shared__ uint32_t smf[];
    uint32_t* AsG = smf;
    uint32_t* AsB = smf + 2 * 16 * SA;
    uint32_t* Bs  = smf + 4 * 16 * SA;

    const int tid = threadIdx.x;
    const int bz  = blockIdx.z;
    const float* Bb = Yin + (size_t)bz * CH * TT;
    const int m0 = blockIdx.y * 128, n0 = blockIdx.x * 128;

    const int wid = tid >> 5, lane = tid & 31;
    const int wm = wid >> 2, wn = wid & 3;
    const int r = lane >> 2, c = lane & 3;

    const int a_kw = (tid & 3) * 4;
    const int a_m  = ((tid >> 2) + (tid & 3) * 8) & 127;
    const int b_kp = tid >> 5;
    const int b_n4 = (tid & 31) * 4;

    float acc_g[2][4][4] = {};
    float acc_b[2][4][4] = {};

    float4 ag0, ag1, ab0, ab1, blo, bhi;
#define LDG_TILE_F(k0)                                                                   \
    {                                                                                    \
        ag0 = *(const float4*)&Wf[(size_t)(m0 + a_m) * CH + (k0) + a_kw * 2];            \
        ag1 = *(const float4*)&Wf[(size_t)(m0 + a_m) * CH + (k0) + a_kw * 2 + 4];        \
        ab0 = *(const float4*)&Wf[(size_t)(256 + m0 + a_m) * CH + (k0) + a_kw * 2];      \
        ab1 = *(const float4*)&Wf[(size_t)(256 + m0 + a_m) * CH + (k0) + a_kw * 2 + 4];  \
        blo = *(const float4*)&Bb[(size_t)((k0) + 2 * b_kp)     * TT + n0 + b_n4];       \
        bhi = *(const float4*)&Bb[(size_t)((k0) + 2 * b_kp + 1) * TT + n0 + b_n4];       \
    }
#define STS_TILE_F(buf)                                                                  \
    {                                                                                    \
        uint32_t* G = AsG + (buf) * 16 * SA;                                             \
        uint32_t* Bq = AsB + (buf) * 16 * SA;                                            \
        G[(a_kw + 0) * SA + a_m] = h2pk(ag0.x, ag0.y);                                   \
        G[(a_kw + 1) * SA + a_m] = h2pk(ag0.z, ag0.w);                                   \
        G[(a_kw + 2) * SA + a_m] = h2pk(ag1.x, ag1.y);                                   \
        G[(a_kw + 3) * SA + a_m] = h2pk(ag1.z, ag1.w);                                   \
        Bq[(a_kw + 0) * SA + a_m] = h2pk(ab0.x, ab0.y);                                  \
        Bq[(a_kw + 1) * SA + a_m] = h2pk(ab0.z, ab0.w);                                  \
        Bq[(a_kw + 2) * SA + a_m] = h2pk(ab1.x, ab1.y);                                  \
        Bq[(a_kw + 3) * SA + a_m] = h2pk(ab1.z, ab1.w);                                  \
        uint4 w;                                                                         \
        w.x = h2pk(blo.x, bhi.x); w.y = h2pk(blo.y, bhi.y);                              \
        w.z = h2pk(blo.z, bhi.z); w.w = h2pk(blo.w, bhi.w);                              \
        *(uint4*)&Bs[(buf) * 16 * SA + b_kp * SA + b_n4] = w;                            \
    }

    LDG_TILE_F(0);
    STS_TILE_F(0);
    __syncthreads();

    const int nk = CH / 32;
    for (int kb = 0; kb < nk; ++kb) {
        const int cur = kb & 1;
        const bool more = (kb + 1 < nk);
        if (more) LDG_TILE_F((kb + 1) * 32);

#pragma unroll
        for (int kw = 0; kw < 16; kw += 8) {
            uint32_t afg[2][4], afb[2][4], bf[4][2];
#pragma unroll
            for (int mt = 0; mt < 2; ++mt) {
                int mbx = wm * 32 + mt * 16 + r;
                afg[mt][0] = AsG[cur * 16 * SA + (kw + c) * SA + mbx];
                afg[mt][1] = AsG[cur * 16 * SA + (kw + c) * SA + mbx + 8];
                afg[mt][2] = AsG[cur * 16 * SA + (kw + c + 4) * SA + mbx];
                afg[mt][3] = AsG[cur * 16 * SA + (kw + c + 4) * SA + mbx + 8];
                afb[mt][0] = AsB[cur * 16 * SA + (kw + c) * SA + mbx];
                afb[mt][1] = AsB[cur * 16 * SA + (kw + c) * SA + mbx + 8];
                afb[mt][2] = AsB[cur * 16 * SA + (kw + c + 4) * SA + mbx];
                afb[mt][3] = AsB[cur * 16 * SA + (kw + c + 4) * SA + mbx + 8];
            }
#pragma unroll
            for (int nt = 0; nt < 4; ++nt) {
                int nb = wn * 32 + nt * 8 + r;
                bf[nt][0] = Bs[cur * 16 * SA + (kw + c) * SA + nb];
                bf[nt][1] = Bs[cur * 16 * SA + (kw + c + 4) * SA + nb];
            }
#pragma unroll
            for (int mt = 0; mt < 2; ++mt)
#pragma unroll
                for (int nt = 0; nt < 4; ++nt) {
                    mma_f16(acc_g[mt][nt], afg[mt], bf[nt]);
                    mma_f16(acc_b[mt][nt], afb[mt], bf[nt]);
                }
        }
        if (more) STS_TILE_F(cur ^ 1);
        __syncthreads();
    }
#undef LDG_TILE_F
#undef STS_TILE_F

#pragma unroll
    for (int mt = 0; mt < 2; ++mt) {
#pragma unroll
        for (int h = 0; h < 2; ++h) {
            const int row = m0 + wm * 32 + mt * 16 + r + h * 8;
            float bg = bfilm[row];
            float bb = bfilm[256 + row];
#pragma unroll
            for (int nt = 0; nt < 4; ++nt) {
                const int col = n0 + wn * 32 + nt * 8 + c * 2;
                float g0  = acc_g[mt][nt][h * 2 + 0] + bg;
                float g1  = acc_g[mt][nt][h * 2 + 1] + bg;
                float be0 = acc_b[mt][nt][h * 2 + 0] + bb;
                float be1 = acc_b[mt][nt][h * 2 + 1] + bb;
                float2 xv = *(const float2*)&x[((size_t)bz * CH + row) * TT + col];
                float xmm0 = xmask[(size_t)bz * TT + col];
                float xmm1 = xmask[(size_t)bz * TT + col + 1];
                float2 o;
                o.x = (xv.x * g0 + be0) * xmm0;
                o.y = (xv.y * g1 + be1) * xmm1;
                *(float2*)&out[((size_t)bz * CH + row) * TT + col] = o;
            }
        }
    }
}

// ---------------- launch ----------------
extern "C" void kernel_launch(void* const* d_in, const int* in_sizes, int n_in,
                              void* d_out, int out_size) {
    const float* x           = (const float*)d_in[0];
    const float* x_mask      = (const float*)d_in[1];
    const float* cond_latent = (const float*)d_in[2];
    const float* cond_mask   = (const float*)d_in[3];
    const float* w_cond      = (const float*)d_in[4];
    const float* b_cond      = (const float*)d_in[5];
    const float* wq          = (const float*)d_in[6];
    const float* bq          = (const float*)d_in[7];
    const float* wk          = (const float*)d_in[8];
    const float* bk          = (const float*)d_in[9];
    const float* wv          = (const float*)d_in[10];
    const float* bv          = (const float*)d_in[11];
    const float* wo          = (const float*)d_in[12];
    const float* bo          = (const float*)d_in[13];
    const float* w_film      = (const float*)d_in[14];
    const float* b_film      = (const float*)d_in[15];
    float* out = (float*)d_out;

    float *p_q, *p_k, *p_v, *p_att, *p_wkc, *p_wvc, *p_wfo, *p_bkc, *p_bvc, *p_bfo, *p_zero;
    cudaGetSymbolAddress((void**)&p_q,    g_q);
    cudaGetSymbolAddress((void**)&p_k,    g_k);
    cudaGetSymbolAddress((void**)&p_v,    g_v);
    cudaGetSymbolAddress((void**)&p_att,  g_att);
    cudaGetSymbolAddress((void**)&p_wkc,  g_wkc);
    cudaGetSymbolAddress((void**)&p_wvc,  g_wvc);
    cudaGetSymbolAddress((void**)&p_wfo,  g_wfo);
    cudaGetSymbolAddress((void**)&p_bkc,  g_bkc);
    cudaGetSymbolAddress((void**)&p_bvc,  g_bvc);
    cudaGetSymbolAddress((void**)&p_bfo,  g_bfo);
    cudaGetSymbolAddress((void**)&p_zero, g_zero);

    cudaFuncSetAttribute(mma_gemm64<0>, cudaFuncAttributeMaxDynamicSharedMemorySize, GEMM_SMEM);
    cudaFuncSetAttribute(mma_gemm64<1>, cudaFuncAttributeMaxDynamicSharedMemorySize, GEMM_SMEM);
    cudaFuncSetAttribute(mma_gemm64<2>, cudaFuncAttributeMaxDynamicSharedMemorySize, GEMM_SMEM);
    cudaFuncSetAttribute(flash_attn,    cudaFuncAttributeMaxDynamicSharedMemorySize, FLASH_SMEM);
    cudaFuncSetAttribute(film_gemm,     cudaFuncAttributeMaxDynamicSharedMemorySize, FILM_SMEM);

    // prologue
    rope_table_kernel<<<(32 * TT + 255) / 256, 256>>>();
    bias_combine2_kernel<<<4, 256>>>(wk, bk, wv, bv, b_cond, w_film, b_film, bo);

    // merged weight combines: z0 wkc=wk@w_cond, z1 wvc=wv@w_cond, z2 wfo=w_film@wo
    mma_gemm64<2><<<dim3(4, 4, 3), 256, GEMM_SMEM>>>(
        wk, wv, w_film, w_cond, wo,
        p_zero, nullptr,
        p_wkc, p_wvc, p_wfo, nullptr);

    // q = rope(wq @ x + bq)                  [b][256][2048]
    mma_gemm64<0><<<dim3(TT / 128, CH / 128, BQ), 256, GEMM_SMEM>>>(
        wq, nullptr, nullptr, x, nullptr,
        bq, nullptr,
        p_q, nullptr, nullptr, nullptr);

    // k = rope+mask(wkc @ cl + bkc); v = wvc @ cl + bvc   (K = 512)
    mma_gemm64<1><<<dim3(TSL / 128, CH / 128, 2 * BQ), 256, GEMM_SMEM>>>(
        p_wkc, p_wvc, nullptr, cond_latent, nullptr,
        p_bkc, p_bvc,
        p_k, p_v, nullptr, cond_mask);

    // fused attention (fixed-shift exp2 softmax, pre-roped Q/K)
    flash_attn<<<dim3(1, TT / 128, BQ * NH), 256, FLASH_SMEM>>>(
        p_q, p_k, p_v, cond_mask, p_att);

    // fused FiLM: gamma/beta = wfo @ att + bfo
    film_gemm<<<dim3(TT / 128, CH / 128, BQ), 512, FILM_SMEM>>>(
        p_wfo, p_att, p_bfo, x, x_mask, out);
}

// round 15
// speedup vs baseline: 1.6720x; 1.1353x over previous
#include <cuda_runtime.h>
#include <math.h>
#include <stdint.h>

// ---------------- problem constants (fixed shapes) ----------------
#define BQ   16
#define CH   256
#define CONDC 512
#define TT   2048
#define TSL  512
#define NH   4
#define KC   64

#define SA 136       // padded smem stride (words): mod 32 = 8, *4 % 16 == 0

// ---------------- scratch (device globals; no allocation) ----------------
// Packed half2 intermediates, laid out exactly as consumers' smem wants them.
__device__ uint32_t g_qh  [BQ * NH * 32 * TT];    // [bh][pair d,(d+32)][t]
__device__ uint32_t g_kh  [BQ * NH * 32 * TSL];   // [bh][pair d,(d+32)][t]  (roped+masked)
__device__ uint32_t g_vh  [BQ * NH * 64 * (TSL/2)]; // [bh][ch][pos-pair]
__device__ uint32_t g_atth[BQ * 128 * TT];        // [b][ch-pair][t]
__device__ uint32_t g_wkch[CH * (CONDC/2)];       // [m][k-pair]  wk@w_cond
__device__ uint32_t g_wvch[CH * (CONDC/2)];       // [m][k-pair]  wv@w_cond
__device__ uint32_t g_wfoh[2 * CH * (CH/2)];      // [m][k-pair]  w_film@wo
__device__ float g_bkc[CH];
__device__ float g_bvc[CH];
__device__ float g_bfo[2 * CH];
__device__ float g_zero[512];
__device__ float g_cos[32 * TT];                  // [d][t]
__device__ float g_sin[32 * TT];

// ---------------- fp16 helpers ----------------
__device__ __forceinline__ uint32_t h2pk(float lo, float hi) {
    uint32_t u;
    asm("cvt.rn.f16x2.f32 %0, %1, %2;" : "=r"(u) : "f"(hi), "f"(lo));
    return u;
}

__device__ __forceinline__ void mma_f16(float* c, const uint32_t* a, const uint32_t* b) {
    asm volatile(
        "mma.sync.aligned.m16n8k16.row.col.f32.f16.f16.f32 "
        "{%0,%1,%2,%3}, {%4,%5,%6,%7}, {%8,%9}, {%0,%1,%2,%3};\n"
        : "+f"(c[0]), "+f"(c[1]), "+f"(c[2]), "+f"(c[3])
        : "r"(a[0]), "r"(a[1]), "r"(a[2]), "r"(a[3]), "r"(b[0]), "r"(b[1]));
}

// ---------------- RoPE tables, layout [d][t] ----------------
__global__ void rope_table_kernel() {
    int idx = blockIdx.x * blockDim.x + threadIdx.x;
    if (idx >= 32 * TT) return;
    int d = idx / TT;
    int t = idx % TT;
    float invf = (float)pow(10000.0, -(double)d / 32.0);
    float ang  = (float)t * invf;            // same fp32 rounding as reference
    g_cos[idx] = (float)cos((double)ang);
    g_sin[idx] = (float)sin((double)ang);
}

// ---------------- combined biases (full fp32) ----------------
__global__ void bias_combine2_kernel(const float* __restrict__ wk, const float* __restrict__ bk,
                                     const float* __restrict__ wv, const float* __restrict__ bv,
                                     const float* __restrict__ b_cond,
                                     const float* __restrict__ wf, const float* __restrict__ bf,
                                     const float* __restrict__ bo) {
    int tid = blockIdx.x * 256 + threadIdx.x;   // 0..1023
    if (tid < 256) {
        float s = 0.f;
        for (int k = 0; k < CH; ++k) s += wk[tid * CH + k] * b_cond[k];
        g_bkc[tid] = s + bk[tid];
    } else if (tid < 512) {
        int m = tid - 256;
        float s = 0.f;
        for (int k = 0; k < CH; ++k) s += wv[m * CH + k] * b_cond[k];
        g_bvc[m] = s + bv[m];
    } else {
        int m = tid - 512;
        float s = 0.f;
        for (int k = 0; k < CH; ++k) s += wf[m * CH + k] * bo[k];
        g_bfo[m] = s + bf[m];
    }
}

// ============================================================================
// Shared fp16-MMA mainloop pieces (128x128 CTA tile, 256 thr, 8 warps 2x4,
// warp tile 64x32, BK=32 floats = 16 half2 word-rows, double-buffered smem).
// ============================================================================
#define GEMM_SMEM (4 * 16 * SA * 4)

#define GEMM_IDS                                                         \
    const int tid = threadIdx.x;                                         \
    const int wid = tid >> 5, lane = tid & 31;                           \
    const int wm = wid >> 2, wn = wid & 3;                               \
    const int r = lane >> 2, c = lane & 3;                               \
    const int a_m  = ((tid >> 1) + ((tid & 1) << 4)) & 127;              \
    const int a_kw = (tid & 1) * 8;                                      \
    const int b_kp = tid >> 4;                                           \
    const int b_n4 = (tid & 15) * 4;

#define GEMM_COMPUTE(Ac, Bc)                                             \
    _Pragma("unroll")                                                    \
    for (int kw = 0; kw < 16; kw += 8) {                                 \
        uint32_t af[4][4], bf[4][2];                                     \
        _Pragma("unroll")                                                \
        for (int mt = 0; mt < 4; ++mt) {                                 \
            int mb = wm * 64 + mt * 16 + r;                              \
            af[mt][0] = (Ac)[(kw + c) * SA + mb];                        \
            af[mt][1] = (Ac)[(kw + c) * SA + mb + 8];                    \
            af[mt][2] = (Ac)[(kw + c + 4) * SA + mb];                    \
            af[mt][3] = (Ac)[(kw + c + 4) * SA + mb + 8];                \
        }                                                                \
        _Pragma("unroll")                                                \
        for (int nt = 0; nt < 4; ++nt) {                                 \
            int nb = wn * 32 + nt * 8 + r;                               \
            bf[nt][0] = (Bc)[(kw + c) * SA + nb];                        \
            bf[nt][1] = (Bc)[(kw + c + 4) * SA + nb];                    \
        }                                                                \
        _Pragma("unroll")                                                \
        for (int mt = 0; mt < 4; ++mt)                                   \
            _Pragma("unroll")                                            \
            for (int nt = 0; nt < 4; ++nt)                               \
                mma_f16(acc[mt][nt], af[mt], bf[nt]);                    \
    }

// ============================================================================
// gemm_q: q = rope(wq @ x + bq) -> g_qh packed (d, d+32). A,B fp32.
// grid (16, 2, 16 batches)
// ============================================================================
__global__ __launch_bounds__(256, 2)
void gemm_q(const float* __restrict__ A, const float* __restrict__ B,
            const float* __restrict__ bias)
{
    extern __shared__ uint32_t smg[];
    uint32_t* Asm = smg;
    uint32_t* Bsm = smg + 2 * 16 * SA;
    GEMM_IDS
    const int bz = blockIdx.z;
    const float* Bb = B + (size_t)bz * CH * TT;
    const int m0 = blockIdx.y * 128, n0 = blockIdx.x * 128;
    float acc[4][4][4] = {};

    float4 avr[4], blo[2], bhi[2];
#define LDG_Q(k0)                                                                        \
    {                                                                                    \
        _Pragma("unroll")                                                                \
        for (int j = 0; j < 4; ++j)                                                      \
            avr[j] = *(const float4*)&A[(size_t)(m0 + a_m) * CH + (k0) + a_kw * 2 + 4 * j]; \
        _Pragma("unroll")                                                                \
        for (int j = 0; j < 2; ++j) {                                                    \
            blo[j] = *(const float4*)&Bb[(size_t)((k0) + 2 * b_kp)     * TT + n0 + b_n4 + 64 * j]; \
            bhi[j] = *(const float4*)&Bb[(size_t)((k0) + 2 * b_kp + 1) * TT + n0 + b_n4 + 64 * j]; \
        }                                                                                \
    }
#define STS_Q(buf)                                                                       \
    {                                                                                    \
        uint32_t* Ab = Asm + (buf) * 16 * SA;                                            \
        uint32_t* Bd = Bsm + (buf) * 16 * SA;                                            \
        _Pragma("unroll")                                                                \
        for (int j = 0; j < 4; ++j) {                                                    \
            Ab[(a_kw + 2 * j + 0) * SA + a_m] = h2pk(avr[j].x, avr[j].y);                \
            Ab[(a_kw + 2 * j + 1) * SA + a_m] = h2pk(avr[j].z, avr[j].w);                \
        }                                                                                \
        _Pragma("unroll")                                                                \
        for (int j = 0; j < 2; ++j) {                                                    \
            uint4 w;                                                                    \
            w.x = h2pk(blo[j].x, bhi[j].x); w.y = h2pk(blo[j].y, bhi[j].y);              \
            w.z = h2pk(blo[j].z, bhi[j].z); w.w = h2pk(blo[j].w, bhi[j].w);              \
            *(uint4*)&Bd[b_kp * SA + b_n4 + 64 * j] = w;                                 \
        }                                                                                \
    }
    LDG_Q(0); STS_Q(0); __syncthreads();
    for (int kb = 0; kb < 8; ++kb) {
        const int cur = kb & 1;
        const bool more = (kb < 7);
        if (more) LDG_Q((kb + 1) * 32);
        GEMM_COMPUTE(Asm + cur * 16 * SA, Bsm + cur * 16 * SA)
        if (more) STS_Q(cur ^ 1);
        __syncthreads();
    }
#undef LDG_Q
#undef STS_Q
    // rope epilogue -> packed (d, d+32) half2, uint2 stores
#pragma unroll
    for (int mtl = 0; mtl < 2; ++mtl) {
#pragma unroll
        for (int h = 0; h < 2; ++h) {
            const int row_lo = m0 + wm * 64 + mtl * 16 + h * 8 + r;
            const int head = row_lo >> 6;
            const int d = row_lo & 63;        // < 32
            float b_lo = bias[row_lo], b_hi = bias[row_lo + 32];
            uint32_t* dst = g_qh + ((size_t)(bz * NH + head) * 32 + d) * TT;
#pragma unroll
            for (int nt = 0; nt < 4; ++nt) {
                const int col = n0 + wn * 32 + nt * 8 + c * 2;
                float2 cs = *(const float2*)&g_cos[(size_t)d * TT + col];
                float2 sn = *(const float2*)&g_sin[(size_t)d * TT + col];
                float k1x = acc[mtl][nt][h * 2 + 0] + b_lo;
                float k1y = acc[mtl][nt][h * 2 + 1] + b_lo;
                float k2x = acc[mtl + 2][nt][h * 2 + 0] + b_hi;
                float k2y = acc[mtl + 2][nt][h * 2 + 1] + b_hi;
                uint2 o;
                o.x = h2pk(k1x * cs.x - k2x * sn.x, k2x * cs.x + k1x * sn.x);
                o.y = h2pk(k1y * cs.y - k2y * sn.y, k2y * cs.y + k1y * sn.y);
                *(uint2*)&dst[col] = o;
            }
        }
    }
}

// ============================================================================
// gemm_kv: k = rope+mask(wkc@cl + bkc) -> g_kh ; v = wvc@cl + bvc -> g_vh.
// A = packed-half weights (g_wkch/g_wvch), B = cond_latent fp32.
// grid (4, 2, 32): z&15 batch, z>>4 sel.
// ============================================================================
__global__ __launch_bounds__(256, 2)
void gemm_kv(const uint32_t* __restrict__ A0h, const uint32_t* __restrict__ A1h,
             const float* __restrict__ B,
             const float* __restrict__ bias0, const float* __restrict__ bias1,
             const float* __restrict__ cmask)
{
    extern __shared__ uint32_t smg[];
    uint32_t* Asm = smg;
    uint32_t* Bsm = smg + 2 * 16 * SA;
    GEMM_IDS
    const int bz  = blockIdx.z & 15;
    const int sel = blockIdx.z >> 4;
    const uint32_t* Ah  = sel ? A1h : A0h;
    const float*    bias = sel ? bias1 : bias0;
    const float* Bb = B + (size_t)bz * CONDC * TSL;
    const int m0 = blockIdx.y * 128, n0 = blockIdx.x * 128;
    float acc[4][4][4] = {};

    uint4 aw[2];
    float4 blo[2], bhi[2];
#define LDG_KV(k0)                                                                       \
    {                                                                                    \
        aw[0] = *(const uint4*)&Ah[(size_t)(m0 + a_m) * (CONDC/2) + (k0)/2 + a_kw];      \
        aw[1] = *(const uint4*)&Ah[(size_t)(m0 + a_m) * (CONDC/2) + (k0)/2 + a_kw + 4];  \
        _Pragma("unroll")                                                                \
        for (int j = 0; j < 2; ++j) {                                                    \
            blo[j] = *(const float4*)&Bb[(size_t)((k0) + 2 * b_kp)     * TSL + n0 + b_n4 + 64 * j]; \
            bhi[j] = *(const float4*)&Bb[(size_t)((k0) + 2 * b_kp + 1) * TSL + n0 + b_n4 + 64 * j]; \
        }                                                                                \
    }
#define STS_KV(buf)                                                                      \
    {                                                                                    \
        uint32_t* Ab = Asm + (buf) * 16 * SA;                                            \
        uint32_t* Bd = Bsm + (buf) * 16 * SA;                                            \
        Ab[(a_kw + 0) * SA + a_m] = aw[0].x;                                             \
        Ab[(a_kw + 1) * SA + a_m] = aw[0].y;                                             \
        Ab[(a_kw + 2) * SA + a_m] = aw[0].z;                                             \
        Ab[(a_kw + 3) * SA + a_m] = aw[0].w;                                             \
        Ab[(a_kw + 4) * SA + a_m] = aw[1].x;                                             \
        Ab[(a_kw + 5) * SA + a_m] = aw[1].y;                                             \
        Ab[(a_kw + 6) * SA + a_m] = aw[1].z;                                             \
        Ab[(a_kw + 7) * SA + a_m] = aw[1].w;                                             \
        _Pragma("unroll")                                                                \
        for (int j = 0; j < 2; ++j) {                                                    \
            uint4 w;                                                                    \
            w.x = h2pk(blo[j].x, bhi[j].x); w.y = h2pk(blo[j].y, bhi[j].y);              \
            w.z = h2pk(blo[j].z, bhi[j].z); w.w = h2pk(blo[j].w, bhi[j].w);              \
            *(uint4*)&Bd[b_kp * SA + b_n4 + 64 * j] = w;                                 \
        }                                                                                \
    }
    LDG_KV(0); STS_KV(0); __syncthreads();
    for (int kb = 0; kb < 16; ++kb) {
        const int cur = kb & 1;
        const bool more = (kb < 15);
        if (more) LDG_KV((kb + 1) * 32);
        GEMM_COMPUTE(Asm + cur * 16 * SA, Bsm + cur * 16 * SA)
        if (more) STS_KV(cur ^ 1);
        __syncthreads();
    }
#undef LDG_KV
#undef STS_KV

    if (sel == 0) {
        // k: rope + cond-mask -> packed (d, d+32)
#pragma unroll
        for (int mtl = 0; mtl < 2; ++mtl) {
#pragma unroll
            for (int h = 0; h < 2; ++h) {
                const int row_lo = m0 + wm * 64 + mtl * 16 + h * 8 + r;
                const int head = row_lo >> 6;
                const int d = row_lo & 63;
                float b_lo = bias[row_lo], b_hi = bias[row_lo + 32];
                uint32_t* dst = g_kh + ((size_t)(bz * NH + head) * 32 + d) * TSL;
#pragma unroll
                for (int nt = 0; nt < 4; ++nt) {
                    const int col = n0 + wn * 32 + nt * 8 + c * 2;
                    float2 cs = *(const float2*)&g_cos[(size_t)d * TT + col];
                    float2 sn = *(const float2*)&g_sin[(size_t)d * TT + col];
                    float2 cm = *(const float2*)&cmask[(size_t)bz * TSL + col];
                    float k1x = acc[mtl][nt][h * 2 + 0] + b_lo;
                    float k1y = acc[mtl][nt][h * 2 + 1] + b_lo;
                    float k2x = acc[mtl + 2][nt][h * 2 + 0] + b_hi;
                    float k2y = acc[mtl + 2][nt][h * 2 + 1] + b_hi;
                    uint2 o;
                    o.x = h2pk((k1x * cs.x - k2x * sn.x) * cm.x,
                               (k2x * cs.x + k1x * sn.x) * cm.x);
                    o.y = h2pk((k1y * cs.y - k2y * sn.y) * cm.y,
                               (k2y * cs.y + k1y * sn.y) * cm.y);
                    *(uint2*)&dst[col] = o;
                }
            }
        }
    } else {
        // v: packed position-pairs
#pragma unroll
        for (int mt = 0; mt < 4; ++mt) {
#pragma unroll
            for (int h = 0; h < 2; ++h) {
                const int row = m0 + wm * 64 + mt * 16 + h * 8 + r;
                float bval = bias[row];
                uint32_t* dst = g_vh + ((size_t)(bz * NH + (row >> 6)) * 64 + (row & 63)) * (TSL / 2);
#pragma unroll
                for (int nt = 0; nt < 4; ++nt) {
                    const int col = n0 + wn * 32 + nt * 8 + c * 2;
                    dst[col >> 1] = h2pk(acc[mt][nt][h * 2 + 0] + bval,
                                         acc[mt][nt][h * 2 + 1] + bval);
                }
            }
        }
    }
}

// ============================================================================
// gemm_cmb: weight combines -> packed-half outputs.
// z: 0 wkc=wk@w_cond [256x512], 1 wvc=wv@w_cond, 2 wfo=w_film@wo [512x256].
// ============================================================================
__global__ __launch_bounds__(256, 2)
void gemm_cmb(const float* __restrict__ wk, const float* __restrict__ wv,
              const float* __restrict__ wf,
              const float* __restrict__ w_cond, const float* __restrict__ wo)
{
    extern __shared__ uint32_t smg[];
    uint32_t* Asm = smg;
    uint32_t* Bsm = smg + 2 * 16 * SA;
    GEMM_IDS
    const int sel = blockIdx.z;
    const float* A    = (sel == 0) ? wk : (sel == 1) ? wv : wf;
    const float* Bsrc = (sel == 2) ? wo : w_cond;
    uint32_t*    Yh   = (sel == 0) ? g_wkch : (sel == 1) ? g_wvch : g_wfoh;
    const int Md = (sel < 2) ? 256 : 512;
    const int Ndim = (sel < 2) ? 512 : 256;
    if ((int)blockIdx.y * 128 >= Md || (int)blockIdx.x * 128 >= Ndim) return;
    const int m0 = blockIdx.y * 128, n0 = blockIdx.x * 128;
    float acc[4][4][4] = {};

    float4 avr[4], blo[2], bhi[2];
#define LDG_C(k0)                                                                        \
    {                                                                                    \
        _Pragma("unroll")                                                                \
        for (int j = 0; j < 4; ++j)                                                      \
            avr[j] = *(const float4*)&A[(size_t)(m0 + a_m) * CH + (k0) + a_kw * 2 + 4 * j]; \
        _Pragma("unroll")                                                                \
        for (int j = 0; j < 2; ++j) {                                                    \
            blo[j] = *(const float4*)&Bsrc[(size_t)((k0) + 2 * b_kp)     * Ndim + n0 + b_n4 + 64 * j]; \
            bhi[j] = *(const float4*)&Bsrc[(size_t)((k0) + 2 * b_kp + 1) * Ndim + n0 + b_n4 + 64 * j]; \
        }                                                                                \
    }
#define STS_C(buf)                                                                       \
    {                                                                                    \
        uint32_t* Ab = Asm + (buf) * 16 * SA;                                            \
        uint32_t* Bd = Bsm + (buf) * 16 * SA;                                            \
        _Pragma("unroll")                                                                \
        for (int j = 0; j < 4; ++j) {                                                    \
            Ab[(a_kw + 2 * j + 0) * SA + a_m] = h2pk(avr[j].x, avr[j].y);                \
            Ab[(a_kw + 2 * j + 1) * SA + a_m] = h2pk(avr[j].z, avr[j].w);                \
        }                                                                                \
        _Pragma("unroll")                                                                \
        for (int j = 0; j < 2; ++j) {                                                    \
            uint4 w;                                                                    \
            w.x = h2pk(blo[j].x, bhi[j].x); w.y = h2pk(blo[j].y, bhi[j].y);              \
            w.z = h2pk(blo[j].z, bhi[j].z); w.w = h2pk(blo[j].w, bhi[j].w);              \
            *(uint4*)&Bd[b_kp * SA + b_n4 + 64 * j] = w;                                 \
        }                                                                                \
    }
    LDG_C(0); STS_C(0); __syncthreads();
    for (int kb = 0; kb < 8; ++kb) {
        const int cur = kb & 1;
        const bool more = (kb < 7);
        if (more) LDG_C((kb + 1) * 32);
        GEMM_COMPUTE(Asm + cur * 16 * SA, Bsm + cur * 16 * SA)
        if (more) STS_C(cur ^ 1);
        __syncthreads();
    }
#undef LDG_C
#undef STS_C
    const int Nw = Ndim / 2;
#pragma unroll
    for (int mt = 0; mt < 4; ++mt) {
#pragma unroll
        for (int h = 0; h < 2; ++h) {
            const int row = m0 + wm * 64 + mt * 16 + h * 8 + r;
#pragma unroll
            for (int nt = 0; nt < 4; ++nt) {
                const int kp = (n0 + wn * 32 + nt * 8) / 2 + c;
                Yh[(size_t)row * Nw + kp] =
                    h2pk(acc[mt][nt][h * 2 + 0], acc[mt][nt][h * 2 + 1]);
            }
        }
    }
}

// ============================================================================
// Fused flash attention — all operands pre-packed half2, loads are pure
// uint4 copies. Fixed-shift exp2 softmax. Output -> g_atth (ch-pair packed).
// smem words: Qs[32][136] Ks[32][72] Vs[64][36] Ps[32][136] cmb[512]
// ============================================================================
#define FSA 136
#define FSK 72
#define FSV2 36
#define FSP 136
#define OFF_KS 4352
#define OFF_VS 6656
#define OFF_PS 8960
#define OFF_CMB 13312
#define FLASH_SMEM (13824 * 4)
#define SCALE_LOG2E 0.18033688f   // 0.125 * log2(e)

__global__ __launch_bounds__(256, 2)
void flash_attn(const float* __restrict__ cmask)
{
    extern __shared__ uint32_t sm[];
    uint32_t* Qs  = sm;
    uint32_t* Ks  = sm + OFF_KS;
    uint32_t* Vs  = sm + OFF_VS;
    uint32_t* Ps  = sm + OFF_PS;
    float*    cmb = (float*)(sm + OFF_CMB);

    const int bh = blockIdx.z;
    const int b  = bh >> 2;
    const int m0 = blockIdx.y * 128;
    const int tid = threadIdx.x, wid = tid >> 5, lane = tid & 31;
    const int r = lane >> 2, c = lane & 3;
    const int mb = wid * 16 + r;

    const uint32_t* Qb = g_qh + (size_t)bh * 32 * TT;
    const uint32_t* Kb = g_kh + (size_t)bh * 32 * TSL;
    const uint32_t* Vb = g_vh + (size_t)bh * 64 * (TSL / 2);

    // ---- Q tile: pure uint4 copy (32 pair-rows x 128 cols) ----
    {
        const int e  = tid >> 3;            // 0..31
        const int mg = (tid & 7) * 16;
#pragma unroll
        for (int j = 0; j < 4; ++j)
            *(uint4*)&Qs[e * FSA + mg + 4 * j] =
                *(const uint4*)&Qb[(size_t)e * TT + m0 + mg + 4 * j];
    }
    for (int i = tid; i < TSL; i += 256)
        cmb[i] = (cmask[(size_t)b * TSL + i] == 0.f) ? -14427.0f : 0.f;

    // ---- prefetch chunk 0 ----
    const int e2 = tid >> 3;            // K pair-row 0..31
    const int n8 = (tid & 7) * 8;
    const int ch = tid >> 2;            // V channel 0..63
    const int kw8 = (tid & 3) * 8;
    uint4 kr[2], vr[2];
    kr[0] = *(const uint4*)&Kb[(size_t)e2 * TSL + n8];
    kr[1] = *(const uint4*)&Kb[(size_t)e2 * TSL + n8 + 4];
    vr[0] = *(const uint4*)&Vb[(size_t)ch * (TSL / 2) + kw8];
    vr[1] = *(const uint4*)&Vb[(size_t)ch * (TSL / 2) + kw8 + 4];

    float l_run[2] = {0.f, 0.f};
    float acc_o[8][4] = {};

    __syncthreads();

    for (int ci = 0; ci < 8; ++ci) {
        const int s0 = ci * 64;
        *(uint4*)&Ks[e2 * FSK + n8]      = kr[0];
        *(uint4*)&Ks[e2 * FSK + n8 + 4]  = kr[1];
        *(uint4*)&Vs[ch * FSV2 + kw8]     = vr[0];
        *(uint4*)&Vs[ch * FSV2 + kw8 + 4] = vr[1];
        __syncthreads();
        if (ci < 7) {
            kr[0] = *(const uint4*)&Kb[(size_t)e2 * TSL + s0 + 64 + n8];
            kr[1] = *(const uint4*)&Kb[(size_t)e2 * TSL + s0 + 64 + n8 + 4];
            vr[0] = *(const uint4*)&Vb[(size_t)ch * (TSL / 2) + (s0 + 64) / 2 + kw8];
            vr[1] = *(const uint4*)&Vb[(size_t)ch * (TSL / 2) + (s0 + 64) / 2 + kw8 + 4];
        }

        // ---- S = Q^T K : warp tile 16 x 64 ----
        float acc_s[8][4] = {};
#pragma unroll
        for (int kw = 0; kw < 32; kw += 8) {
            uint32_t af[4];
            af[0] = Qs[(kw + c) * FSA + mb];
            af[1] = Qs[(kw + c) * FSA + mb + 8];
            af[2] = Qs[(kw + c + 4) * FSA + mb];
            af[3] = Qs[(kw + c + 4) * FSA + mb + 8];
#pragma unroll
            for (int nt = 0; nt < 8; ++nt) {
                uint32_t bf[2];
                bf[0] = Ks[(kw + c) * FSK + nt * 8 + r];
                bf[1] = Ks[(kw + c + 4) * FSK + nt * 8 + r];
                mma_f16(acc_s[nt], af, bf);
            }
        }

        // ---- exp2(scale*s + bias), row sums ----
        float lad[2] = {0.f, 0.f};
#pragma unroll
        for (int nt = 0; nt < 8; ++nt) {
            float2 bias = *(float2*)&cmb[s0 + nt * 8 + 2 * c];
#pragma unroll
            for (int jj = 0; jj < 4; ++jj) {
                float e = exp2f(acc_s[nt][jj] * SCALE_LOG2E + ((jj & 1) ? bias.y : bias.x));
                acc_s[nt][jj] = e;
                lad[jj >> 1] += e;
            }
        }
#pragma unroll
        for (int h = 0; h < 2; ++h) {
            lad[h] += __shfl_xor_sync(0xffffffffu, lad[h], 1);
            lad[h] += __shfl_xor_sync(0xffffffffu, lad[h], 2);
            l_run[h] += lad[h];
        }
#pragma unroll
        for (int nt = 0; nt < 8; ++nt) {
            int kwp = nt * 4 + c;
            Ps[kwp * FSP + wid * 16 + r]     = h2pk(acc_s[nt][0], acc_s[nt][1]);
            Ps[kwp * FSP + wid * 16 + r + 8] = h2pk(acc_s[nt][2], acc_s[nt][3]);
        }
        __syncwarp();

        // ---- O += P @ V^T ----
#pragma unroll
        for (int kw = 0; kw < 32; kw += 8) {
            uint32_t af[4];
            af[0] = Ps[(kw + c) * FSP + mb];
            af[1] = Ps[(kw + c) * FSP + mb + 8];
            af[2] = Ps[(kw + c + 4) * FSP + mb];
            af[3] = Ps[(kw + c + 4) * FSP + mb + 8];
#pragma unroll
            for (int nt = 0; nt < 8; ++nt) {
                uint32_t bf[2];
                bf[0] = Vs[(nt * 8 + r) * FSV2 + kw + c];
                bf[1] = Vs[(nt * 8 + r) * FSV2 + kw + c + 4];
                mma_f16(acc_o[nt], af, bf);
            }
        }
        __syncthreads();
    }

    // ---- epilogue: /l, transpose via smem, packed ch-pair store ----
    float inv[2] = {1.f / l_run[0], 1.f / l_run[1]};
    float* Pf = (float*)sm;    // [64][136] floats
#pragma unroll
    for (int nt = 0; nt < 8; ++nt) {
#pragma unroll
        for (int jj = 0; jj < 4; ++jj) {
            int n = nt * 8 + 2 * c + (jj & 1);
            int m = wid * 16 + r + (jj >> 1) * 8;
            Pf[n * FSA + m] = acc_o[nt][jj] * inv[jj >> 1];
        }
    }
    __syncthreads();
    {
        const int e  = tid >> 3;            // local ch-pair 0..31
        const int mq = (tid & 7) * 4;
        uint32_t* dst = g_atth + ((size_t)b * 128 + (bh & 3) * 32 + e) * TT;
#pragma unroll
        for (int j = 0; j < 4; ++j) {
            int m = mq + 32 * j;
            float4 lo = *(float4*)&Pf[(2 * e) * FSA + m];
            float4 hi = *(float4*)&Pf[(2 * e + 1) * FSA + m];
            uint4 w;
            w.x = h2pk(lo.x, hi.x); w.y = h2pk(lo.y, hi.y);
            w.z = h2pk(lo.z, hi.z); w.w = h2pk(lo.w, hi.w);
            *(uint4*)&dst[m0 + m] = w;
        }
    }
}

// ============================================================================
// Fused FiLM GEMM — A (wfo) and B (att) pre-packed half2: pure copy loads.
// ============================================================================
#define FILM_SMEM (6 * 16 * SA * 4)

__global__ __launch_bounds__(512)
void film_gemm(const float* __restrict__ bfilm, const float* __restrict__ x,
               const float* __restrict__ xmask, float* __restrict__ out)
{
    extern __shared__ uint32_t smf[];
    uint32_t* AsG = smf;
    uint32_t* AsB = smf + 2 * 16 * SA;
    uint32_t* Bs  = smf + 4 * 16 * SA;

    const int tid = threadIdx.x;
    const int bz  = blockIdx.z;
    const uint32_t* Bb = g_atth + (size_t)bz * 128 * TT;
    const int m0 = blockIdx.y * 128, n0 = blockIdx.x * 128;

    const int wid = tid >> 5, lane = tid & 31;
    const int wm = wid >> 2, wn = wid & 3;
    const int r = lane >> 2, c = lane & 3;

    const int a_kw = (tid & 3) * 4;
    const int a_m  = ((tid >> 2) + (tid & 3) * 8) & 127;
    const int b_kp = tid >> 5;
    const int b_n4 = (tid & 31) * 4;

    float acc_g[2][4][4] = {};
    float acc_b[2][4][4] = {};

    uint4 wG, wB, wBt;
#define LDG_TILE_F(k0)                                                                   \
    {                                                                                    \
        wG  = *(const uint4*)&g_wfoh[(size_t)(m0 + a_m) * 128 + (k0)/2 + a_kw];          \
        wB  = *(const uint4*)&g_wfoh[(size_t)(256 + m0 + a_m) * 128 + (k0)/2 + a_kw];    \
        wBt = *(const uint4*)&Bb[(size_t)((k0)/2 + b_kp) * TT + n0 + b_n4];              \
    }
#define STS_TILE_F(buf)                                                                  \
    {                                                                                    \
        uint32_t* G = AsG + (buf) * 16 * SA;                                             \
        uint32_t* Bq = AsB + (buf) * 16 * SA;                                            \
        G[(a_kw + 0) * SA + a_m] = wG.x;                                                 \
        G[(a_kw + 1) * SA + a_m] = wG.y;                                                 \
        G[(a_kw + 2) * SA + a_m] = wG.z;                                                 \
        G[(a_kw + 3) * SA + a_m] = wG.w;                                                 \
        Bq[(a_kw + 0) * SA + a_m] = wB.x;                                                \
        Bq[(a_kw + 1) * SA + a_m] = wB.y;                                                \
        Bq[(a_kw + 2) * SA + a_m] = wB.z;                                                \
        Bq[(a_kw + 3) * SA + a_m] = wB.w;                                                \
        *(uint4*)&Bs[(buf) * 16 * SA + b_kp * SA + b_n4] = wBt;                          \
    }

    LDG_TILE_F(0);
    STS_TILE_F(0);
    __syncthreads();

    const int nk = CH / 32;
    for (int kb = 0; kb < nk; ++kb) {
        const int cur = kb & 1;
        const bool more = (kb + 1 < nk);
        if (more) LDG_TILE_F((kb + 1) * 32);

#pragma unroll
        for (int kw = 0; kw < 16; kw += 8) {
            uint32_t afg[2][4], afb[2][4], bf[4][2];
#pragma unroll
            for (int mt = 0; mt < 2; ++mt) {
                int mbx = wm * 32 + mt * 16 + r;
                afg[mt][0] = AsG[cur * 16 * SA + (kw + c) * SA + mbx];
                afg[mt][1] = AsG[cur * 16 * SA + (kw + c) * SA + mbx + 8];
                afg[mt][2] = AsG[cur * 16 * SA + (kw + c + 4) * SA + mbx];
                afg[mt][3] = AsG[cur * 16 * SA + (kw + c + 4) * SA + mbx + 8];
                afb[mt][0] = AsB[cur * 16 * SA + (kw + c) * SA + mbx];
                afb[mt][1] = AsB[cur * 16 * SA + (kw + c) * SA + mbx + 8];
                afb[mt][2] = AsB[cur * 16 * SA + (kw + c + 4) * SA + mbx];
                afb[mt][3] = AsB[cur * 16 * SA + (kw + c + 4) * SA + mbx + 8];
            }
#pragma unroll
            for (int nt = 0; nt < 4; ++nt) {
                int nb = wn * 32 + nt * 8 + r;
                bf[nt][0] = Bs[cur * 16 * SA + (kw + c) * SA + nb];
                bf[nt][1] = Bs[cur * 16 * SA + (kw + c + 4) * SA + nb];
            }
#pragma unroll
            for (int mt = 0; mt < 2; ++mt)
#pragma unroll
                for (int nt = 0; nt < 4; ++nt) {
                    mma_f16(acc_g[mt][nt], afg[mt], bf[nt]);
                    mma_f16(acc_b[mt][nt], afb[mt], bf[nt]);
                }
        }
        if (more) STS_TILE_F(cur ^ 1);
        __syncthreads();
    }
#undef LDG_TILE_F
#undef STS_TILE_F

#pragma unroll
    for (int mt = 0; mt < 2; ++mt) {
#pragma unroll
        for (int h = 0; h < 2; ++h) {
            const int row = m0 + wm * 32 + mt * 16 + r + h * 8;
            float bg = bfilm[row];
            float bb = bfilm[256 + row];
#pragma unroll
            for (int nt = 0; nt < 4; ++nt) {
                const int col = n0 + wn * 32 + nt * 8 + c * 2;
                float g0  = acc_g[mt][nt][h * 2 + 0] + bg;
                float g1  = acc_g[mt][nt][h * 2 + 1] + bg;
                float be0 = acc_b[mt][nt][h * 2 + 0] + bb;
                float be1 = acc_b[mt][nt][h * 2 + 1] + bb;
                float2 xv = *(const float2*)&x[((size_t)bz * CH + row) * TT + col];
                float xmm0 = xmask[(size_t)bz * TT + col];
                float xmm1 = xmask[(size_t)bz * TT + col + 1];
                float2 o;
                o.x = (xv.x * g0 + be0) * xmm0;
                o.y = (xv.y * g1 + be1) * xmm1;
                *(float2*)&out[((size_t)bz * CH + row) * TT + col] = o;
            }
        }
    }
}

// ---------------- launch ----------------
extern "C" void kernel_launch(void* const* d_in, const int* in_sizes, int n_in,
                              void* d_out, int out_size) {
    const float* x           = (const float*)d_in[0];
    const float* x_mask      = (const float*)d_in[1];
    const float* cond_latent = (const float*)d_in[2];
    const float* cond_mask   = (const float*)d_in[3];
    const float* w_cond      = (const float*)d_in[4];
    const float* b_cond      = (const float*)d_in[5];
    const float* wq          = (const float*)d_in[6];
    const float* bq          = (const float*)d_in[7];
    const float* wk          = (const float*)d_in[8];
    const float* bk          = (const float*)d_in[9];
    const float* wv          = (const float*)d_in[10];
    const float* bv          = (const float*)d_in[11];
    const float* wo          = (const float*)d_in[12];
    const float* bo          = (const float*)d_in[13];
    const float* w_film      = (const float*)d_in[14];
    const float* b_film      = (const float*)d_in[15];
    float* out = (float*)d_out;

    uint32_t *p_wkch, *p_wvch;
    float *p_bkc, *p_bvc, *p_bfo;
    cudaGetSymbolAddress((void**)&p_wkch, g_wkch);
    cudaGetSymbolAddress((void**)&p_wvch, g_wvch);
    cudaGetSymbolAddress((void**)&p_bkc,  g_bkc);
    cudaGetSymbolAddress((void**)&p_bvc,  g_bvc);
    cudaGetSymbolAddress((void**)&p_bfo,  g_bfo);

    cudaFuncSetAttribute(gemm_q,    cudaFuncAttributeMaxDynamicSharedMemorySize, GEMM_SMEM);
    cudaFuncSetAttribute(gemm_kv,   cudaFuncAttributeMaxDynamicSharedMemorySize, GEMM_SMEM);
    cudaFuncSetAttribute(gemm_cmb,  cudaFuncAttributeMaxDynamicSharedMemorySize, GEMM_SMEM);
    cudaFuncSetAttribute(flash_attn, cudaFuncAttributeMaxDynamicSharedMemorySize, FLASH_SMEM);
    cudaFuncSetAttribute(film_gemm, cudaFuncAttributeMaxDynamicSharedMemorySize, FILM_SMEM);

    // prologue
    rope_table_kernel<<<(32 * TT + 255) / 256, 256>>>();
    bias_combine2_kernel<<<4, 256>>>(wk, bk, wv, bv, b_cond, w_film, b_film, bo);

    // weight combines -> packed half
    gemm_cmb<<<dim3(4, 4, 3), 256, GEMM_SMEM>>>(wk, wv, w_film, w_cond, wo);

    // q = rope(wq @ x + bq) -> g_qh
    gemm_q<<<dim3(TT / 128, CH / 128, BQ), 256, GEMM_SMEM>>>(wq, x, bq);

    // k -> g_kh (rope+mask); v -> g_vh
    gemm_kv<<<dim3(TSL / 128, CH / 128, 2 * BQ), 256, GEMM_SMEM>>>(
        p_wkch, p_wvch, cond_latent, p_bkc, p_bvc, cond_mask);

    // fused attention -> g_atth
    flash_attn<<<dim3(1, TT / 128, BQ * NH), 256, FLASH_SMEM>>>(cond_mask);

    // fused FiLM
    film_gemm<<<dim3(TT / 128, CH / 128, BQ), 512, FILM_SMEM>>>(
        p_bfo, x, x_mask, out);
}

// round 16
// speedup vs baseline: 1.8481x; 1.1053x over previous
#include <cuda_runtime.h>
#include <math.h>
#include <stdint.h>

// ---------------- problem constants (fixed shapes) ----------------
#define BQ   16
#define CH   256
#define CONDC 512
#define TT   2048
#define TSL  512
#define NH   4
#define KC   64

#define SA 136       // padded smem stride (words): mod 32 = 8, *4 % 16 == 0

// ---------------- scratch (device globals; no allocation) ----------------
__device__ uint32_t g_qh  [BQ * NH * 32 * TT];      // [bh][pair d,(d+32)][t]
__device__ uint32_t g_kh  [BQ * NH * 32 * TSL];     // [bh][pair d,(d+32)][t] roped+masked
__device__ uint32_t g_vh  [BQ * NH * 64 * (TSL/2)]; // [bh][ch][pos-pair]
__device__ uint32_t g_atth[BQ * 128 * TT];          // [b][ch-pair][t]
__device__ uint32_t g_wkch[CH * (CONDC/2)];         // [m][k-pair]  wk@w_cond
__device__ uint32_t g_wvch[CH * (CONDC/2)];         // [m][k-pair]  wv@w_cond
__device__ uint32_t g_wfoh[2 * CH * (CH/2)];        // [m][k-pair]  w_film@wo
__device__ float g_bkc[CH];
__device__ float g_bvc[CH];
__device__ float g_bfo[2 * CH];
__device__ float g_cos[32 * TT];                    // [d][t]
__device__ float g_sin[32 * TT];

// ---------------- fp16 helpers ----------------
__device__ __forceinline__ uint32_t h2pk(float lo, float hi) {
    uint32_t u;
    asm("cvt.rn.f16x2.f32 %0, %1, %2;" : "=r"(u) : "f"(hi), "f"(lo));
    return u;
}

__device__ __forceinline__ void mma_f16(float* c, const uint32_t* a, const uint32_t* b) {
    asm volatile(
        "mma.sync.aligned.m16n8k16.row.col.f32.f16.f16.f32 "
        "{%0,%1,%2,%3}, {%4,%5,%6,%7}, {%8,%9}, {%0,%1,%2,%3};\n"
        : "+f"(c[0]), "+f"(c[1]), "+f"(c[2]), "+f"(c[3])
        : "r"(a[0]), "r"(a[1]), "r"(a[2]), "r"(a[3]), "r"(b[0]), "r"(b[1]));
}

// ---------------- prologue: RoPE tables + combined biases (one launch) ----
__global__ void prologue_kernel(const float* __restrict__ wk, const float* __restrict__ bk,
                                const float* __restrict__ wv, const float* __restrict__ bv,
                                const float* __restrict__ b_cond,
                                const float* __restrict__ wf, const float* __restrict__ bf,
                                const float* __restrict__ bo) {
    if (blockIdx.x < 256) {
        int idx = blockIdx.x * 256 + threadIdx.x;   // 0..65535
        int d = idx / TT;
        int t = idx % TT;
        float invf = (float)pow(10000.0, -(double)d / 32.0);
        float ang  = (float)t * invf;               // same fp32 rounding as reference
        g_cos[idx] = (float)cos((double)ang);
        g_sin[idx] = (float)sin((double)ang);
    } else {
        int tid = (blockIdx.x - 256) * 256 + threadIdx.x;   // 0..1023
        if (tid < 256) {
            float s = 0.f;
            for (int k = 0; k < CH; ++k) s += wk[tid * CH + k] * b_cond[k];
            g_bkc[tid] = s + bk[tid];
        } else if (tid < 512) {
            int m = tid - 256;
            float s = 0.f;
            for (int k = 0; k < CH; ++k) s += wv[m * CH + k] * b_cond[k];
            g_bvc[m] = s + bv[m];
        } else {
            int m = tid - 512;
            float s = 0.f;
            for (int k = 0; k < CH; ++k) s += wf[m * CH + k] * bo[k];
            g_bfo[m] = s + bf[m];
        }
    }
}

// ============================================================================
// Shared fp16-MMA mainloop pieces (128x128 CTA tile, 256 thr, 8 warps 2x4,
// warp tile 64x32, BK=32 floats = 16 half2 word-rows, double-buffered smem).
// ============================================================================
#define GEMM_SMEM (4 * 16 * SA * 4)

#define GEMM_IDS                                                         \
    const int tid = threadIdx.x;                                         \
    const int wid = tid >> 5, lane = tid & 31;                           \
    const int wm = wid >> 2, wn = wid & 3;                               \
    const int r = lane >> 2, c = lane & 3;                               \
    const int a_m  = ((tid >> 1) + ((tid & 1) << 4)) & 127;              \
    const int a_kw = (tid & 1) * 8;                                      \
    const int b_kp = tid >> 4;                                           \
    const int b_n4 = (tid & 15) * 4;

#define GEMM_COMPUTE(Ac, Bc)                                             \
    _Pragma("unroll")                                                    \
    for (int kw = 0; kw < 16; kw += 8) {                                 \
        uint32_t af[4][4], bf[4][2];                                     \
        _Pragma("unroll")                                                \
        for (int mt = 0; mt < 4; ++mt) {                                 \
            int mb = wm * 64 + mt * 16 + r;                              \
            af[mt][0] = (Ac)[(kw + c) * SA + mb];                        \
            af[mt][1] = (Ac)[(kw + c) * SA + mb + 8];                    \
            af[mt][2] = (Ac)[(kw + c + 4) * SA + mb];                    \
            af[mt][3] = (Ac)[(kw + c + 4) * SA + mb + 8];                \
        }                                                                \
        _Pragma("unroll")                                                \
        for (int nt = 0; nt < 4; ++nt) {                                 \
            int nb = wn * 32 + nt * 8 + r;                               \
            bf[nt][0] = (Bc)[(kw + c) * SA + nb];                        \
            bf[nt][1] = (Bc)[(kw + c + 4) * SA + nb];                    \
        }                                                                \
        _Pragma("unroll")                                                \
        for (int mt = 0; mt < 4; ++mt)                                   \
            _Pragma("unroll")                                            \
            for (int nt = 0; nt < 4; ++nt)                               \
                mma_f16(acc[mt][nt], af[mt], bf[nt]);                    \
    }

// ============================================================================
// gemm_q: q = rope(wq @ x + bq) -> g_qh packed (d, d+32). A,B fp32.
// ============================================================================
__global__ __launch_bounds__(256, 2)
void gemm_q(const float* __restrict__ A, const float* __restrict__ B,
            const float* __restrict__ bias)
{
    extern __shared__ uint32_t smg[];
    uint32_t* Asm = smg;
    uint32_t* Bsm = smg + 2 * 16 * SA;
    GEMM_IDS
    const int bz = blockIdx.z;
    const float* Bb = B + (size_t)bz * CH * TT;
    const int m0 = blockIdx.y * 128, n0 = blockIdx.x * 128;
    float acc[4][4][4] = {};

    float4 avr[4], blo[2], bhi[2];
#define LDG_Q(k0)                                                                        \
    {                                                                                    \
        _Pragma("unroll")                                                                \
        for (int j = 0; j < 4; ++j)                                                      \
            avr[j] = *(const float4*)&A[(size_t)(m0 + a_m) * CH + (k0) + a_kw * 2 + 4 * j]; \
        _Pragma("unroll")                                                                \
        for (int j = 0; j < 2; ++j) {                                                    \
            blo[j] = *(const float4*)&Bb[(size_t)((k0) + 2 * b_kp)     * TT + n0 + b_n4 + 64 * j]; \
            bhi[j] = *(const float4*)&Bb[(size_t)((k0) + 2 * b_kp + 1) * TT + n0 + b_n4 + 64 * j]; \
        }                                                                                \
    }
#define STS_Q(buf)                                                                       \
    {                                                                                    \
        uint32_t* Ab = Asm + (buf) * 16 * SA;                                            \
        uint32_t* Bd = Bsm + (buf) * 16 * SA;                                            \
        _Pragma("unroll")                                                                \
        for (int j = 0; j < 4; ++j) {                                                    \
            Ab[(a_kw + 2 * j + 0) * SA + a_m] = h2pk(avr[j].x, avr[j].y);                \
            Ab[(a_kw + 2 * j + 1) * SA + a_m] = h2pk(avr[j].z, avr[j].w);                \
        }                                                                                \
        _Pragma("unroll")                                                                \
        for (int j = 0; j < 2; ++j) {                                                    \
            uint4 w;                                                                    \
            w.x = h2pk(blo[j].x, bhi[j].x); w.y = h2pk(blo[j].y, bhi[j].y);              \
            w.z = h2pk(blo[j].z, bhi[j].z); w.w = h2pk(blo[j].w, bhi[j].w);              \
            *(uint4*)&Bd[b_kp * SA + b_n4 + 64 * j] = w;                                 \
        }                                                                                \
    }
    LDG_Q(0); STS_Q(0); __syncthreads();
    for (int kb = 0; kb < 8; ++kb) {
        const int cur = kb & 1;
        const bool more = (kb < 7);
        if (more) LDG_Q((kb + 1) * 32);
        GEMM_COMPUTE(Asm + cur * 16 * SA, Bsm + cur * 16 * SA)
        if (more) STS_Q(cur ^ 1);
        __syncthreads();
    }
#undef LDG_Q
#undef STS_Q
#pragma unroll
    for (int mtl = 0; mtl < 2; ++mtl) {
#pragma unroll
        for (int h = 0; h < 2; ++h) {
            const int row_lo = m0 + wm * 64 + mtl * 16 + h * 8 + r;
            const int head = row_lo >> 6;
            const int d = row_lo & 63;        // < 32
            float b_lo = bias[row_lo], b_hi = bias[row_lo + 32];
            uint32_t* dst = g_qh + ((size_t)(bz * NH + head) * 32 + d) * TT;
#pragma unroll
            for (int nt = 0; nt < 4; ++nt) {
                const int col = n0 + wn * 32 + nt * 8 + c * 2;
                float2 cs = *(const float2*)&g_cos[(size_t)d * TT + col];
                float2 sn = *(const float2*)&g_sin[(size_t)d * TT + col];
                float k1x = acc[mtl][nt][h * 2 + 0] + b_lo;
                float k1y = acc[mtl][nt][h * 2 + 1] + b_lo;
                float k2x = acc[mtl + 2][nt][h * 2 + 0] + b_hi;
                float k2y = acc[mtl + 2][nt][h * 2 + 1] + b_hi;
                uint2 o;
                o.x = h2pk(k1x * cs.x - k2x * sn.x, k2x * cs.x + k1x * sn.x);
                o.y = h2pk(k1y * cs.y - k2y * sn.y, k2y * cs.y + k1y * sn.y);
                *(uint2*)&dst[col] = o;
            }
        }
    }
}

// ============================================================================
// gemm_kv: k = rope+mask(wkc@cl + bkc) -> g_kh ; v = wvc@cl + bvc -> g_vh.
// ============================================================================
__global__ __launch_bounds__(256, 2)
void gemm_kv(const uint32_t* __restrict__ A0h, const uint32_t* __restrict__ A1h,
             const float* __restrict__ B,
             const float* __restrict__ bias0, const float* __restrict__ bias1,
             const float* __restrict__ cmask)
{
    extern __shared__ uint32_t smg[];
    uint32_t* Asm = smg;
    uint32_t* Bsm = smg + 2 * 16 * SA;
    GEMM_IDS
    const int bz  = blockIdx.z & 15;
    const int sel = blockIdx.z >> 4;
    const uint32_t* Ah  = sel ? A1h : A0h;
    const float*    bias = sel ? bias1 : bias0;
    const float* Bb = B + (size_t)bz * CONDC * TSL;
    const int m0 = blockIdx.y * 128, n0 = blockIdx.x * 128;
    float acc[4][4][4] = {};

    uint4 aw[2];
    float4 blo[2], bhi[2];
#define LDG_KV(k0)                                                                       \
    {                                                                                    \
        aw[0] = *(const uint4*)&Ah[(size_t)(m0 + a_m) * (CONDC/2) + (k0)/2 + a_kw];      \
        aw[1] = *(const uint4*)&Ah[(size_t)(m0 + a_m) * (CONDC/2) + (k0)/2 + a_kw + 4];  \
        _Pragma("unroll")                                                                \
        for (int j = 0; j < 2; ++j) {                                                    \
            blo[j] = *(const float4*)&Bb[(size_t)((k0) + 2 * b_kp)     * TSL + n0 + b_n4 + 64 * j]; \
            bhi[j] = *(const float4*)&Bb[(size_t)((k0) + 2 * b_kp + 1) * TSL + n0 + b_n4 + 64 * j]; \
        }                                                                                \
    }
#define STS_KV(buf)                                                                      \
    {                                                                                    \
        uint32_t* Ab = Asm + (buf) * 16 * SA;                                            \
        uint32_t* Bd = Bsm + (buf) * 16 * SA;                                            \
        Ab[(a_kw + 0) * SA + a_m] = aw[0].x;                                             \
        Ab[(a_kw + 1) * SA + a_m] = aw[0].y;                                             \
        Ab[(a_kw + 2) * SA + a_m] = aw[0].z;                                             \
        Ab[(a_kw + 3) * SA + a_m] = aw[0].w;                                             \
        Ab[(a_kw + 4) * SA + a_m] = aw[1].x;                                             \
        Ab[(a_kw + 5) * SA + a_m] = aw[1].y;                                             \
        Ab[(a_kw + 6) * SA + a_m] = aw[1].z;                                             \
        Ab[(a_kw + 7) * SA + a_m] = aw[1].w;                                             \
        _Pragma("unroll")                                                                \
        for (int j = 0; j < 2; ++j) {                                                    \
            uint4 w;                                                                    \
            w.x = h2pk(blo[j].x, bhi[j].x); w.y = h2pk(blo[j].y, bhi[j].y);              \
            w.z = h2pk(blo[j].z, bhi[j].z); w.w = h2pk(blo[j].w, bhi[j].w);              \
            *(uint4*)&Bd[b_kp * SA + b_n4 + 64 * j] = w;                                 \
        }                                                                                \
    }
    LDG_KV(0); STS_KV(0); __syncthreads();
    for (int kb = 0; kb < 16; ++kb) {
        const int cur = kb & 1;
        const bool more = (kb < 15);
        if (more) LDG_KV((kb + 1) * 32);
        GEMM_COMPUTE(Asm + cur * 16 * SA, Bsm + cur * 16 * SA)
        if (more) STS_KV(cur ^ 1);
        __syncthreads();
    }
#undef LDG_KV
#undef STS_KV

    if (sel == 0) {
#pragma unroll
        for (int mtl = 0; mtl < 2; ++mtl) {
#pragma unroll
            for (int h = 0; h < 2; ++h) {
                const int row_lo = m0 + wm * 64 + mtl * 16 + h * 8 + r;
                const int head = row_lo >> 6;
                const int d = row_lo & 63;
                float b_lo = bias[row_lo], b_hi = bias[row_lo + 32];
                uint32_t* dst = g_kh + ((size_t)(bz * NH + head) * 32 + d) * TSL;
#pragma unroll
                for (int nt = 0; nt < 4; ++nt) {
                    const int col = n0 + wn * 32 + nt * 8 + c * 2;
                    float2 cs = *(const float2*)&g_cos[(size_t)d * TT + col];
                    float2 sn = *(const float2*)&g_sin[(size_t)d * TT + col];
                    float2 cm = *(const float2*)&cmask[(size_t)bz * TSL + col];
                    float k1x = acc[mtl][nt][h * 2 + 0] + b_lo;
                    float k1y = acc[mtl][nt][h * 2 + 1] + b_lo;
                    float k2x = acc[mtl + 2][nt][h * 2 + 0] + b_hi;
                    float k2y = acc[mtl + 2][nt][h * 2 + 1] + b_hi;
                    uint2 o;
                    o.x = h2pk((k1x * cs.x - k2x * sn.x) * cm.x,
                               (k2x * cs.x + k1x * sn.x) * cm.x);
                    o.y = h2pk((k1y * cs.y - k2y * sn.y) * cm.y,
                               (k2y * cs.y + k1y * sn.y) * cm.y);
                    *(uint2*)&dst[col] = o;
                }
            }
        }
    } else {
#pragma unroll
        for (int mt = 0; mt < 4; ++mt) {
#pragma unroll
            for (int h = 0; h < 2; ++h) {
                const int row = m0 + wm * 64 + mt * 16 + h * 8 + r;
                float bval = bias[row];
                uint32_t* dst = g_vh + ((size_t)(bz * NH + (row >> 6)) * 64 + (row & 63)) * (TSL / 2);
#pragma unroll
                for (int nt = 0; nt < 4; ++nt) {
                    const int col = n0 + wn * 32 + nt * 8 + c * 2;
                    dst[col >> 1] = h2pk(acc[mt][nt][h * 2 + 0] + bval,
                                         acc[mt][nt][h * 2 + 1] + bval);
                }
            }
        }
    }
}

// ============================================================================
// gemm_cmb: weight combines -> packed-half outputs.
// ============================================================================
__global__ __launch_bounds__(256, 2)
void gemm_cmb(const float* __restrict__ wk, const float* __restrict__ wv,
              const float* __restrict__ wf,
              const float* __restrict__ w_cond, const float* __restrict__ wo)
{
    extern __shared__ uint32_t smg[];
    uint32_t* Asm = smg;
    uint32_t* Bsm = smg + 2 * 16 * SA;
    GEMM_IDS
    const int sel = blockIdx.z;
    const float* A    = (sel == 0) ? wk : (sel == 1) ? wv : wf;
    const float* Bsrc = (sel == 2) ? wo : w_cond;
    uint32_t*    Yh   = (sel == 0) ? g_wkch : (sel == 1) ? g_wvch : g_wfoh;
    const int Md = (sel < 2) ? 256 : 512;
    const int Ndim = (sel < 2) ? 512 : 256;
    if ((int)blockIdx.y * 128 >= Md || (int)blockIdx.x * 128 >= Ndim) return;
    const int m0 = blockIdx.y * 128, n0 = blockIdx.x * 128;
    float acc[4][4][4] = {};

    float4 avr[4], blo[2], bhi[2];
#define LDG_C(k0)                                                                        \
    {                                                                                    \
        _Pragma("unroll")                                                                \
        for (int j = 0; j < 4; ++j)                                                      \
            avr[j] = *(const float4*)&A[(size_t)(m0 + a_m) * CH + (k0) + a_kw * 2 + 4 * j]; \
        _Pragma("unroll")                                                                \
        for (int j = 0; j < 2; ++j) {                                                    \
            blo[j] = *(const float4*)&Bsrc[(size_t)((k0) + 2 * b_kp)     * Ndim + n0 + b_n4 + 64 * j]; \
            bhi[j] = *(const float4*)&Bsrc[(size_t)((k0) + 2 * b_kp + 1) * Ndim + n0 + b_n4 + 64 * j]; \
        }                                                                                \
    }
#define STS_C(buf)                                                                       \
    {                                                                                    \
        uint32_t* Ab = Asm + (buf) * 16 * SA;                                            \
        uint32_t* Bd = Bsm + (buf) * 16 * SA;                                            \
        _Pragma("unroll")                                                                \
        for (int j = 0; j < 4; ++j) {                                                    \
            Ab[(a_kw + 2 * j + 0) * SA + a_m] = h2pk(avr[j].x, avr[j].y);                \
            Ab[(a_kw + 2 * j + 1) * SA + a_m] = h2pk(avr[j].z, avr[j].w);                \
        }                                                                                \
        _Pragma("unroll")                                                                \
        for (int j = 0; j < 2; ++j) {                                                    \
            uint4 w;                                                                    \
            w.x = h2pk(blo[j].x, bhi[j].x); w.y = h2pk(blo[j].y, bhi[j].y);              \
            w.z = h2pk(blo[j].z, bhi[j].z); w.w = h2pk(blo[j].w, bhi[j].w);              \
            *(uint4*)&Bd[b_kp * SA + b_n4 + 64 * j] = w;                                 \
        }                                                                                \
    }
    LDG_C(0); STS_C(0); __syncthreads();
    for (int kb = 0; kb < 8; ++kb) {
        const int cur = kb & 1;
        const bool more = (kb < 7);
        if (more) LDG_C((kb + 1) * 32);
        GEMM_COMPUTE(Asm + cur * 16 * SA, Bsm + cur * 16 * SA)
        if (more) STS_C(cur ^ 1);
        __syncthreads();
    }
#undef LDG_C
#undef STS_C
    const int Nw = Ndim / 2;
#pragma unroll
    for (int mt = 0; mt < 4; ++mt) {
#pragma unroll
        for (int h = 0; h < 2; ++h) {
            const int row = m0 + wm * 64 + mt * 16 + h * 8 + r;
#pragma unroll
            for (int nt = 0; nt < 4; ++nt) {
                const int kp = (n0 + wn * 32 + nt * 8) / 2 + c;
                Yh[(size_t)row * Nw + kp] =
                    h2pk(acc[mt][nt][h * 2 + 0], acc[mt][nt][h * 2 + 1]);
            }
        }
    }
}

// ============================================================================
// Fused flash attention — packed operands, pure-copy loads, fixed-shift exp2
// softmax, and FA2-style register reuse: P (S fragment) feeds PV MMAs
// DIRECTLY from registers (C-layout == A-layout), no smem round-trip.
// smem words: Qs[32][136]=4352 | Ks[32][72]=2304 | Vs[64][36]=2304 | cmb[512]
// ============================================================================
#define FSA 136
#define FSK 72
#define FSV2 36
#define OFF_KS 4352
#define OFF_VS 6656
#define OFF_CMB 8960
#define FLASH_SMEM (9472 * 4)
#define SCALE_LOG2E 0.18033688f   // 0.125 * log2(e)

__global__ __launch_bounds__(256, 2)
void flash_attn(const float* __restrict__ cmask)
{
    extern __shared__ uint32_t sm[];
    uint32_t* Qs  = sm;
    uint32_t* Ks  = sm + OFF_KS;
    uint32_t* Vs  = sm + OFF_VS;
    float*    cmb = (float*)(sm + OFF_CMB);

    const int bh = blockIdx.z;
    const int b  = bh >> 2;
    const int m0 = blockIdx.y * 128;
    const int tid = threadIdx.x, wid = tid >> 5, lane = tid & 31;
    const int r = lane >> 2, c = lane & 3;
    const int mb = wid * 16 + r;

    const uint32_t* Qb = g_qh + (size_t)bh * 32 * TT;
    const uint32_t* Kb = g_kh + (size_t)bh * 32 * TSL;
    const uint32_t* Vb = g_vh + (size_t)bh * 64 * (TSL / 2);

    // ---- Q tile: pure uint4 copy ----
    {
        const int e  = tid >> 3;            // 0..31
        const int mg = (tid & 7) * 16;
#pragma unroll
        for (int j = 0; j < 4; ++j)
            *(uint4*)&Qs[e * FSA + mg + 4 * j] =
                *(const uint4*)&Qb[(size_t)e * TT + m0 + mg + 4 * j];
    }
    for (int i = tid; i < TSL; i += 256)
        cmb[i] = (cmask[(size_t)b * TSL + i] == 0.f) ? -14427.0f : 0.f;

    // ---- prefetch chunk 0 ----
    const int e2 = tid >> 3;            // K pair-row 0..31
    const int n8 = (tid & 7) * 8;
    const int ch = tid >> 2;            // V channel 0..63
    const int kw8 = (tid & 3) * 8;
    uint4 kr[2], vr[2];
    kr[0] = *(const uint4*)&Kb[(size_t)e2 * TSL + n8];
    kr[1] = *(const uint4*)&Kb[(size_t)e2 * TSL + n8 + 4];
    vr[0] = *(const uint4*)&Vb[(size_t)ch * (TSL / 2) + kw8];
    vr[1] = *(const uint4*)&Vb[(size_t)ch * (TSL / 2) + kw8 + 4];

    float l_run[2] = {0.f, 0.f};
    float acc_o[8][4] = {};

    __syncthreads();

    for (int ci = 0; ci < 8; ++ci) {
        const int s0 = ci * 64;
        *(uint4*)&Ks[e2 * FSK + n8]       = kr[0];
        *(uint4*)&Ks[e2 * FSK + n8 + 4]   = kr[1];
        *(uint4*)&Vs[ch * FSV2 + kw8]     = vr[0];
        *(uint4*)&Vs[ch * FSV2 + kw8 + 4] = vr[1];
        __syncthreads();
        if (ci < 7) {
            kr[0] = *(const uint4*)&Kb[(size_t)e2 * TSL + s0 + 64 + n8];
            kr[1] = *(const uint4*)&Kb[(size_t)e2 * TSL + s0 + 64 + n8 + 4];
            vr[0] = *(const uint4*)&Vb[(size_t)ch * (TSL / 2) + (s0 + 64) / 2 + kw8];
            vr[1] = *(const uint4*)&Vb[(size_t)ch * (TSL / 2) + (s0 + 64) / 2 + kw8 + 4];
        }

        // ---- S = Q^T K : warp tile 16 x 64 ----
        float acc_s[8][4] = {};
#pragma unroll
        for (int kw = 0; kw < 32; kw += 8) {
            uint32_t af[4];
            af[0] = Qs[(kw + c) * FSA + mb];
            af[1] = Qs[(kw + c) * FSA + mb + 8];
            af[2] = Qs[(kw + c + 4) * FSA + mb];
            af[3] = Qs[(kw + c + 4) * FSA + mb + 8];
#pragma unroll
            for (int nt = 0; nt < 8; ++nt) {
                uint32_t bf[2];
                bf[0] = Ks[(kw + c) * FSK + nt * 8 + r];
                bf[1] = Ks[(kw + c + 4) * FSK + nt * 8 + r];
                mma_f16(acc_s[nt], af, bf);
            }
        }

        // ---- exp2(scale*s + bias), row sums ----
        float lad[2] = {0.f, 0.f};
#pragma unroll
        for (int nt = 0; nt < 8; ++nt) {
            float2 bias = *(float2*)&cmb[s0 + nt * 8 + 2 * c];
#pragma unroll
            for (int jj = 0; jj < 4; ++jj) {
                float e = exp2f(acc_s[nt][jj] * SCALE_LOG2E + ((jj & 1) ? bias.y : bias.x));
                acc_s[nt][jj] = e;
                lad[jj >> 1] += e;
            }
        }
#pragma unroll
        for (int h = 0; h < 2; ++h) {
            lad[h] += __shfl_xor_sync(0xffffffffu, lad[h], 1);
            lad[h] += __shfl_xor_sync(0xffffffffu, lad[h], 2);
            l_run[h] += lad[h];
        }

        // ---- O += P @ V^T : P fed DIRECTLY from S registers (C == A layout).
        // k16-step g covers score cols 16g..16g+15: A frag = S tiles 2g, 2g+1.
#pragma unroll
        for (int g = 0; g < 4; ++g) {
            uint32_t af[4];
            af[0] = h2pk(acc_s[2 * g][0],     acc_s[2 * g][1]);
            af[1] = h2pk(acc_s[2 * g][2],     acc_s[2 * g][3]);
            af[2] = h2pk(acc_s[2 * g + 1][0], acc_s[2 * g + 1][1]);
            af[3] = h2pk(acc_s[2 * g + 1][2], acc_s[2 * g + 1][3]);
            const int kw = 8 * g;
#pragma unroll
            for (int nt = 0; nt < 8; ++nt) {
                uint32_t bf[2];
                bf[0] = Vs[(nt * 8 + r) * FSV2 + kw + c];
                bf[1] = Vs[(nt * 8 + r) * FSV2 + kw + c + 4];
                mma_f16(acc_o[nt], af, bf);
            }
        }
        __syncthreads();   // Vs reads done before next chunk's stores
    }

    // ---- epilogue: /l, transpose via smem (reuse Q/K/V region), pack store ----
    float inv[2] = {1.f / l_run[0], 1.f / l_run[1]};
    float* Pf = (float*)sm;    // [64][136] floats = 8704 <= 9472 words
#pragma unroll
    for (int nt = 0; nt < 8; ++nt) {
#pragma unroll
        for (int jj = 0; jj < 4; ++jj) {
            int n = nt * 8 + 2 * c + (jj & 1);
            int m = wid * 16 + r + (jj >> 1) * 8;
            Pf[n * FSA + m] = acc_o[nt][jj] * inv[jj >> 1];
        }
    }
    __syncthreads();
    {
        const int e  = tid >> 3;            // local ch-pair 0..31
        const int mq = (tid & 7) * 4;
        uint32_t* dst = g_atth + ((size_t)b * 128 + (bh & 3) * 32 + e) * TT;
#pragma unroll
        for (int j = 0; j < 4; ++j) {
            int m = mq + 32 * j;
            float4 lo = *(float4*)&Pf[(2 * e) * FSA + m];
            float4 hi = *(float4*)&Pf[(2 * e + 1) * FSA + m];
            uint4 w;
            w.x = h2pk(lo.x, hi.x); w.y = h2pk(lo.y, hi.y);
            w.z = h2pk(lo.z, hi.z); w.w = h2pk(lo.w, hi.w);
            *(uint4*)&dst[m0 + m] = w;
        }
    }
}

// ============================================================================
// Fused FiLM GEMM — packed A/B, pure-copy loads (unchanged from R15).
// ============================================================================
#define FILM_SMEM (6 * 16 * SA * 4)

__global__ __launch_bounds__(512)
void film_gemm(const float* __restrict__ bfilm, const float* __restrict__ x,
               const float* __restrict__ xmask, float* __restrict__ out)
{
    extern __shared__ uint32_t smf[];
    uint32_t* AsG = smf;
    uint32_t* AsB = smf + 2 * 16 * SA;
    uint32_t* Bs  = smf + 4 * 16 * SA;

    const int tid = threadIdx.x;
    const int bz  = blockIdx.z;
    const uint32_t* Bb = g_atth + (size_t)bz * 128 * TT;
    const int m0 = blockIdx.y * 128, n0 = blockIdx.x * 128;

    const int wid = tid >> 5, lane = tid & 31;
    const int wm = wid >> 2, wn = wid & 3;
    const int r = lane >> 2, c = lane & 3;

    const int a_kw = (tid & 3) * 4;
    const int a_m  = ((tid >> 2) + (tid & 3) * 8) & 127;
    const int b_kp = tid >> 5;
    const int b_n4 = (tid & 31) * 4;

    float acc_g[2][4][4] = {};
    float acc_b[2][4][4] = {};

    uint4 wG, wB, wBt;
#define LDG_TILE_F(k0)                                                                   \
    {                                                                                    \
        wG  = *(const uint4*)&g_wfoh[(size_t)(m0 + a_m) * 128 + (k0)/2 + a_kw];          \
        wB  = *(const uint4*)&g_wfoh[(size_t)(256 + m0 + a_m) * 128 + (k0)/2 + a_kw];    \
        wBt = *(const uint4*)&Bb[(size_t)((k0)/2 + b_kp) * TT + n0 + b_n4];              \
    }
#define STS_TILE_F(buf)                                                                  \
    {                                                                                    \
        uint32_t* G = AsG + (buf) * 16 * SA;                                             \
        uint32_t* Bq = AsB + (buf) * 16 * SA;                                            \
        G[(a_kw + 0) * SA + a_m] = wG.x;                                                 \
        G[(a_kw + 1) * SA + a_m] = wG.y;                                                 \
        G[(a_kw + 2) * SA + a_m] = wG.z;                                                 \
        G[(a_kw + 3) * SA + a_m] = wG.w;                                                 \
        Bq[(a_kw + 0) * SA + a_m] = wB.x;                                                \
        Bq[(a_kw + 1) * SA + a_m] = wB.y;                                                \
        Bq[(a_kw + 2) * SA + a_m] = wB.z;                                                \
        Bq[(a_kw + 3) * SA + a_m] = wB.w;                                                \
        *(uint4*)&Bs[(buf) * 16 * SA + b_kp * SA + b_n4] = wBt;                          \
    }

    LDG_TILE_F(0);
    STS_TILE_F(0);
    __syncthreads();

    const int nk = CH / 32;
    for (int kb = 0; kb < nk; ++kb) {
        const int cur = kb & 1;
        const bool more = (kb + 1 < nk);
        if (more) LDG_TILE_F((kb + 1) * 32);

#pragma unroll
        for (int kw = 0; kw < 16; kw += 8) {
            uint32_t afg[2][4], afb[2][4], bf[4][2];
#pragma unroll
            for (int mt = 0; mt < 2; ++mt) {
                int mbx = wm * 32 + mt * 16 + r;
                afg[mt][0] = AsG[cur * 16 * SA + (kw + c) * SA + mbx];
                afg[mt][1] = AsG[cur * 16 * SA + (kw + c) * SA + mbx + 8];
                afg[mt][2] = AsG[cur * 16 * SA + (kw + c + 4) * SA + mbx];
                afg[mt][3] = AsG[cur * 16 * SA + (kw + c + 4) * SA + mbx + 8];
                afb[mt][0] = AsB[cur * 16 * SA + (kw + c) * SA + mbx];
                afb[mt][1] = AsB[cur * 16 * SA + (kw + c) * SA + mbx + 8];
                afb[mt][2] = AsB[cur * 16 * SA + (kw + c + 4) * SA + mbx];
                afb[mt][3] = AsB[cur * 16 * SA + (kw + c + 4) * SA + mbx + 8];
            }
#pragma unroll
            for (int nt = 0; nt < 4; ++nt) {
                int nb = wn * 32 + nt * 8 + r;
                bf[nt][0] = Bs[cur * 16 * SA + (kw + c) * SA + nb];
                bf[nt][1] = Bs[cur * 16 * SA + (kw + c + 4) * SA + nb];
            }
#pragma unroll
            for (int mt = 0; mt < 2; ++mt)
#pragma unroll
                for (int nt = 0; nt < 4; ++nt) {
                    mma_f16(acc_g[mt][nt], afg[mt], bf[nt]);
                    mma_f16(acc_b[mt][nt], afb[mt], bf[nt]);
                }
        }
        if (more) STS_TILE_F(cur ^ 1);
        __syncthreads();
    }
#undef LDG_TILE_F
#undef STS_TILE_F

#pragma unroll
    for (int mt = 0; mt < 2; ++mt) {
#pragma unroll
        for (int h = 0; h < 2; ++h) {
            const int row = m0 + wm * 32 + mt * 16 + r + h * 8;
            float bg = bfilm[row];
            float bb = bfilm[256 + row];
#pragma unroll
            for (int nt = 0; nt < 4; ++nt) {
                const int col = n0 + wn * 32 + nt * 8 + c * 2;
                float g0  = acc_g[mt][nt][h * 2 + 0] + bg;
                float g1  = acc_g[mt][nt][h * 2 + 1] + bg;
                float be0 = acc_b[mt][nt][h * 2 + 0] + bb;
                float be1 = acc_b[mt][nt][h * 2 + 1] + bb;
                float2 xv = *(const float2*)&x[((size_t)bz * CH + row) * TT + col];
                float xmm0 = xmask[(size_t)bz * TT + col];
                float xmm1 = xmask[(size_t)bz * TT + col + 1];
                float2 o;
                o.x = (xv.x * g0 + be0) * xmm0;
                o.y = (xv.y * g1 + be1) * xmm1;
                *(float2*)&out[((size_t)bz * CH + row) * TT + col] = o;
            }
        }
    }
}

// ---------------- launch ----------------
extern "C" void kernel_launch(void* const* d_in, const int* in_sizes, int n_in,
                              void* d_out, int out_size) {
    const float* x           = (const float*)d_in[0];
    const float* x_mask      = (const float*)d_in[1];
    const float* cond_latent = (const float*)d_in[2];
    const float* cond_mask   = (const float*)d_in[3];
    const float* w_cond      = (const float*)d_in[4];
    const float* b_cond      = (const float*)d_in[5];
    const float* wq          = (const float*)d_in[6];
    const float* bq          = (const float*)d_in[7];
    const float* wk          = (const float*)d_in[8];
    const float* bk          = (const float*)d_in[9];
    const float* wv          = (const float*)d_in[10];
    const float* bv          = (const float*)d_in[11];
    const float* wo          = (const float*)d_in[12];
    const float* bo          = (const float*)d_in[13];
    const float* w_film      = (const float*)d_in[14];
    const float* b_film      = (const float*)d_in[15];
    float* out = (float*)d_out;

    uint32_t *p_wkch, *p_wvch;
    float *p_bkc, *p_bvc, *p_bfo;
    cudaGetSymbolAddress((void**)&p_wkch, g_wkch);
    cudaGetSymbolAddress((void**)&p_wvch, g_wvch);
    cudaGetSymbolAddress((void**)&p_bkc,  g_bkc);
    cudaGetSymbolAddress((void**)&p_bvc,  g_bvc);
    cudaGetSymbolAddress((void**)&p_bfo,  g_bfo);

    cudaFuncSetAttribute(gemm_q,     cudaFuncAttributeMaxDynamicSharedMemorySize, GEMM_SMEM);
    cudaFuncSetAttribute(gemm_kv,    cudaFuncAttributeMaxDynamicSharedMemorySize, GEMM_SMEM);
    cudaFuncSetAttribute(gemm_cmb,   cudaFuncAttributeMaxDynamicSharedMemorySize, GEMM_SMEM);
    cudaFuncSetAttribute(flash_attn, cudaFuncAttributeMaxDynamicSharedMemorySize, FLASH_SMEM);
    cudaFuncSetAttribute(film_gemm,  cudaFuncAttributeMaxDynamicSharedMemorySize, FILM_SMEM);

    // prologue: rope tables + combined biases (one launch)
    prologue_kernel<<<260, 256>>>(wk, bk, wv, bv, b_cond, w_film, b_film, bo);

    // weight combines -> packed half
    gemm_cmb<<<dim3(4, 4, 3), 256, GEMM_SMEM>>>(wk, wv, w_film, w_cond, wo);

    // q = rope(wq @ x + bq) -> g_qh
    gemm_q<<<dim3(TT / 128, CH / 128, BQ), 256, GEMM_SMEM>>>(wq, x, bq);

    // k -> g_kh (rope+mask); v -> g_vh
    gemm_kv<<<dim3(TSL / 128, CH / 128, 2 * BQ), 256, GEMM_SMEM>>>(
        p_wkch, p_wvch, cond_latent, p_bkc, p_bvc, cond_mask);

    // fused attention -> g_atth (FA2 register-reuse PV)
    flash_attn<<<dim3(1, TT / 128, BQ * NH), 256, FLASH_SMEM>>>(cond_mask);

    // fused FiLM
    film_gemm<<<dim3(TT / 128, CH / 128, BQ), 512, FILM_SMEM>>>(
        p_bfo, x, x_mask, out);
}

// round 17
// speedup vs baseline: 1.8682x; 1.0109x over previous
#include <cuda_runtime.h>
#include <math.h>
#include <stdint.h>

// ---------------- problem constants (fixed shapes) ----------------
#define BQ   16
#define CH   256
#define CONDC 512
#define TT   2048
#define TSL  512
#define NH   4
#define KC   64

#define SA 136       // padded smem stride (words): mod 32 = 8, *4 % 16 == 0

// ---------------- scratch (device globals; no allocation) ----------------
__device__ uint32_t g_qh  [BQ * NH * 32 * TT];      // [bh][pair d,(d+32)][t]
__device__ uint32_t g_kh  [BQ * NH * 32 * TSL];     // [bh][pair d,(d+32)][t] roped+masked
__device__ uint32_t g_vh  [BQ * NH * 64 * (TSL/2)]; // [bh][ch][pos-pair]
__device__ uint32_t g_atth[BQ * 128 * TT];          // [b][ch-pair][t]
__device__ uint32_t g_xh  [BQ * 128 * TT];          // x packed  [b][k-pair][t]
__device__ uint32_t g_clh [BQ * 256 * TSL];         // cl packed [b][k-pair][s]
__device__ uint32_t g_wqh [CH * (CH/2)];            // wq packed [m][k-pair]
__device__ uint32_t g_wkch[CH * (CONDC/2)];         // [m][k-pair]  wk@w_cond
__device__ uint32_t g_wvch[CH * (CONDC/2)];         // [m][k-pair]  wv@w_cond
__device__ uint32_t g_wfoh[2 * CH * (CH/2)];        // [m][k-pair]  w_film@wo
__device__ float g_bkc[CH];
__device__ float g_bvc[CH];
__device__ float g_bfo[2 * CH];
__device__ float g_cos[32 * TT];                    // [d][t]
__device__ float g_sin[32 * TT];

// ---------------- fp16 helpers ----------------
__device__ __forceinline__ uint32_t h2pk(float lo, float hi) {
    uint32_t u;
    asm("cvt.rn.f16x2.f32 %0, %1, %2;" : "=r"(u) : "f"(hi), "f"(lo));
    return u;
}

__device__ __forceinline__ void mma_f16(float* c, const uint32_t* a, const uint32_t* b) {
    asm volatile(
        "mma.sync.aligned.m16n8k16.row.col.f32.f16.f16.f32 "
        "{%0,%1,%2,%3}, {%4,%5,%6,%7}, {%8,%9}, {%0,%1,%2,%3};\n"
        : "+f"(c[0]), "+f"(c[1]), "+f"(c[2]), "+f"(c[3])
        : "r"(a[0]), "r"(a[1]), "r"(a[2]), "r"(a[3]), "r"(b[0]), "r"(b[1]));
}

// ---------------- prologue: RoPE tables + combined biases (one launch) ----
__global__ void prologue_kernel(const float* __restrict__ wk, const float* __restrict__ bk,
                                const float* __restrict__ wv, const float* __restrict__ bv,
                                const float* __restrict__ b_cond,
                                const float* __restrict__ wf, const float* __restrict__ bf,
                                const float* __restrict__ bo) {
    if (blockIdx.x < 256) {
        int idx = blockIdx.x * 256 + threadIdx.x;
        int d = idx / TT;
        int t = idx % TT;
        float invf = (float)pow(10000.0, -(double)d / 32.0);
        float ang  = (float)t * invf;               // same fp32 rounding as reference
        g_cos[idx] = (float)cos((double)ang);
        g_sin[idx] = (float)sin((double)ang);
    } else {
        int tid = (blockIdx.x - 256) * 256 + threadIdx.x;   // 0..1023
        if (tid < 256) {
            float s = 0.f;
            for (int k = 0; k < CH; ++k) s += wk[tid * CH + k] * b_cond[k];
            g_bkc[tid] = s + bk[tid];
        } else if (tid < 512) {
            int m = tid - 256;
            float s = 0.f;
            for (int k = 0; k < CH; ++k) s += wv[m * CH + k] * b_cond[k];
            g_bvc[m] = s + bv[m];
        } else {
            int m = tid - 512;
            float s = 0.f;
            for (int k = 0; k < CH; ++k) s += wf[m * CH + k] * bo[k];
            g_bfo[m] = s + bf[m];
        }
    }
}

// ---------------- pack x / cond_latent / wq into k-pair half2 words ----------
#define NX_U4  (BQ * 128 * (TT / 4))      // 1048576
#define NCL_U4 (BQ * 256 * (TSL / 4))     // 524288
#define NWQ_U4 (CH * (CH / 2) / 4)        // 8192

__global__ void pack_kernel(const float* __restrict__ x, const float* __restrict__ cl,
                            const float* __restrict__ wq) {
    int i = blockIdx.x * 256 + threadIdx.x;
    if (i < NX_U4) {
        int b   = i / (128 * (TT / 4));
        int rem = i % (128 * (TT / 4));
        int kp  = rem / (TT / 4);
        int t4  = rem % (TT / 4);
        float4 lo = *(const float4*)&x[((size_t)b * CH + 2 * kp)     * TT + 4 * t4];
        float4 hi = *(const float4*)&x[((size_t)b * CH + 2 * kp + 1) * TT + 4 * t4];
        uint4 w;
        w.x = h2pk(lo.x, hi.x); w.y = h2pk(lo.y, hi.y);
        w.z = h2pk(lo.z, hi.z); w.w = h2pk(lo.w, hi.w);
        *(uint4*)&g_xh[((size_t)b * 128 + kp) * TT + 4 * t4] = w;
    } else if (i < NX_U4 + NCL_U4) {
        int j   = i - NX_U4;
        int b   = j / (256 * (TSL / 4));
        int rem = j % (256 * (TSL / 4));
        int kp  = rem / (TSL / 4);
        int s4  = rem % (TSL / 4);
        float4 lo = *(const float4*)&cl[((size_t)b * CONDC + 2 * kp)     * TSL + 4 * s4];
        float4 hi = *(const float4*)&cl[((size_t)b * CONDC + 2 * kp + 1) * TSL + 4 * s4];
        uint4 w;
        w.x = h2pk(lo.x, hi.x); w.y = h2pk(lo.y, hi.y);
        w.z = h2pk(lo.z, hi.z); w.w = h2pk(lo.w, hi.w);
        *(uint4*)&g_clh[((size_t)b * 256 + kp) * TSL + 4 * s4] = w;
    } else if (i < NX_U4 + NCL_U4 + NWQ_U4) {
        int j = i - NX_U4 - NCL_U4;           // covers 8 consecutive k of one row
        int m  = j / 32;
        int k8 = (j % 32) * 8;
        float4 a0 = *(const float4*)&wq[(size_t)m * CH + k8];
        float4 a1 = *(const float4*)&wq[(size_t)m * CH + k8 + 4];
        uint4 w;
        w.x = h2pk(a0.x, a0.y); w.y = h2pk(a0.z, a0.w);
        w.z = h2pk(a1.x, a1.y); w.w = h2pk(a1.z, a1.w);
        *(uint4*)&g_wqh[(size_t)m * 128 + k8 / 2] = w;
    }
}

// ============================================================================
// Shared fp16-MMA mainloop pieces (128x128 CTA tile, 256 thr, 8 warps 2x4,
// warp tile 64x32, BK=32 floats = 16 half2 word-rows, double-buffered smem).
// ============================================================================
#define GEMM_SMEM (4 * 16 * SA * 4)

#define GEMM_IDS                                                         \
    const int tid = threadIdx.x;                                         \
    const int wid = tid >> 5, lane = tid & 31;                           \
    const int wm = wid >> 2, wn = wid & 3;                               \
    const int r = lane >> 2, c = lane & 3;                               \
    const int a_m  = ((tid >> 1) + ((tid & 1) << 4)) & 127;              \
    const int a_kw = (tid & 1) * 8;                                      \
    const int b_kp = tid >> 4;                                           \
    const int b_n4 = (tid & 15) * 4;

#define GEMM_COMPUTE(Ac, Bc)                                             \
    _Pragma("unroll")                                                    \
    for (int kw = 0; kw < 16; kw += 8) {                                 \
        uint32_t af[4][4], bf[4][2];                                     \
        _Pragma("unroll")                                                \
        for (int mt = 0; mt < 4; ++mt) {                                 \
            int mb = wm * 64 + mt * 16 + r;                              \
            af[mt][0] = (Ac)[(kw + c) * SA + mb];                        \
            af[mt][1] = (Ac)[(kw + c) * SA + mb + 8];                    \
            af[mt][2] = (Ac)[(kw + c + 4) * SA + mb];                    \
            af[mt][3] = (Ac)[(kw + c + 4) * SA + mb + 8];                \
        }                                                                \
        _Pragma("unroll")                                                \
        for (int nt = 0; nt < 4; ++nt) {                                 \
            int nb = wn * 32 + nt * 8 + r;                               \
            bf[nt][0] = (Bc)[(kw + c) * SA + nb];                        \
            bf[nt][1] = (Bc)[(kw + c + 4) * SA + nb];                    \
        }                                                                \
        _Pragma("unroll")                                                \
        for (int mt = 0; mt < 4; ++mt)                                   \
            _Pragma("unroll")                                            \
            for (int nt = 0; nt < 4; ++nt)                               \
                mma_f16(acc[mt][nt], af[mt], bf[nt]);                    \
    }

// Pure-copy loader pair shared by gemm_q / gemm_kv (A and B both packed).
#define LDG_PK(Ah, AW, Bbh, BW, k0)                                                     \
    {                                                                                   \
        aw[0] = *(const uint4*)&(Ah)[(size_t)(m0 + a_m) * (AW) + (k0)/2 + a_kw];        \
        aw[1] = *(const uint4*)&(Ah)[(size_t)(m0 + a_m) * (AW) + (k0)/2 + a_kw + 4];    \
        wBt[0] = *(const uint4*)&(Bbh)[(size_t)((k0)/2 + b_kp) * (BW) + n0 + b_n4];     \
        wBt[1] = *(const uint4*)&(Bbh)[(size_t)((k0)/2 + b_kp) * (BW) + n0 + b_n4 + 64];\
    }
#define STS_PK(buf)                                                                     \
    {                                                                                   \
        uint32_t* Ab = Asm + (buf) * 16 * SA;                                           \
        uint32_t* Bd = Bsm + (buf) * 16 * SA;                                           \
        Ab[(a_kw + 0) * SA + a_m] = aw[0].x;                                            \
        Ab[(a_kw + 1) * SA + a_m] = aw[0].y;                                            \
        Ab[(a_kw + 2) * SA + a_m] = aw[0].z;                                            \
        Ab[(a_kw + 3) * SA + a_m] = aw[0].w;                                            \
        Ab[(a_kw + 4) * SA + a_m] = aw[1].x;                                            \
        Ab[(a_kw + 5) * SA + a_m] = aw[1].y;                                            \
        Ab[(a_kw + 6) * SA + a_m] = aw[1].z;                                            \
        Ab[(a_kw + 7) * SA + a_m] = aw[1].w;                                            \
        *(uint4*)&Bd[b_kp * SA + b_n4]      = wBt[0];                                   \
        *(uint4*)&Bd[b_kp * SA + b_n4 + 64] = wBt[1];                                   \
    }

// ============================================================================
// gemm_q: q = rope(wq @ x + bq) -> g_qh packed (d, d+32). Fully packed loads.
// ============================================================================
__global__ __launch_bounds__(256, 2)
void gemm_q(const float* __restrict__ bias)
{
    extern __shared__ uint32_t smg[];
    uint32_t* Asm = smg;
    uint32_t* Bsm = smg + 2 * 16 * SA;
    GEMM_IDS
    const int bz = blockIdx.z;
    const uint32_t* Bbh = g_xh + (size_t)bz * 128 * TT;
    const int m0 = blockIdx.y * 128, n0 = blockIdx.x * 128;
    float acc[4][4][4] = {};

    uint4 aw[2], wBt[2];
    LDG_PK(g_wqh, 128, Bbh, TT, 0); STS_PK(0); __syncthreads();
    for (int kb = 0; kb < 8; ++kb) {
        const int cur = kb & 1;
        const bool more = (kb < 7);
        if (more) LDG_PK(g_wqh, 128, Bbh, TT, (kb + 1) * 32);
        GEMM_COMPUTE(Asm + cur * 16 * SA, Bsm + cur * 16 * SA)
        if (more) STS_PK(cur ^ 1);
        __syncthreads();
    }
#pragma unroll
    for (int mtl = 0; mtl < 2; ++mtl) {
#pragma unroll
        for (int h = 0; h < 2; ++h) {
            const int row_lo = m0 + wm * 64 + mtl * 16 + h * 8 + r;
            const int head = row_lo >> 6;
            const int d = row_lo & 63;        // < 32
            float b_lo = bias[row_lo], b_hi = bias[row_lo + 32];
            uint32_t* dst = g_qh + ((size_t)(bz * NH + head) * 32 + d) * TT;
#pragma unroll
            for (int nt = 0; nt < 4; ++nt) {
                const int col = n0 + wn * 32 + nt * 8 + c * 2;
                float2 cs = *(const float2*)&g_cos[(size_t)d * TT + col];
                float2 sn = *(const float2*)&g_sin[(size_t)d * TT + col];
                float k1x = acc[mtl][nt][h * 2 + 0] + b_lo;
                float k1y = acc[mtl][nt][h * 2 + 1] + b_lo;
                float k2x = acc[mtl + 2][nt][h * 2 + 0] + b_hi;
                float k2y = acc[mtl + 2][nt][h * 2 + 1] + b_hi;
                uint2 o;
                o.x = h2pk(k1x * cs.x - k2x * sn.x, k2x * cs.x + k1x * sn.x);
                o.y = h2pk(k1y * cs.y - k2y * sn.y, k2y * cs.y + k1y * sn.y);
                *(uint2*)&dst[col] = o;
            }
        }
    }
}

// ============================================================================
// gemm_kv: k = rope+mask(wkc@cl + bkc) -> g_kh ; v = wvc@cl + bvc -> g_vh.
// Fully packed loads.
// ============================================================================
__global__ __launch_bounds__(256, 2)
void gemm_kv(const float* __restrict__ bias0, const float* __restrict__ bias1,
             const float* __restrict__ cmask)
{
    extern __shared__ uint32_t smg[];
    uint32_t* Asm = smg;
    uint32_t* Bsm = smg + 2 * 16 * SA;
    GEMM_IDS
    const int bz  = blockIdx.z & 15;
    const int sel = blockIdx.z >> 4;
    const uint32_t* Ah   = sel ? g_wvch : g_wkch;
    const float*    bias = sel ? bias1 : bias0;
    const uint32_t* Bbh = g_clh + (size_t)bz * 256 * TSL;
    const int m0 = blockIdx.y * 128, n0 = blockIdx.x * 128;
    float acc[4][4][4] = {};

    uint4 aw[2], wBt[2];
    LDG_PK(Ah, CONDC/2, Bbh, TSL, 0); STS_PK(0); __syncthreads();
    for (int kb = 0; kb < 16; ++kb) {
        const int cur = kb & 1;
        const bool more = (kb < 15);
        if (more) LDG_PK(Ah, CONDC/2, Bbh, TSL, (kb + 1) * 32);
        GEMM_COMPUTE(Asm + cur * 16 * SA, Bsm + cur * 16 * SA)
        if (more) STS_PK(cur ^ 1);
        __syncthreads();
    }

    if (sel == 0) {
#pragma unroll
        for (int mtl = 0; mtl < 2; ++mtl) {
#pragma unroll
            for (int h = 0; h < 2; ++h) {
                const int row_lo = m0 + wm * 64 + mtl * 16 + h * 8 + r;
                const int head = row_lo >> 6;
                const int d = row_lo & 63;
                float b_lo = bias[row_lo], b_hi = bias[row_lo + 32];
                uint32_t* dst = g_kh + ((size_t)(bz * NH + head) * 32 + d) * TSL;
#pragma unroll
                for (int nt = 0; nt < 4; ++nt) {
                    const int col = n0 + wn * 32 + nt * 8 + c * 2;
                    float2 cs = *(const float2*)&g_cos[(size_t)d * TT + col];
                    float2 sn = *(const float2*)&g_sin[(size_t)d * TT + col];
                    float2 cm = *(const float2*)&cmask[(size_t)bz * TSL + col];
                    float k1x = acc[mtl][nt][h * 2 + 0] + b_lo;
                    float k1y = acc[mtl][nt][h * 2 + 1] + b_lo;
                    float k2x = acc[mtl + 2][nt][h * 2 + 0] + b_hi;
                    float k2y = acc[mtl + 2][nt][h * 2 + 1] + b_hi;
                    uint2 o;
                    o.x = h2pk((k1x * cs.x - k2x * sn.x) * cm.x,
                               (k2x * cs.x + k1x * sn.x) * cm.x);
                    o.y = h2pk((k1y * cs.y - k2y * sn.y) * cm.y,
                               (k2y * cs.y + k1y * sn.y) * cm.y);
                    *(uint2*)&dst[col] = o;
                }
            }
        }
    } else {
#pragma unroll
        for (int mt = 0; mt < 4; ++mt) {
#pragma unroll
            for (int h = 0; h < 2; ++h) {
                const int row = m0 + wm * 64 + mt * 16 + h * 8 + r;
                float bval = bias[row];
                uint32_t* dst = g_vh + ((size_t)(bz * NH + (row >> 6)) * 64 + (row & 63)) * (TSL / 2);
#pragma unroll
                for (int nt = 0; nt < 4; ++nt) {
                    const int col = n0 + wn * 32 + nt * 8 + c * 2;
                    dst[col >> 1] = h2pk(acc[mt][nt][h * 2 + 0] + bval,
                                         acc[mt][nt][h * 2 + 1] + bval);
                }
            }
        }
    }
}

// ============================================================================
// gemm_cmb: weight combines -> packed-half outputs (unchanged from R16).
// ============================================================================
__global__ __launch_bounds__(256, 2)
void gemm_cmb(const float* __restrict__ wk, const float* __restrict__ wv,
              const float* __restrict__ wf,
              const float* __restrict__ w_cond, const float* __restrict__ wo)
{
    extern __shared__ uint32_t smg[];
    uint32_t* Asm = smg;
    uint32_t* Bsm = smg + 2 * 16 * SA;
    GEMM_IDS
    const int sel = blockIdx.z;
    const float* A    = (sel == 0) ? wk : (sel == 1) ? wv : wf;
    const float* Bsrc = (sel == 2) ? wo : w_cond;
    uint32_t*    Yh   = (sel == 0) ? g_wkch : (sel == 1) ? g_wvch : g_wfoh;
    const int Md = (sel < 2) ? 256 : 512;
    const int Ndim = (sel < 2) ? 512 : 256;
    if ((int)blockIdx.y * 128 >= Md || (int)blockIdx.x * 128 >= Ndim) return;
    const int m0 = blockIdx.y * 128, n0 = blockIdx.x * 128;
    float acc[4][4][4] = {};

    float4 avr[4], blo[2], bhi[2];
#define LDG_C(k0)                                                                        \
    {                                                                                    \
        _Pragma("unroll")                                                                \
        for (int j = 0; j < 4; ++j)                                                      \
            avr[j] = *(const float4*)&A[(size_t)(m0 + a_m) * CH + (k0) + a_kw * 2 + 4 * j]; \
        _Pragma("unroll")                                                                \
        for (int j = 0; j < 2; ++j) {                                                    \
            blo[j] = *(const float4*)&Bsrc[(size_t)((k0) + 2 * b_kp)     * Ndim + n0 + b_n4 + 64 * j]; \
            bhi[j] = *(const float4*)&Bsrc[(size_t)((k0) + 2 * b_kp + 1) * Ndim + n0 + b_n4 + 64 * j]; \
        }                                                                                \
    }
#define STS_C(buf)                                                                       \
    {                                                                                    \
        uint32_t* Ab = Asm + (buf) * 16 * SA;                                            \
        uint32_t* Bd = Bsm + (buf) * 16 * SA;                                            \
        _Pragma("unroll")                                                                \
        for (int j = 0; j < 4; ++j) {                                                    \
            Ab[(a_kw + 2 * j + 0) * SA + a_m] = h2pk(avr[j].x, avr[j].y);                \
            Ab[(a_kw + 2 * j + 1) * SA + a_m] = h2pk(avr[j].z, avr[j].w);                \
        }                                                                                \
        _Pragma("unroll")                                                                \
        for (int j = 0; j < 2; ++j) {                                                    \
            uint4 w;                                                                    \
            w.x = h2pk(blo[j].x, bhi[j].x); w.y = h2pk(blo[j].y, bhi[j].y);              \
            w.z = h2pk(blo[j].z, bhi[j].z); w.w = h2pk(blo[j].w, bhi[j].w);              \
            *(uint4*)&Bd[b_kp * SA + b_n4 + 64 * j] = w;                                 \
        }                                                                                \
    }
    LDG_C(0); STS_C(0); __syncthreads();
    for (int kb = 0; kb < 8; ++kb) {
        const int cur = kb & 1;
        const bool more = (kb < 7);
        if (more) LDG_C((kb + 1) * 32);
        GEMM_COMPUTE(Asm + cur * 16 * SA, Bsm + cur * 16 * SA)
        if (more) STS_C(cur ^ 1);
        __syncthreads();
    }
#undef LDG_C
#undef STS_C
    const int Nw = Ndim / 2;
#pragma unroll
    for (int mt = 0; mt < 4; ++mt) {
#pragma unroll
        for (int h = 0; h < 2; ++h) {
            const int row = m0 + wm * 64 + mt * 16 + h * 8 + r;
#pragma unroll
            for (int nt = 0; nt < 4; ++nt) {
                const int kp = (n0 + wn * 32 + nt * 8) / 2 + c;
                Yh[(size_t)row * Nw + kp] =
                    h2pk(acc[mt][nt][h * 2 + 0], acc[mt][nt][h * 2 + 1]);
            }
        }
    }
}

// ============================================================================
// Fused flash attention — packed operands, FA2 register-reuse PV, and now
// DOUBLE-BUFFERED K/V smem: one __syncthreads per chunk (9 total vs 16).
// smem words: Qs[32][136]=4352 | Ks[2][32][72]=4608 | Vs[2][64][36]=4608 | cmb 512
// ============================================================================
#define FSA 136
#define FSK 72
#define FSV2 36
#define OFF_KS 4352
#define OFF_VS 8960
#define OFF_CMB 13568
#define FLASH_SMEM (14080 * 4)
#define SCALE_LOG2E 0.18033688f   // 0.125 * log2(e)

__global__ __launch_bounds__(256, 2)
void flash_attn(const float* __restrict__ cmask)
{
    extern __shared__ uint32_t sm[];
    uint32_t* Qs  = sm;
    uint32_t* Ks  = sm + OFF_KS;     // [2][2304]
    uint32_t* Vs  = sm + OFF_VS;     // [2][2304]
    float*    cmb = (float*)(sm + OFF_CMB);

    const int bh = blockIdx.z;
    const int b  = bh >> 2;
    const int m0 = blockIdx.y * 128;
    const int tid = threadIdx.x, wid = tid >> 5, lane = tid & 31;
    const int r = lane >> 2, c = lane & 3;
    const int mb = wid * 16 + r;

    const uint32_t* Qb = g_qh + (size_t)bh * 32 * TT;
    const uint32_t* Kb = g_kh + (size_t)bh * 32 * TSL;
    const uint32_t* Vb = g_vh + (size_t)bh * 64 * (TSL / 2);

    // ---- Q tile: pure uint4 copy ----
    {
        const int e  = tid >> 3;
        const int mg = (tid & 7) * 16;
#pragma unroll
        for (int j = 0; j < 4; ++j)
            *(uint4*)&Qs[e * FSA + mg + 4 * j] =
                *(const uint4*)&Qb[(size_t)e * TT + m0 + mg + 4 * j];
    }
    for (int i = tid; i < TSL; i += 256)
        cmb[i] = (cmask[(size_t)b * TSL + i] == 0.f) ? -14427.0f : 0.f;

    const int e2 = tid >> 3;            // K pair-row 0..31
    const int n8 = (tid & 7) * 8;
    const int ch = tid >> 2;            // V channel 0..63
    const int kw8 = (tid & 3) * 8;
    uint4 kr[2], vr[2];

#define FKV_LDG(cc)                                                                      \
    {                                                                                    \
        const int ss = (cc) * 64;                                                        \
        kr[0] = *(const uint4*)&Kb[(size_t)e2 * TSL + ss + n8];                          \
        kr[1] = *(const uint4*)&Kb[(size_t)e2 * TSL + ss + n8 + 4];                      \
        vr[0] = *(const uint4*)&Vb[(size_t)ch * (TSL / 2) + ss / 2 + kw8];               \
        vr[1] = *(const uint4*)&Vb[(size_t)ch * (TSL / 2) + ss / 2 + kw8 + 4];           \
    }
#define FKV_STS(buf)                                                                     \
    {                                                                                    \
        uint32_t* Kd = Ks + (buf) * 2304;                                                \
        uint32_t* Vd = Vs + (buf) * 2304;                                                \
        *(uint4*)&Kd[e2 * FSK + n8]       = kr[0];                                       \
        *(uint4*)&Kd[e2 * FSK + n8 + 4]   = kr[1];                                       \
        *(uint4*)&Vd[ch * FSV2 + kw8]     = vr[0];                                       \
        *(uint4*)&Vd[ch * FSV2 + kw8 + 4] = vr[1];                                       \
    }

    FKV_LDG(0);
    FKV_STS(0);

    float l_run[2] = {0.f, 0.f};
    float acc_o[8][4] = {};

    __syncthreads();   // Qs, cmb, chunk-0 K/V all visible

    for (int ci = 0; ci < 8; ++ci) {
        const int cur = ci & 1;
        const int s0 = ci * 64;
        const bool more = (ci < 7);
        if (more) FKV_LDG(ci + 1);

        const uint32_t* Kc = Ks + cur * 2304;
        const uint32_t* Vc = Vs + cur * 2304;

        // ---- S = Q^T K : warp tile 16 x 64 ----
        float acc_s[8][4] = {};
#pragma unroll
        for (int kw = 0; kw < 32; kw += 8) {
            uint32_t af[4];
            af[0] = Qs[(kw + c) * FSA + mb];
            af[1] = Qs[(kw + c) * FSA + mb + 8];
            af[2] = Qs[(kw + c + 4) * FSA + mb];
            af[3] = Qs[(kw + c + 4) * FSA + mb + 8];
#pragma unroll
            for (int nt = 0; nt < 8; ++nt) {
                uint32_t bf[2];
                bf[0] = Kc[(kw + c) * FSK + nt * 8 + r];
                bf[1] = Kc[(kw + c + 4) * FSK + nt * 8 + r];
                mma_f16(acc_s[nt], af, bf);
            }
        }

        // ---- exp2(scale*s + bias), row sums ----
        float lad[2] = {0.f, 0.f};
#pragma unroll
        for (int nt = 0; nt < 8; ++nt) {
            float2 bias = *(float2*)&cmb[s0 + nt * 8 + 2 * c];
#pragma unroll
            for (int jj = 0; jj < 4; ++jj) {
                float e = exp2f(acc_s[nt][jj] * SCALE_LOG2E + ((jj & 1) ? bias.y : bias.x));
                acc_s[nt][jj] = e;
                lad[jj >> 1] += e;
            }
        }
#pragma unroll
        for (int h = 0; h < 2; ++h) {
            lad[h] += __shfl_xor_sync(0xffffffffu, lad[h], 1);
            lad[h] += __shfl_xor_sync(0xffffffffu, lad[h], 2);
            l_run[h] += lad[h];
        }

        // ---- O += P @ V^T : P from S registers (C == A layout) ----
#pragma unroll
        for (int g = 0; g < 4; ++g) {
            uint32_t af[4];
            af[0] = h2pk(acc_s[2 * g][0],     acc_s[2 * g][1]);
            af[1] = h2pk(acc_s[2 * g][2],     acc_s[2 * g][3]);
            af[2] = h2pk(acc_s[2 * g + 1][0], acc_s[2 * g + 1][1]);
            af[3] = h2pk(acc_s[2 * g + 1][2], acc_s[2 * g + 1][3]);
            const int kw = 8 * g;
#pragma unroll
            for (int nt = 0; nt < 8; ++nt) {
                uint32_t bf[2];
                bf[0] = Vc[(nt * 8 + r) * FSV2 + kw + c];
                bf[1] = Vc[(nt * 8 + r) * FSV2 + kw + c + 4];
                mma_f16(acc_o[nt], af, bf);
            }
        }

        if (more) FKV_STS(cur ^ 1);
        __syncthreads();
    }
#undef FKV_LDG
#undef FKV_STS

    // ---- epilogue: /l, transpose via smem, packed ch-pair store ----
    float inv[2] = {1.f / l_run[0], 1.f / l_run[1]};
    float* Pf = (float*)sm;    // [64][136] floats = 8704 <= 14080 words
#pragma unroll
    for (int nt = 0; nt < 8; ++nt) {
#pragma unroll
        for (int jj = 0; jj < 4; ++jj) {
            int n = nt * 8 + 2 * c + (jj & 1);
            int m = wid * 16 + r + (jj >> 1) * 8;
            Pf[n * FSA + m] = acc_o[nt][jj] * inv[jj >> 1];
        }
    }
    __syncthreads();
    {
        const int e  = tid >> 3;            // local ch-pair 0..31
        const int mq = (tid & 7) * 4;
        uint32_t* dst = g_atth + ((size_t)b * 128 + (bh & 3) * 32 + e) * TT;
#pragma unroll
        for (int j = 0; j < 4; ++j) {
            int m = mq + 32 * j;
            float4 lo = *(float4*)&Pf[(2 * e) * FSA + m];
            float4 hi = *(float4*)&Pf[(2 * e + 1) * FSA + m];
            uint4 w;
            w.x = h2pk(lo.x, hi.x); w.y = h2pk(lo.y, hi.y);
            w.z = h2pk(lo.z, hi.z); w.w = h2pk(lo.w, hi.w);
            *(uint4*)&dst[m0 + m] = w;
        }
    }
}

// ============================================================================
// Fused FiLM GEMM — packed A/B, pure-copy loads (unchanged from R16).
// ============================================================================
#define FILM_SMEM (6 * 16 * SA * 4)

__global__ __launch_bounds__(512)
void film_gemm(const float* __restrict__ bfilm, const float* __restrict__ x,
               const float* __restrict__ xmask, float* __restrict__ out)
{
    extern __shared__ uint32_t smf[];
    uint32_t* AsG = smf;
    uint32_t* AsB = smf + 2 * 16 * SA;
    uint32_t* Bs  = smf + 4 * 16 * SA;

    const int tid = threadIdx.x;
    const int bz  = blockIdx.z;
    const uint32_t* Bb = g_atth + (size_t)bz * 128 * TT;
    const int m0 = blockIdx.y * 128, n0 = blockIdx.x * 128;

    const int wid = tid >> 5, lane = tid & 31;
    const int wm = wid >> 2, wn = wid & 3;
    const int r = lane >> 2, c = lane & 3;

    const int a_kw = (tid & 3) * 4;
    const int a_m  = ((tid >> 2) + (tid & 3) * 8) & 127;
    const int b_kp = tid >> 5;
    const int b_n4 = (tid & 31) * 4;

    float acc_g[2][4][4] = {};
    float acc_b[2][4][4] = {};

    uint4 wG, wB, wBt;
#define LDG_TILE_F(k0)                                                                   \
    {                                                                                    \
        wG  = *(const uint4*)&g_wfoh[(size_t)(m0 + a_m) * 128 + (k0)/2 + a_kw];          \
        wB  = *(const uint4*)&g_wfoh[(size_t)(256 + m0 + a_m) * 128 + (k0)/2 + a_kw];    \
        wBt = *(const uint4*)&Bb[(size_t)((k0)/2 + b_kp) * TT + n0 + b_n4];              \
    }
#define STS_TILE_F(buf)                                                                  \
    {                                                                                    \
        uint32_t* G = AsG + (buf) * 16 * SA;                                             \
        uint32_t* Bq = AsB + (buf) * 16 * SA;                                            \
        G[(a_kw + 0) * SA + a_m] = wG.x;                                                 \
        G[(a_kw + 1) * SA + a_m] = wG.y;                                                 \
        G[(a_kw + 2) * SA + a_m] = wG.z;                                                 \
        G[(a_kw + 3) * SA + a_m] = wG.w;                                                 \
        Bq[(a_kw + 0) * SA + a_m] = wB.x;                                                \
        Bq[(a_kw + 1) * SA + a_m] = wB.y;                                                \
        Bq[(a_kw + 2) * SA + a_m] = wB.z;                                                \
        Bq[(a_kw + 3) * SA + a_m] = wB.w;                                                \
        *(uint4*)&Bs[(buf) * 16 * SA + b_kp * SA + b_n4] = wBt;                          \
    }

    LDG_TILE_F(0);
    STS_TILE_F(0);
    __syncthreads();

    const int nk = CH / 32;
    for (int kb = 0; kb < nk; ++kb) {
        const int cur = kb & 1;
        const bool more = (kb + 1 < nk);
        if (more) LDG_TILE_F((kb + 1) * 32);

#pragma unroll
        for (int kw = 0; kw < 16; kw += 8) {
            uint32_t afg[2][4], afb[2][4], bf[4][2];
#pragma unroll
            for (int mt = 0; mt < 2; ++mt) {
                int mbx = wm * 32 + mt * 16 + r;
                afg[mt][0] = AsG[cur * 16 * SA + (kw + c) * SA + mbx];
                afg[mt][1] = AsG[cur * 16 * SA + (kw + c) * SA + mbx + 8];
                afg[mt][2] = AsG[cur * 16 * SA + (kw + c + 4) * SA + mbx];
                afg[mt][3] = AsG[cur * 16 * SA + (kw + c + 4) * SA + mbx + 8];
                afb[mt][0] = AsB[cur * 16 * SA + (kw + c) * SA + mbx];
                afb[mt][1] = AsB[cur * 16 * SA + (kw + c) * SA + mbx + 8];
                afb[mt][2] = AsB[cur * 16 * SA + (kw + c + 4) * SA + mbx];
                afb[mt][3] = AsB[cur * 16 * SA + (kw + c + 4) * SA + mbx + 8];
            }
#pragma unroll
            for (int nt = 0; nt < 4; ++nt) {
                int nb = wn * 32 + nt * 8 + r;
                bf[nt][0] = Bs[cur * 16 * SA + (kw + c) * SA + nb];
                bf[nt][1] = Bs[cur * 16 * SA + (kw + c + 4) * SA + nb];
            }
#pragma unroll
            for (int mt = 0; mt < 2; ++mt)
#pragma unroll
                for (int nt = 0; nt < 4; ++nt) {
                    mma_f16(acc_g[mt][nt], afg[mt], bf[nt]);
                    mma_f16(acc_b[mt][nt], afb[mt], bf[nt]);
                }
        }
        if (more) STS_TILE_F(cur ^ 1);
        __syncthreads();
    }
#undef LDG_TILE_F
#undef STS_TILE_F

#pragma unroll
    for (int mt = 0; mt < 2; ++mt) {
#pragma unroll
        for (int h = 0; h < 2; ++h) {
            const int row = m0 + wm * 32 + mt * 16 + r + h * 8;
            float bg = bfilm[row];
            float bb = bfilm[256 + row];
#pragma unroll
            for (int nt = 0; nt < 4; ++nt) {
                const int col = n0 + wn * 32 + nt * 8 + c * 2;
                float g0  = acc_g[mt][nt][h * 2 + 0] + bg;
                float g1  = acc_g[mt][nt][h * 2 + 1] + bg;
                float be0 = acc_b[mt][nt][h * 2 + 0] + bb;
                float be1 = acc_b[mt][nt][h * 2 + 1] + bb;
                float2 xv = *(const float2*)&x[((size_t)bz * CH + row) * TT + col];
                float xmm0 = xmask[(size_t)bz * TT + col];
                float xmm1 = xmask[(size_t)bz * TT + col + 1];
                float2 o;
                o.x = (xv.x * g0 + be0) * xmm0;
                o.y = (xv.y * g1 + be1) * xmm1;
                *(float2*)&out[((size_t)bz * CH + row) * TT + col] = o;
            }
        }
    }
}

// ---------------- launch ----------------
extern "C" void kernel_launch(void* const* d_in, const int* in_sizes, int n_in,
                              void* d_out, int out_size) {
    const float* x           = (const float*)d_in[0];
    const float* x_mask      = (const float*)d_in[1];
    const float* cond_latent = (const float*)d_in[2];
    const float* cond_mask   = (const float*)d_in[3];
    const float* w_cond      = (const float*)d_in[4];
    const float* b_cond      = (const float*)d_in[5];
    const float* wq          = (const float*)d_in[6];
    const float* bq          = (const float*)d_in[7];
    const float* wk          = (const float*)d_in[8];
    const float* bk          = (const float*)d_in[9];
    const float* wv          = (const float*)d_in[10];
    const float* bv          = (const float*)d_in[11];
    const float* wo          = (const float*)d_in[12];
    const float* bo          = (const float*)d_in[13];
    const float* w_film      = (const float*)d_in[14];
    const float* b_film      = (const float*)d_in[15];
    float* out = (float*)d_out;

    float *p_bkc, *p_bvc, *p_bfo;
    cudaGetSymbolAddress((void**)&p_bkc, g_bkc);
    cudaGetSymbolAddress((void**)&p_bvc, g_bvc);
    cudaGetSymbolAddress((void**)&p_bfo, g_bfo);

    cudaFuncSetAttribute(gemm_q,     cudaFuncAttributeMaxDynamicSharedMemorySize, GEMM_SMEM);
    cudaFuncSetAttribute(gemm_kv,    cudaFuncAttributeMaxDynamicSharedMemorySize, GEMM_SMEM);
    cudaFuncSetAttribute(gemm_cmb,   cudaFuncAttributeMaxDynamicSharedMemorySize, GEMM_SMEM);
    cudaFuncSetAttribute(flash_attn, cudaFuncAttributeMaxDynamicSharedMemorySize, FLASH_SMEM);
    cudaFuncSetAttribute(film_gemm,  cudaFuncAttributeMaxDynamicSharedMemorySize, FILM_SMEM);

    // prologue: rope tables + combined biases
    prologue_kernel<<<260, 256>>>(wk, bk, wv, bv, b_cond, w_film, b_film, bo);

    // pack x / cond_latent / wq into k-pair half2 layout
    pack_kernel<<<(NX_U4 + NCL_U4 + NWQ_U4 + 255) / 256, 256>>>(x, cond_latent, wq);

    // weight combines -> packed half
    gemm_cmb<<<dim3(4, 4, 3), 256, GEMM_SMEM>>>(wk, wv, w_film, w_cond, wo);

    // q = rope(wq @ x + bq) -> g_qh (fully packed loads)
    gemm_q<<<dim3(TT / 128, CH / 128, BQ), 256, GEMM_SMEM>>>(bq);

    // k -> g_kh (rope+mask); v -> g_vh (fully packed loads)
    gemm_kv<<<dim3(TSL / 128, CH / 128, 2 * BQ), 256, GEMM_SMEM>>>(
        p_bkc, p_bvc, cond_mask);

    // fused attention -> g_atth (double-buffered K/V, one sync per chunk)
    flash_attn<<<dim3(1, TT / 128, BQ * NH), 256, FLASH_SMEM>>>(cond_mask);

    // fused FiLM
    film_gemm<<<dim3(TT / 128, CH / 128, BQ), 512, FILM_SMEM>>>(
        p_bfo, x, x_mask, out);
}